// round 6
// baseline (speedup 1.0000x reference)
#include <cuda_runtime.h>
#include <cuda_bf16.h>
#include <math.h>
#include <stdint.h>

// ---------------- problem constants ----------------
#define LAYERS 6
#define BATCH  2
#define SEQ    1024
#define DMODEL 1024
#define NHEAD  16
#define HDIM   64
#define DFF    4096
#define WIN    5
#define TOKENS (BATCH*SEQ)          // 2048
#define EPS    1e-5f

// weight scratch layout (elements)
#define QKV_ELEMS  (LAYERS*DMODEL*3*DMODEL)
#define WO_ELEMS   (LAYERS*DMODEL*DMODEL)
#define W1_ELEMS   (LAYERS*DMODEL*DFF)
#define W2_ELEMS   (LAYERS*DFF*DMODEL)
#define QKV_OFF 0
#define WO_OFF  (QKV_ELEMS)
#define W1_OFF  (WO_OFF + WO_ELEMS)
#define W2_OFF  (W1_OFF + W1_ELEMS)
#define WTOTAL  (W2_OFF + W2_ELEMS)

// ---------------- device scratch (no allocation allowed) ----------------
__device__ float d_h   [TOKENS*DMODEL];
__device__ float d_hn  [TOKENS*DMODEL];
__device__ __nv_bfloat16 d_hn_hi[TOKENS*DMODEL];
__device__ __nv_bfloat16 d_hn_lo[TOKENS*DMODEL];
__device__ __nv_bfloat16 d_qkv_hi[TOKENS*3*DMODEL];
__device__ __nv_bfloat16 d_qkv_lo[TOKENS*3*DMODEL];
__device__ __nv_bfloat16 d_o_hi[TOKENS*DMODEL];
__device__ __nv_bfloat16 d_o_lo[TOKENS*DMODEL];
__device__ __nv_bfloat16 d_ff_hi[TOKENS*DFF];
__device__ __nv_bfloat16 d_ff_lo[TOKENS*DFF];
__device__ __nv_bfloat16 d_w_hi[WTOTAL];
__device__ __nv_bfloat16 d_w_lo[WTOTAL];

// ---------------- small helpers ----------------
__device__ __forceinline__ float warp_sum(float v){
    #pragma unroll
    for (int o = 16; o; o >>= 1) v += __shfl_xor_sync(0xffffffffu, v, o);
    return v;
}
__device__ __forceinline__ float gelu_exact(float x){
    return 0.5f * x * (1.0f + erff(x * 0.70710678118654752440f));
}
__device__ __forceinline__ uint32_t smem_u32(const void* p){
    uint32_t a;
    asm("{ .reg .u64 t; cvta.to.shared.u64 t, %1; cvt.u32.u64 %0, t; }" : "=r"(a) : "l"(p));
    return a;
}
__device__ __forceinline__ uint32_t pack_hi2(float x, float y){
    return (__float_as_uint(x) >> 16) | (__float_as_uint(y) & 0xFFFF0000u);
}
__device__ __forceinline__ uint32_t pack_lo2(float x, float y){
    float lx = x - __uint_as_float(__float_as_uint(x) & 0xFFFF0000u);
    float ly = y - __uint_as_float(__float_as_uint(y) & 0xFFFF0000u);
    __nv_bfloat162 t = __floats2bfloat162_rn(lx, ly);
    return *reinterpret_cast<uint32_t*>(&t);
}

// ---------------- mma.sync / ldmatrix / cp.async wrappers ----------------
__device__ __forceinline__ void mma_bf16(float* d, const uint32_t* a, const uint32_t* b){
    asm volatile(
      "mma.sync.aligned.m16n8k16.row.col.f32.bf16.bf16.f32 "
      "{%0,%1,%2,%3}, {%4,%5,%6,%7}, {%8,%9}, {%0,%1,%2,%3};\n"
      : "+f"(d[0]), "+f"(d[1]), "+f"(d[2]), "+f"(d[3])
      : "r"(a[0]), "r"(a[1]), "r"(a[2]), "r"(a[3]), "r"(b[0]), "r"(b[1]));
}
__device__ __forceinline__ void ldsm_x4(uint32_t* r, uint32_t addr){
    asm volatile("ldmatrix.sync.aligned.m8n8.x4.shared.b16 {%0,%1,%2,%3}, [%4];"
      : "=r"(r[0]), "=r"(r[1]), "=r"(r[2]), "=r"(r[3]) : "r"(addr));
}
__device__ __forceinline__ void ldsm_x2(uint32_t* r, uint32_t addr){
    asm volatile("ldmatrix.sync.aligned.m8n8.x2.shared.b16 {%0,%1}, [%2];"
      : "=r"(r[0]), "=r"(r[1]) : "r"(addr));
}
__device__ __forceinline__ void ldsm_x2t(uint32_t* r, uint32_t addr){
    asm volatile("ldmatrix.sync.aligned.m8n8.x2.trans.shared.b16 {%0,%1}, [%2];"
      : "=r"(r[0]), "=r"(r[1]) : "r"(addr));
}
__device__ __forceinline__ void cp16(uint32_t s, const void* g){
    asm volatile("cp.async.cg.shared.global [%0], [%1], 16;\n" :: "r"(s), "l"(g));
}

// ---------------- GEMM smem layout (2 stages -> 2 CTAs/SM) ----------------
#define KC          32
#define A_STRIDE    80
#define B_STRIDE    272
#define A_LO_OFF    10240
#define B_OFF       20480
#define B_LO_OFF    8704
#define STAGE_BYTES 37888
#define GEMM_SMEM   (2*STAGE_BYTES)   // 75776 -> two CTAs per SM

__device__ __forceinline__ void issue_stage(
    const __nv_bfloat16* __restrict__ Ah, const __nv_bfloat16* __restrict__ Al,
    const __nv_bfloat16* __restrict__ Bh, const __nv_bfloat16* __restrict__ Bl,
    uint32_t sb0, int tid, int m0, int n0, int K, int N, int c)
{
    uint32_t sb = sb0 + (uint32_t)(c & 1) * STAGE_BYTES;
    int k0 = c * KC;
    #pragma unroll
    for (int i = 0; i < 2; i++){
        int idx = tid + i*256;
        int r = idx >> 2, cc = idx & 3;
        uint32_t sa = sb + r*A_STRIDE + cc*16;
        size_t g = (size_t)(m0 + r) * K + k0 + cc*8;
        cp16(sa,            Ah + g);
        cp16(sa + A_LO_OFF, Al + g);
    }
    #pragma unroll
    for (int i = 0; i < 2; i++){
        int idx = tid + i*256;
        int r = idx >> 4, cc = idx & 15;
        uint32_t sa = sb + B_OFF + r*B_STRIDE + cc*16;
        size_t g = (size_t)(k0 + r) * N + n0 + cc*8;
        cp16(sa,            Bh + g);
        cp16(sa + B_LO_OFF, Bl + g);
    }
    asm volatile("cp.async.commit_group;");
}

// =====================================================================
// bf16x3 emulated-fp32 GEMM:  C[M,N] = epi(A @ B + bias)
// 2-stage pipeline, 2 CTAs/SM (cross-CTA overlap of barriers/epilogue).
// EPI: 0 = bias (f32)  1 = bias+residual (f32)
//      2 = bias+GELU -> split bf16 hi/lo   3 = bias -> split bf16 hi/lo
// =====================================================================
template<int EPI>
__global__ __launch_bounds__(256, 2)
void gemm_bf16x3(const __nv_bfloat16* __restrict__ Ah, const __nv_bfloat16* __restrict__ Al,
                 const __nv_bfloat16* __restrict__ Bh, const __nv_bfloat16* __restrict__ Bl,
                 const float* __restrict__ bias, const float* __restrict__ res,
                 float* __restrict__ C,
                 __nv_bfloat16* __restrict__ Chi, __nv_bfloat16* __restrict__ Clo,
                 int M, int N, int K)
{
    extern __shared__ char smem[];
    const uint32_t sb0 = smem_u32(smem);
    const int tid  = threadIdx.x;
    const int lane = tid & 31, wid = tid >> 5;
    const int m0 = blockIdx.y * 128, n0 = blockIdx.x * 128;
    const int wm = (wid >> 2) * 64, wn = (wid & 3) * 32;

    float acc[4][4][4];
    #pragma unroll
    for (int a = 0; a < 4; a++)
        #pragma unroll
        for (int b = 0; b < 4; b++)
            #pragma unroll
            for (int cc = 0; cc < 4; cc++) acc[a][b][cc] = 0.f;

    const int nch = K / KC;
    issue_stage(Ah, Al, Bh, Bl, sb0, tid, m0, n0, K, N, 0);
    issue_stage(Ah, Al, Bh, Bl, sb0, tid, m0, n0, K, N, 1);

    const uint32_t a_lrow = wm + (lane & 15);
    const uint32_t a_lcol = (lane >> 4) * 8;
    const uint32_t b_lrow = (lane & 15);

    for (int c = 0; c < nch; c++){
        asm volatile("cp.async.wait_group %0;" :: "n"(1));
        __syncthreads();

        uint32_t sb = sb0 + (uint32_t)(c & 1) * STAGE_BYTES;
        #pragma unroll
        for (int ks = 0; ks < 2; ks++){
            uint32_t ah[4][4], al[4][4], bh[4][2], bl[4][2];
            #pragma unroll
            for (int mt = 0; mt < 4; mt++){
                uint32_t ad = sb + (a_lrow + mt*16)*A_STRIDE + (ks*16 + a_lcol)*2;
                ldsm_x4(ah[mt], ad);
                ldsm_x4(al[mt], ad + A_LO_OFF);
            }
            #pragma unroll
            for (int nt = 0; nt < 4; nt++){
                uint32_t bd = sb + B_OFF + (ks*16 + b_lrow)*B_STRIDE + (wn + nt*8)*2;
                ldsm_x2t(bh[nt], bd);
                ldsm_x2t(bl[nt], bd + B_LO_OFF);
            }
            #pragma unroll
            for (int mt = 0; mt < 4; mt++)
                #pragma unroll
                for (int nt = 0; nt < 4; nt++)
                    mma_bf16(acc[mt][nt], ah[mt], bh[nt]);
            #pragma unroll
            for (int mt = 0; mt < 4; mt++)
                #pragma unroll
                for (int nt = 0; nt < 4; nt++)
                    mma_bf16(acc[mt][nt], ah[mt], bl[nt]);
            #pragma unroll
            for (int mt = 0; mt < 4; mt++)
                #pragma unroll
                for (int nt = 0; nt < 4; nt++)
                    mma_bf16(acc[mt][nt], al[mt], bh[nt]);
        }
        __syncthreads();    // all reads of buffer (c&1) done before re-fill
        if (c + 2 < nch) issue_stage(Ah, Al, Bh, Bl, sb0, tid, m0, n0, K, N, c + 2);
        else asm volatile("cp.async.commit_group;");
    }

    // ---- epilogue ----
    const int g  = lane >> 2;
    const int tq = (lane & 3) * 2;
    #pragma unroll
    for (int mt = 0; mt < 4; mt++){
        #pragma unroll
        for (int half = 0; half < 2; half++){
            int m = m0 + wm + mt*16 + g + half*8;
            #pragma unroll
            for (int nt = 0; nt < 4; nt++){
                int n = n0 + wn + nt*8 + tq;
                float v0 = acc[mt][nt][half*2+0] + bias[n];
                float v1 = acc[mt][nt][half*2+1] + bias[n+1];
                size_t gi = (size_t)m * N + n;
                if (EPI == 1){ v0 += res[gi]; v1 += res[gi+1]; }
                if (EPI >= 2){
                    if (EPI == 2){ v0 = gelu_exact(v0); v1 = gelu_exact(v1); }
                    *(uint32_t*)&Chi[gi] = pack_hi2(v0, v1);
                    *(uint32_t*)&Clo[gi] = pack_lo2(v0, v1);
                } else {
                    float2 o; o.x = v0; o.y = v1;
                    *(float2*)&C[gi] = o;
                }
            }
        }
    }
}

// =====================================================================
// Flash attention, bf16x3, causal.  Bq=128 (8 warps x 16 rows), Bc=64.
// =====================================================================
#define FL_SMEM 110592

__global__ __launch_bounds__(256)
void flash_kernel(const __nv_bfloat16* __restrict__ qkv_hi,
                  const __nv_bfloat16* __restrict__ qkv_lo,
                  __nv_bfloat16* __restrict__ o_hi,
                  __nv_bfloat16* __restrict__ o_lo)
{
    extern __shared__ char fsm[];
    const uint32_t sb = smem_u32(fsm);
    const int tid = threadIdx.x, lane = tid & 31, w = tid >> 5;
    const int bh = blockIdx.x;
    const int it = 7 - blockIdx.y;           // heavy q-tiles first
    const int b = bh >> 4, h = bh & 15;
    const int nk = 2*(it+1);
    const size_t rs = 3*DMODEL;

    {
        const size_t tok0 = (size_t)(b*SEQ + it*128);
        #pragma unroll
        for (int i = 0; i < 4; i++){
            int idx = tid + i*256;
            int r = idx >> 3, c = idx & 7;
            size_t g = (tok0 + r)*rs + h*64 + c*8;
            uint32_t sa = sb + r*144 + c*16;
            cp16(sa,         qkv_hi + g);
            cp16(sa + 18432, qkv_lo + g);
        }
        asm volatile("cp.async.commit_group;");
    }
    #define ISSUE_KV(jt_) do {                                               \
        uint32_t st_ = sb + 36864u + (uint32_t)((jt_)&1)*36864u;             \
        const size_t tok0_ = (size_t)(b*SEQ + (jt_)*64);                     \
        _Pragma("unroll")                                                    \
        for (int i_ = 0; i_ < 2; i_++){                                      \
            int idx_ = tid + i_*256;                                         \
            int r_ = idx_ >> 3, c_ = idx_ & 7;                               \
            size_t gk_ = (tok0_ + r_)*rs + DMODEL   + h*64 + c_*8;           \
            size_t gv_ = (tok0_ + r_)*rs + 2*DMODEL + h*64 + c_*8;           \
            uint32_t sa_ = st_ + r_*144 + c_*16;                             \
            cp16(sa_,         qkv_hi + gk_);                                 \
            cp16(sa_ + 9216,  qkv_lo + gk_);                                 \
            cp16(sa_ + 18432, qkv_hi + gv_);                                 \
            cp16(sa_ + 27648, qkv_lo + gv_);                                 \
        }                                                                    \
        asm volatile("cp.async.commit_group;");                              \
    } while(0)

    ISSUE_KV(0);
    asm volatile("cp.async.wait_group 1;");   // Q ready
    __syncthreads();

    uint32_t qh[4][4], ql[4][4];
    {
        uint32_t rbase = sb + (w*16 + (lane & 15))*144 + ((lane >> 4)*8)*2;
        #pragma unroll
        for (int ks = 0; ks < 4; ks++){
            ldsm_x4(qh[ks], rbase + ks*32);
            ldsm_x4(ql[ks], rbase + ks*32 + 18432);
        }
    }

    float O[8][4];
    #pragma unroll
    for (int nt = 0; nt < 8; nt++)
        #pragma unroll
        for (int c = 0; c < 4; c++) O[nt][c] = 0.f;
    float m0 = -INFINITY, m1 = -INFINITY, l0 = 0.f, l1 = 0.f;
    const int r0g = it*128 + w*16 + (lane >> 2);

    for (int jt = 0; jt < nk; jt++){
        if (jt + 1 < nk){ ISSUE_KV(jt+1); asm volatile("cp.async.wait_group 1;"); }
        else            { asm volatile("cp.async.wait_group 0;"); }
        __syncthreads();
        const uint32_t st = sb + 36864u + (uint32_t)(jt&1)*36864u;

        float S[8][4];
        #pragma unroll
        for (int nt = 0; nt < 8; nt++)
            #pragma unroll
            for (int c = 0; c < 4; c++) S[nt][c] = 0.f;

        const uint32_t kb = st + (lane & 7)*144 + (((lane >> 3) & 1)*8)*2;
        #pragma unroll
        for (int nt = 0; nt < 8; nt++){
            #pragma unroll
            for (int ks = 0; ks < 4; ks++){
                uint32_t a = kb + nt*8*144 + ks*32;
                uint32_t kh[2], kl[2];
                ldsm_x2(kh, a);
                ldsm_x2(kl, a + 9216);
                mma_bf16(S[nt], qh[ks], kh);
                mma_bf16(S[nt], qh[ks], kl);
                mma_bf16(S[nt], ql[ks], kh);
            }
        }

        const bool diag = (jt >= 2*it);
        float mx0 = -INFINITY, mx1 = -INFINITY;
        #pragma unroll
        for (int nt = 0; nt < 8; nt++){
            int colb = jt*64 + nt*8 + (lane & 3)*2;
            #pragma unroll
            for (int q = 0; q < 2; q++){
                float v0 = S[nt][q]   * 0.125f;
                float v1 = S[nt][2+q] * 0.125f;
                if (diag){
                    if (colb + q > r0g)     v0 = -INFINITY;
                    if (colb + q > r0g + 8) v1 = -INFINITY;
                }
                S[nt][q] = v0; S[nt][2+q] = v1;
                mx0 = fmaxf(mx0, v0); mx1 = fmaxf(mx1, v1);
            }
        }
        mx0 = fmaxf(mx0, __shfl_xor_sync(0xffffffffu, mx0, 1));
        mx0 = fmaxf(mx0, __shfl_xor_sync(0xffffffffu, mx0, 2));
        mx1 = fmaxf(mx1, __shfl_xor_sync(0xffffffffu, mx1, 1));
        mx1 = fmaxf(mx1, __shfl_xor_sync(0xffffffffu, mx1, 2));
        float mn0 = fmaxf(m0, mx0), mn1 = fmaxf(m1, mx1);
        float f0 = __expf(m0 - mn0), f1 = __expf(m1 - mn1);
        m0 = mn0; m1 = mn1;
        float ls0 = 0.f, ls1 = 0.f;
        #pragma unroll
        for (int nt = 0; nt < 8; nt++){
            #pragma unroll
            for (int q = 0; q < 2; q++){
                float e0 = __expf(S[nt][q]   - m0);
                float e1 = __expf(S[nt][2+q] - m1);
                S[nt][q] = e0; S[nt][2+q] = e1;
                ls0 += e0; ls1 += e1;
            }
        }
        l0 = l0*f0 + ls0;
        l1 = l1*f1 + ls1;
        #pragma unroll
        for (int nt = 0; nt < 8; nt++){
            O[nt][0] *= f0; O[nt][1] *= f0;
            O[nt][2] *= f1; O[nt][3] *= f1;
        }

        #pragma unroll
        for (int ks = 0; ks < 4; ks++){
            uint32_t ph[4], pl[4];
            ph[0] = pack_hi2(S[2*ks][0],   S[2*ks][1]);
            ph[1] = pack_hi2(S[2*ks][2],   S[2*ks][3]);
            ph[2] = pack_hi2(S[2*ks+1][0], S[2*ks+1][1]);
            ph[3] = pack_hi2(S[2*ks+1][2], S[2*ks+1][3]);
            pl[0] = pack_lo2(S[2*ks][0],   S[2*ks][1]);
            pl[1] = pack_lo2(S[2*ks][2],   S[2*ks][3]);
            pl[2] = pack_lo2(S[2*ks+1][0], S[2*ks+1][1]);
            pl[3] = pack_lo2(S[2*ks+1][2], S[2*ks+1][3]);
            uint32_t vb = st + 18432u + (ks*16 + (lane & 15))*144;
            #pragma unroll
            for (int nt = 0; nt < 8; nt++){
                uint32_t vh[2], vl[2];
                ldsm_x2t(vh, vb + nt*16);
                ldsm_x2t(vl, vb + nt*16 + 9216);
                mma_bf16(O[nt], ph, vh);
                mma_bf16(O[nt], ph, vl);
                mma_bf16(O[nt], pl, vh);
            }
        }
        __syncthreads();
    }

    l0 += __shfl_xor_sync(0xffffffffu, l0, 1);
    l0 += __shfl_xor_sync(0xffffffffu, l0, 2);
    l1 += __shfl_xor_sync(0xffffffffu, l1, 1);
    l1 += __shfl_xor_sync(0xffffffffu, l1, 2);
    float inv0 = 1.0f / l0, inv1 = 1.0f / l1;
    const size_t tok0 = (size_t)(b*SEQ + it*128 + w*16 + (lane >> 2));
    const int colb = h*64 + (lane & 3)*2;
    #pragma unroll
    for (int nt = 0; nt < 8; nt++){
        #pragma unroll
        for (int rh = 0; rh < 2; rh++){
            float inv = rh ? inv1 : inv0;
            float v0 = O[nt][rh*2+0] * inv;
            float v1 = O[nt][rh*2+1] * inv;
            size_t gi = (tok0 + rh*8)*DMODEL + colb + nt*8;
            *(uint32_t*)&o_hi[gi] = pack_hi2(v0, v1);
            *(uint32_t*)&o_lo[gi] = pack_lo2(v0, v1);
        }
    }
}

// ---------------- weight split: fp32 -> bf16 hi/lo ----------------
__global__ void wsplit_kernel(const float4* __restrict__ in,
                              uint2* __restrict__ hi, uint2* __restrict__ lo, int n4){
    int i = blockIdx.x * blockDim.x + threadIdx.x;
    if (i >= n4) return;
    float4 v = in[i];
    uint2 H, L;
    H.x = pack_hi2(v.x, v.y); H.y = pack_hi2(v.z, v.w);
    L.x = pack_lo2(v.x, v.y); L.y = pack_lo2(v.z, v.w);
    hi[i] = H; lo[i] = L;
}

// ---------------- copy x -> h ----------------
__global__ void copy_kernel(const float* __restrict__ in, float* __restrict__ out){
    int idx = blockIdx.x * blockDim.x + threadIdx.x;
    float4 v = ((const float4*)in)[idx];
    ((float4*)out)[idx] = v;
}

// ---------------- LayerNorm (bf16 hi/lo out; fp32 out optional) ----------------
template<bool WF32>
__global__ void ln_kernel(const float* __restrict__ in,
                          const float* __restrict__ w,
                          const float* __restrict__ b,
                          float* __restrict__ out,
                          __nv_bfloat16* __restrict__ out_hi,
                          __nv_bfloat16* __restrict__ out_lo){
    int row = blockIdx.x;
    int t   = threadIdx.x;
    const float* x = in + (size_t)row * DMODEL;
    float4 v = *(const float4*)&x[t*4];
    float s  = v.x + v.y + v.z + v.w;
    float sq = v.x*v.x + v.y*v.y + v.z*v.z + v.w*v.w;
    s  = warp_sum(s);
    sq = warp_sum(sq);
    __shared__ float sh1[8], sh2[8];
    int warp = t >> 5, lane = t & 31;
    if (lane == 0){ sh1[warp] = s; sh2[warp] = sq; }
    __syncthreads();
    float tot = 0.f, tot2 = 0.f;
    #pragma unroll
    for (int i = 0; i < 8; i++){ tot += sh1[i]; tot2 += sh2[i]; }
    float mu   = tot  * (1.0f/DMODEL);
    float var  = tot2 * (1.0f/DMODEL) - mu*mu;
    float rstd = rsqrtf(var + EPS);
    float4 wv = *(const float4*)&w[t*4];
    float4 bv = *(const float4*)&b[t*4];
    float4 ov;
    ov.x = (v.x - mu)*rstd*wv.x + bv.x;
    ov.y = (v.y - mu)*rstd*wv.y + bv.y;
    ov.z = (v.z - mu)*rstd*wv.z + bv.z;
    ov.w = (v.w - mu)*rstd*wv.w + bv.w;
    size_t base = (size_t)row*DMODEL + t*4;
    if (WF32) *(float4*)&out[base] = ov;
    uint2 H, L;
    H.x = pack_hi2(ov.x, ov.y); H.y = pack_hi2(ov.z, ov.w);
    L.x = pack_lo2(ov.x, ov.y); L.y = pack_lo2(ov.z, ov.w);
    *(uint2*)&out_hi[base] = H;
    *(uint2*)&out_lo[base] = L;
}

// ---------------- final projection ----------------
__global__ __launch_bounds__(256)
void pred_kernel(const float* __restrict__ hn, const float* __restrict__ Wp,
                 const float* __restrict__ bp, float* __restrict__ out){
    int row = blockIdx.x;
    int t = threadIdx.x;
    float local[WIN] = {0,0,0,0,0};
    const float* x = hn + (size_t)row * DMODEL;
    for (int k = t; k < DMODEL; k += 256){
        float xv = x[k];
        const float* wr = Wp + (size_t)k * WIN;
        #pragma unroll
        for (int w = 0; w < WIN; w++) local[w] = fmaf(xv, wr[w], local[w]);
    }
    __shared__ float red[WIN][256];
    #pragma unroll
    for (int w = 0; w < WIN; w++) red[w][t] = local[w];
    __syncthreads();
    for (int s = 128; s > 0; s >>= 1){
        if (t < s){
            #pragma unroll
            for (int w = 0; w < WIN; w++) red[w][t] += red[w][t + s];
        }
        __syncthreads();
    }
    if (t < WIN) out[(size_t)row * WIN + t] = red[t][0] + bp[t];
}

// ---------------- host orchestration ----------------
extern "C" void kernel_launch(void* const* d_in, const int* in_sizes, int n_in,
                              void* d_out, int out_size){
    const float* x     = (const float*)d_in[0];
    const float* Wqkv  = (const float*)d_in[1];
    const float* bqkv  = (const float*)d_in[2];
    const float* Wo    = (const float*)d_in[3];
    const float* bo    = (const float*)d_in[4];
    const float* ln1w  = (const float*)d_in[5];
    const float* ln1b  = (const float*)d_in[6];
    const float* W1    = (const float*)d_in[7];
    const float* b1    = (const float*)d_in[8];
    const float* W2    = (const float*)d_in[9];
    const float* b2    = (const float*)d_in[10];
    const float* ln2w  = (const float*)d_in[11];
    const float* ln2b  = (const float*)d_in[12];
    const float* lnfw  = (const float*)d_in[13];
    const float* lnfb  = (const float*)d_in[14];
    const float* Wp    = (const float*)d_in[15];
    const float* bp    = (const float*)d_in[16];
    float* out = (float*)d_out;

    float *g_h, *g_hn;
    __nv_bfloat16 *g_hn_hi, *g_hn_lo, *g_qkv_hi, *g_qkv_lo,
                  *g_o_hi, *g_o_lo, *g_ff_hi, *g_ff_lo, *g_w_hi, *g_w_lo;
    cudaGetSymbolAddress((void**)&g_h,      d_h);
    cudaGetSymbolAddress((void**)&g_hn,     d_hn);
    cudaGetSymbolAddress((void**)&g_hn_hi,  d_hn_hi);
    cudaGetSymbolAddress((void**)&g_hn_lo,  d_hn_lo);
    cudaGetSymbolAddress((void**)&g_qkv_hi, d_qkv_hi);
    cudaGetSymbolAddress((void**)&g_qkv_lo, d_qkv_lo);
    cudaGetSymbolAddress((void**)&g_o_hi,   d_o_hi);
    cudaGetSymbolAddress((void**)&g_o_lo,   d_o_lo);
    cudaGetSymbolAddress((void**)&g_ff_hi,  d_ff_hi);
    cudaGetSymbolAddress((void**)&g_ff_lo,  d_ff_lo);
    cudaGetSymbolAddress((void**)&g_w_hi,   d_w_hi);
    cudaGetSymbolAddress((void**)&g_w_lo,   d_w_lo);

    cudaFuncSetAttribute(gemm_bf16x3<0>, cudaFuncAttributeMaxDynamicSharedMemorySize, GEMM_SMEM);
    cudaFuncSetAttribute(gemm_bf16x3<1>, cudaFuncAttributeMaxDynamicSharedMemorySize, GEMM_SMEM);
    cudaFuncSetAttribute(gemm_bf16x3<2>, cudaFuncAttributeMaxDynamicSharedMemorySize, GEMM_SMEM);
    cudaFuncSetAttribute(gemm_bf16x3<3>, cudaFuncAttributeMaxDynamicSharedMemorySize, GEMM_SMEM);
    cudaFuncSetAttribute(flash_kernel,   cudaFuncAttributeMaxDynamicSharedMemorySize, FL_SMEM);

    wsplit_kernel<<<QKV_ELEMS/4/256, 256>>>((const float4*)Wqkv,
        (uint2*)(g_w_hi + QKV_OFF), (uint2*)(g_w_lo + QKV_OFF), QKV_ELEMS/4);
    wsplit_kernel<<<WO_ELEMS/4/256, 256>>>((const float4*)Wo,
        (uint2*)(g_w_hi + WO_OFF),  (uint2*)(g_w_lo + WO_OFF),  WO_ELEMS/4);
    wsplit_kernel<<<W1_ELEMS/4/256, 256>>>((const float4*)W1,
        (uint2*)(g_w_hi + W1_OFF),  (uint2*)(g_w_lo + W1_OFF),  W1_ELEMS/4);
    wsplit_kernel<<<W2_ELEMS/4/256, 256>>>((const float4*)W2,
        (uint2*)(g_w_hi + W2_OFF),  (uint2*)(g_w_lo + W2_OFF),  W2_ELEMS/4);

    copy_kernel<<<TOKENS*DMODEL/4/256, 256>>>(x, g_h);

    for (int l = 0; l < LAYERS; l++){
        const __nv_bfloat16* wqkv_h = g_w_hi + QKV_OFF + (size_t)l * DMODEL * 3*DMODEL;
        const __nv_bfloat16* wqkv_l = g_w_lo + QKV_OFF + (size_t)l * DMODEL * 3*DMODEL;
        const __nv_bfloat16* wo_h   = g_w_hi + WO_OFF  + (size_t)l * DMODEL * DMODEL;
        const __nv_bfloat16* wo_l   = g_w_lo + WO_OFF  + (size_t)l * DMODEL * DMODEL;
        const __nv_bfloat16* w1_h   = g_w_hi + W1_OFF  + (size_t)l * DMODEL * DFF;
        const __nv_bfloat16* w1_l   = g_w_lo + W1_OFF  + (size_t)l * DMODEL * DFF;
        const __nv_bfloat16* w2_h   = g_w_hi + W2_OFF  + (size_t)l * DFF * DMODEL;
        const __nv_bfloat16* w2_l   = g_w_lo + W2_OFF  + (size_t)l * DFF * DMODEL;
        const float* bq = bqkv + (size_t)l * 3*DMODEL;
        const float* bO = bo   + (size_t)l * DMODEL;
        const float* B1 = b1   + (size_t)l * DFF;
        const float* B2 = b2   + (size_t)l * DMODEL;

        // pre-norm attention
        ln_kernel<false><<<TOKENS, 256>>>(g_h, ln1w + l*DMODEL, ln1b + l*DMODEL,
                                          nullptr, g_hn_hi, g_hn_lo);
        gemm_bf16x3<3><<<dim3(3*DMODEL/128, TOKENS/128), 256, GEMM_SMEM>>>(
            g_hn_hi, g_hn_lo, wqkv_h, wqkv_l, bq, nullptr,
            nullptr, g_qkv_hi, g_qkv_lo, TOKENS, 3*DMODEL, DMODEL);
        flash_kernel<<<dim3(BATCH*NHEAD, SEQ/128), 256, FL_SMEM>>>(
            g_qkv_hi, g_qkv_lo, g_o_hi, g_o_lo);
        gemm_bf16x3<1><<<dim3(DMODEL/128, TOKENS/128), 256, GEMM_SMEM>>>(
            g_o_hi, g_o_lo, wo_h, wo_l, bO, g_h,
            g_h, nullptr, nullptr, TOKENS, DMODEL, DMODEL);

        // pre-norm FFN
        ln_kernel<false><<<TOKENS, 256>>>(g_h, ln2w + l*DMODEL, ln2b + l*DMODEL,
                                          nullptr, g_hn_hi, g_hn_lo);
        gemm_bf16x3<2><<<dim3(DFF/128, TOKENS/128), 256, GEMM_SMEM>>>(
            g_hn_hi, g_hn_lo, w1_h, w1_l, B1, nullptr,
            nullptr, g_ff_hi, g_ff_lo, TOKENS, DFF, DMODEL);
        gemm_bf16x3<1><<<dim3(DMODEL/128, TOKENS/128), 256, GEMM_SMEM>>>(
            g_ff_hi, g_ff_lo, w2_h, w2_l, B2, g_h,
            g_h, nullptr, nullptr, TOKENS, DMODEL, DFF);
    }

    // final LN + projection
    ln_kernel<true><<<TOKENS, 256>>>(g_h, lnfw, lnfb, g_hn, g_hn_hi, g_hn_lo);
    pred_kernel<<<TOKENS, 256>>>(g_hn, Wp, bp, out);
    (void)in_sizes; (void)n_in; (void)out_size;
}

// round 7
// speedup vs baseline: 1.0233x; 1.0233x over previous
#include <cuda_runtime.h>
#include <cuda_bf16.h>
#include <math.h>
#include <stdint.h>

// ---------------- problem constants ----------------
#define LAYERS 6
#define BATCH  2
#define SEQ    1024
#define DMODEL 1024
#define NHEAD  16
#define HDIM   64
#define DFF    4096
#define WIN    5
#define TOKENS (BATCH*SEQ)          // 2048
#define EPS    1e-5f

// weight scratch layout (elements)
#define QKV_ELEMS  (LAYERS*DMODEL*3*DMODEL)
#define WO_ELEMS   (LAYERS*DMODEL*DMODEL)
#define W1_ELEMS   (LAYERS*DMODEL*DFF)
#define W2_ELEMS   (LAYERS*DFF*DMODEL)
#define QKV_OFF 0
#define WO_OFF  (QKV_ELEMS)
#define W1_OFF  (WO_OFF + WO_ELEMS)
#define W2_OFF  (W1_OFF + W1_ELEMS)
#define WTOTAL  (W2_OFF + W2_ELEMS)

// ---------------- device scratch (no allocation allowed) ----------------
__device__ float d_h   [TOKENS*DMODEL];
__device__ float d_hn  [TOKENS*DMODEL];
__device__ __nv_bfloat16 d_hn_hi[TOKENS*DMODEL];
__device__ __nv_bfloat16 d_hn_lo[TOKENS*DMODEL];
__device__ __nv_bfloat16 d_qkv_hi[TOKENS*3*DMODEL];
__device__ __nv_bfloat16 d_qkv_lo[TOKENS*3*DMODEL];
__device__ __nv_bfloat16 d_o_hi[TOKENS*DMODEL];
__device__ __nv_bfloat16 d_o_lo[TOKENS*DMODEL];
__device__ __nv_bfloat16 d_ff_hi[TOKENS*DFF];
__device__ __nv_bfloat16 d_ff_lo[TOKENS*DFF];
__device__ __nv_bfloat16 d_w_hi[WTOTAL];
__device__ __nv_bfloat16 d_w_lo[WTOTAL];

// ---------------- small helpers ----------------
__device__ __forceinline__ float warp_sum(float v){
    #pragma unroll
    for (int o = 16; o; o >>= 1) v += __shfl_xor_sync(0xffffffffu, v, o);
    return v;
}
__device__ __forceinline__ float gelu_exact(float x){
    return 0.5f * x * (1.0f + erff(x * 0.70710678118654752440f));
}
__device__ __forceinline__ uint32_t smem_u32(const void* p){
    uint32_t a;
    asm("{ .reg .u64 t; cvta.to.shared.u64 t, %1; cvt.u32.u64 %0, t; }" : "=r"(a) : "l"(p));
    return a;
}
__device__ __forceinline__ uint32_t pack_hi2(float x, float y){
    return (__float_as_uint(x) >> 16) | (__float_as_uint(y) & 0xFFFF0000u);
}
__device__ __forceinline__ uint32_t pack_lo2(float x, float y){
    float lx = x - __uint_as_float(__float_as_uint(x) & 0xFFFF0000u);
    float ly = y - __uint_as_float(__float_as_uint(y) & 0xFFFF0000u);
    __nv_bfloat162 t = __floats2bfloat162_rn(lx, ly);
    return *reinterpret_cast<uint32_t*>(&t);
}

// ---------------- mma.sync / ldmatrix / cp.async wrappers ----------------
__device__ __forceinline__ void mma_bf16(float* d, const uint32_t* a, const uint32_t* b){
    asm volatile(
      "mma.sync.aligned.m16n8k16.row.col.f32.bf16.bf16.f32 "
      "{%0,%1,%2,%3}, {%4,%5,%6,%7}, {%8,%9}, {%0,%1,%2,%3};\n"
      : "+f"(d[0]), "+f"(d[1]), "+f"(d[2]), "+f"(d[3])
      : "r"(a[0]), "r"(a[1]), "r"(a[2]), "r"(a[3]), "r"(b[0]), "r"(b[1]));
}
__device__ __forceinline__ void ldsm_x4(uint32_t* r, uint32_t addr){
    asm volatile("ldmatrix.sync.aligned.m8n8.x4.shared.b16 {%0,%1,%2,%3}, [%4];"
      : "=r"(r[0]), "=r"(r[1]), "=r"(r[2]), "=r"(r[3]) : "r"(addr));
}
__device__ __forceinline__ void ldsm_x2(uint32_t* r, uint32_t addr){
    asm volatile("ldmatrix.sync.aligned.m8n8.x2.shared.b16 {%0,%1}, [%2];"
      : "=r"(r[0]), "=r"(r[1]) : "r"(addr));
}
__device__ __forceinline__ void ldsm_x2t(uint32_t* r, uint32_t addr){
    asm volatile("ldmatrix.sync.aligned.m8n8.x2.trans.shared.b16 {%0,%1}, [%2];"
      : "=r"(r[0]), "=r"(r[1]) : "r"(addr));
}
__device__ __forceinline__ void cp16(uint32_t s, const void* g){
    asm volatile("cp.async.cg.shared.global [%0], [%1], 16;\n" :: "r"(s), "l"(g));
}

// ---------------- GEMM smem layout (3 stages, 2 CTAs/SM) ----------------
#define KC          32
#define A_STRIDE    80
#define B_STRIDE    272
#define A_LO_OFF    10240
#define B_OFF       20480
#define B_LO_OFF    8704
#define STAGE_BYTES 37888
#define GEMM_SMEM   (3*STAGE_BYTES)   // 113664; 2 CTAs -> 227328 <= 228KB

__device__ __forceinline__ void issue_stage(
    const __nv_bfloat16* __restrict__ Ah, const __nv_bfloat16* __restrict__ Al,
    const __nv_bfloat16* __restrict__ Bh, const __nv_bfloat16* __restrict__ Bl,
    uint32_t sb0, int tid, int m0, int n0, int K, int N, int c)
{
    uint32_t sb = sb0 + (uint32_t)(c % 3) * STAGE_BYTES;
    int k0 = c * KC;
    #pragma unroll
    for (int i = 0; i < 2; i++){
        int idx = tid + i*256;
        int r = idx >> 2, cc = idx & 3;
        uint32_t sa = sb + r*A_STRIDE + cc*16;
        size_t g = (size_t)(m0 + r) * K + k0 + cc*8;
        cp16(sa,            Ah + g);
        cp16(sa + A_LO_OFF, Al + g);
    }
    #pragma unroll
    for (int i = 0; i < 2; i++){
        int idx = tid + i*256;
        int r = idx >> 4, cc = idx & 15;
        uint32_t sa = sb + B_OFF + r*B_STRIDE + cc*16;
        size_t g = (size_t)(k0 + r) * N + n0 + cc*8;
        cp16(sa,            Bh + g);
        cp16(sa + B_LO_OFF, Bl + g);
    }
    asm volatile("cp.async.commit_group;");
}

// =====================================================================
// bf16x3 emulated-fp32 GEMM:  C[M,N] = epi(A @ B + bias)
// 3-stage issue-early pipeline (single barrier/chunk) + 2 CTAs/SM.
// B fragments staged (bh -> hh+lh sweeps, bl -> hl sweep) to stay <=128 regs.
// EPI: 0 = bias (f32)  1 = bias+residual (f32)
//      2 = bias+GELU -> split bf16 hi/lo   3 = bias -> split bf16 hi/lo
// =====================================================================
template<int EPI>
__global__ __launch_bounds__(256, 2)
void gemm_bf16x3(const __nv_bfloat16* __restrict__ Ah, const __nv_bfloat16* __restrict__ Al,
                 const __nv_bfloat16* __restrict__ Bh, const __nv_bfloat16* __restrict__ Bl,
                 const float* __restrict__ bias, const float* __restrict__ res,
                 float* __restrict__ C,
                 __nv_bfloat16* __restrict__ Chi, __nv_bfloat16* __restrict__ Clo,
                 int M, int N, int K)
{
    extern __shared__ char smem[];
    const uint32_t sb0 = smem_u32(smem);
    const int tid  = threadIdx.x;
    const int lane = tid & 31, wid = tid >> 5;
    const int m0 = blockIdx.y * 128, n0 = blockIdx.x * 128;
    const int wm = (wid >> 2) * 64, wn = (wid & 3) * 32;

    float acc[4][4][4];
    #pragma unroll
    for (int a = 0; a < 4; a++)
        #pragma unroll
        for (int b = 0; b < 4; b++)
            #pragma unroll
            for (int cc = 0; cc < 4; cc++) acc[a][b][cc] = 0.f;

    const int nch = K / KC;
    issue_stage(Ah, Al, Bh, Bl, sb0, tid, m0, n0, K, N, 0);
    issue_stage(Ah, Al, Bh, Bl, sb0, tid, m0, n0, K, N, 1);

    const uint32_t a_lrow = wm + (lane & 15);
    const uint32_t a_lcol = (lane >> 4) * 8;
    const uint32_t b_lrow = (lane & 15);

    for (int c = 0; c < nch; c++){
        asm volatile("cp.async.wait_group %0;" :: "n"(1));
        __syncthreads();
        if (c + 2 < nch) issue_stage(Ah, Al, Bh, Bl, sb0, tid, m0, n0, K, N, c + 2);
        else asm volatile("cp.async.commit_group;");

        uint32_t sb = sb0 + (uint32_t)(c % 3) * STAGE_BYTES;
        #pragma unroll
        for (int ks = 0; ks < 2; ks++){
            uint32_t ah[4][4], al[4][4];
            #pragma unroll
            for (int mt = 0; mt < 4; mt++){
                uint32_t ad = sb + (a_lrow + mt*16)*A_STRIDE + (ks*16 + a_lcol)*2;
                ldsm_x4(ah[mt], ad);
                ldsm_x4(al[mt], ad + A_LO_OFF);
            }
            {   // hi-B phase: hh + lh sweeps
                uint32_t bh[4][2];
                #pragma unroll
                for (int nt = 0; nt < 4; nt++)
                    ldsm_x2t(bh[nt], sb + B_OFF + (ks*16 + b_lrow)*B_STRIDE + (wn + nt*8)*2);
                #pragma unroll
                for (int mt = 0; mt < 4; mt++)
                    #pragma unroll
                    for (int nt = 0; nt < 4; nt++)
                        mma_bf16(acc[mt][nt], ah[mt], bh[nt]);
                #pragma unroll
                for (int mt = 0; mt < 4; mt++)
                    #pragma unroll
                    for (int nt = 0; nt < 4; nt++)
                        mma_bf16(acc[mt][nt], al[mt], bh[nt]);
            }
            {   // lo-B phase: hl sweep
                uint32_t bl[4][2];
                #pragma unroll
                for (int nt = 0; nt < 4; nt++)
                    ldsm_x2t(bl[nt], sb + B_OFF + B_LO_OFF + (ks*16 + b_lrow)*B_STRIDE + (wn + nt*8)*2);
                #pragma unroll
                for (int mt = 0; mt < 4; mt++)
                    #pragma unroll
                    for (int nt = 0; nt < 4; nt++)
                        mma_bf16(acc[mt][nt], ah[mt], bl[nt]);
            }
        }
    }

    // ---- epilogue ----
    const int g  = lane >> 2;
    const int tq = (lane & 3) * 2;
    #pragma unroll
    for (int mt = 0; mt < 4; mt++){
        #pragma unroll
        for (int half = 0; half < 2; half++){
            int m = m0 + wm + mt*16 + g + half*8;
            #pragma unroll
            for (int nt = 0; nt < 4; nt++){
                int n = n0 + wn + nt*8 + tq;
                float v0 = acc[mt][nt][half*2+0] + bias[n];
                float v1 = acc[mt][nt][half*2+1] + bias[n+1];
                size_t gi = (size_t)m * N + n;
                if (EPI == 1){ v0 += res[gi]; v1 += res[gi+1]; }
                if (EPI >= 2){
                    if (EPI == 2){ v0 = gelu_exact(v0); v1 = gelu_exact(v1); }
                    *(uint32_t*)&Chi[gi] = pack_hi2(v0, v1);
                    *(uint32_t*)&Clo[gi] = pack_lo2(v0, v1);
                } else {
                    float2 o; o.x = v0; o.y = v1;
                    *(float2*)&C[gi] = o;
                }
            }
        }
    }
}

// =====================================================================
// Flash attention, bf16x3, causal.  Bq=128 (8 warps x 16 rows), Bc=64.
// =====================================================================
#define FL_SMEM 110592

__global__ __launch_bounds__(256)
void flash_kernel(const __nv_bfloat16* __restrict__ qkv_hi,
                  const __nv_bfloat16* __restrict__ qkv_lo,
                  __nv_bfloat16* __restrict__ o_hi,
                  __nv_bfloat16* __restrict__ o_lo)
{
    extern __shared__ char fsm[];
    const uint32_t sb = smem_u32(fsm);
    const int tid = threadIdx.x, lane = tid & 31, w = tid >> 5;
    const int bh = blockIdx.x;
    const int it = 7 - blockIdx.y;           // heavy q-tiles first
    const int b = bh >> 4, h = bh & 15;
    const int nk = 2*(it+1);
    const size_t rs = 3*DMODEL;

    {
        const size_t tok0 = (size_t)(b*SEQ + it*128);
        #pragma unroll
        for (int i = 0; i < 4; i++){
            int idx = tid + i*256;
            int r = idx >> 3, c = idx & 7;
            size_t g = (tok0 + r)*rs + h*64 + c*8;
            uint32_t sa = sb + r*144 + c*16;
            cp16(sa,         qkv_hi + g);
            cp16(sa + 18432, qkv_lo + g);
        }
        asm volatile("cp.async.commit_group;");
    }
    #define ISSUE_KV(jt_) do {                                               \
        uint32_t st_ = sb + 36864u + (uint32_t)((jt_)&1)*36864u;             \
        const size_t tok0_ = (size_t)(b*SEQ + (jt_)*64);                     \
        _Pragma("unroll")                                                    \
        for (int i_ = 0; i_ < 2; i_++){                                      \
            int idx_ = tid + i_*256;                                         \
            int r_ = idx_ >> 3, c_ = idx_ & 7;                               \
            size_t gk_ = (tok0_ + r_)*rs + DMODEL   + h*64 + c_*8;           \
            size_t gv_ = (tok0_ + r_)*rs + 2*DMODEL + h*64 + c_*8;           \
            uint32_t sa_ = st_ + r_*144 + c_*16;                             \
            cp16(sa_,         qkv_hi + gk_);                                 \
            cp16(sa_ + 9216,  qkv_lo + gk_);                                 \
            cp16(sa_ + 18432, qkv_hi + gv_);                                 \
            cp16(sa_ + 27648, qkv_lo + gv_);                                 \
        }                                                                    \
        asm volatile("cp.async.commit_group;");                              \
    } while(0)

    ISSUE_KV(0);
    asm volatile("cp.async.wait_group 1;");   // Q ready
    __syncthreads();

    uint32_t qh[4][4], ql[4][4];
    {
        uint32_t rbase = sb + (w*16 + (lane & 15))*144 + ((lane >> 4)*8)*2;
        #pragma unroll
        for (int ks = 0; ks < 4; ks++){
            ldsm_x4(qh[ks], rbase + ks*32);
            ldsm_x4(ql[ks], rbase + ks*32 + 18432);
        }
    }

    float O[8][4];
    #pragma unroll
    for (int nt = 0; nt < 8; nt++)
        #pragma unroll
        for (int c = 0; c < 4; c++) O[nt][c] = 0.f;
    float m0 = -INFINITY, m1 = -INFINITY, l0 = 0.f, l1 = 0.f;
    const int r0g = it*128 + w*16 + (lane >> 2);

    for (int jt = 0; jt < nk; jt++){
        if (jt + 1 < nk){ ISSUE_KV(jt+1); asm volatile("cp.async.wait_group 1;"); }
        else            { asm volatile("cp.async.wait_group 0;"); }
        __syncthreads();
        const uint32_t st = sb + 36864u + (uint32_t)(jt&1)*36864u;

        float S[8][4];
        #pragma unroll
        for (int nt = 0; nt < 8; nt++)
            #pragma unroll
            for (int c = 0; c < 4; c++) S[nt][c] = 0.f;

        const uint32_t kb = st + (lane & 7)*144 + (((lane >> 3) & 1)*8)*2;
        #pragma unroll
        for (int nt = 0; nt < 8; nt++){
            #pragma unroll
            for (int ks = 0; ks < 4; ks++){
                uint32_t a = kb + nt*8*144 + ks*32;
                uint32_t kh[2], kl[2];
                ldsm_x2(kh, a);
                ldsm_x2(kl, a + 9216);
                mma_bf16(S[nt], qh[ks], kh);
                mma_bf16(S[nt], qh[ks], kl);
                mma_bf16(S[nt], ql[ks], kh);
            }
        }

        const bool diag = (jt >= 2*it);
        float mx0 = -INFINITY, mx1 = -INFINITY;
        #pragma unroll
        for (int nt = 0; nt < 8; nt++){
            int colb = jt*64 + nt*8 + (lane & 3)*2;
            #pragma unroll
            for (int q = 0; q < 2; q++){
                float v0 = S[nt][q]   * 0.125f;
                float v1 = S[nt][2+q] * 0.125f;
                if (diag){
                    if (colb + q > r0g)     v0 = -INFINITY;
                    if (colb + q > r0g + 8) v1 = -INFINITY;
                }
                S[nt][q] = v0; S[nt][2+q] = v1;
                mx0 = fmaxf(mx0, v0); mx1 = fmaxf(mx1, v1);
            }
        }
        mx0 = fmaxf(mx0, __shfl_xor_sync(0xffffffffu, mx0, 1));
        mx0 = fmaxf(mx0, __shfl_xor_sync(0xffffffffu, mx0, 2));
        mx1 = fmaxf(mx1, __shfl_xor_sync(0xffffffffu, mx1, 1));
        mx1 = fmaxf(mx1, __shfl_xor_sync(0xffffffffu, mx1, 2));
        float mn0 = fmaxf(m0, mx0), mn1 = fmaxf(m1, mx1);
        float f0 = __expf(m0 - mn0), f1 = __expf(m1 - mn1);
        m0 = mn0; m1 = mn1;
        float ls0 = 0.f, ls1 = 0.f;
        #pragma unroll
        for (int nt = 0; nt < 8; nt++){
            #pragma unroll
            for (int q = 0; q < 2; q++){
                float e0 = __expf(S[nt][q]   - m0);
                float e1 = __expf(S[nt][2+q] - m1);
                S[nt][q] = e0; S[nt][2+q] = e1;
                ls0 += e0; ls1 += e1;
            }
        }
        l0 = l0*f0 + ls0;
        l1 = l1*f1 + ls1;
        #pragma unroll
        for (int nt = 0; nt < 8; nt++){
            O[nt][0] *= f0; O[nt][1] *= f0;
            O[nt][2] *= f1; O[nt][3] *= f1;
        }

        #pragma unroll
        for (int ks = 0; ks < 4; ks++){
            uint32_t ph[4], pl[4];
            ph[0] = pack_hi2(S[2*ks][0],   S[2*ks][1]);
            ph[1] = pack_hi2(S[2*ks][2],   S[2*ks][3]);
            ph[2] = pack_hi2(S[2*ks+1][0], S[2*ks+1][1]);
            ph[3] = pack_hi2(S[2*ks+1][2], S[2*ks+1][3]);
            pl[0] = pack_lo2(S[2*ks][0],   S[2*ks][1]);
            pl[1] = pack_lo2(S[2*ks][2],   S[2*ks][3]);
            pl[2] = pack_lo2(S[2*ks+1][0], S[2*ks+1][1]);
            pl[3] = pack_lo2(S[2*ks+1][2], S[2*ks+1][3]);
            uint32_t vb = st + 18432u + (ks*16 + (lane & 15))*144;
            #pragma unroll
            for (int nt = 0; nt < 8; nt++){
                uint32_t vh[2], vl[2];
                ldsm_x2t(vh, vb + nt*16);
                ldsm_x2t(vl, vb + nt*16 + 9216);
                mma_bf16(O[nt], ph, vh);
                mma_bf16(O[nt], ph, vl);
                mma_bf16(O[nt], pl, vh);
            }
        }
        __syncthreads();
    }

    l0 += __shfl_xor_sync(0xffffffffu, l0, 1);
    l0 += __shfl_xor_sync(0xffffffffu, l0, 2);
    l1 += __shfl_xor_sync(0xffffffffu, l1, 1);
    l1 += __shfl_xor_sync(0xffffffffu, l1, 2);
    float inv0 = 1.0f / l0, inv1 = 1.0f / l1;
    const size_t tok0 = (size_t)(b*SEQ + it*128 + w*16 + (lane >> 2));
    const int colb = h*64 + (lane & 3)*2;
    #pragma unroll
    for (int nt = 0; nt < 8; nt++){
        #pragma unroll
        for (int rh = 0; rh < 2; rh++){
            float inv = rh ? inv1 : inv0;
            float v0 = O[nt][rh*2+0] * inv;
            float v1 = O[nt][rh*2+1] * inv;
            size_t gi = (tok0 + rh*8)*DMODEL + colb + nt*8;
            *(uint32_t*)&o_hi[gi] = pack_hi2(v0, v1);
            *(uint32_t*)&o_lo[gi] = pack_lo2(v0, v1);
        }
    }
}

// ---------------- weight split: fp32 -> bf16 hi/lo ----------------
__global__ void wsplit_kernel(const float4* __restrict__ in,
                              uint2* __restrict__ hi, uint2* __restrict__ lo, int n4){
    int i = blockIdx.x * blockDim.x + threadIdx.x;
    if (i >= n4) return;
    float4 v = in[i];
    uint2 H, L;
    H.x = pack_hi2(v.x, v.y); H.y = pack_hi2(v.z, v.w);
    L.x = pack_lo2(v.x, v.y); L.y = pack_lo2(v.z, v.w);
    hi[i] = H; lo[i] = L;
}

// ---------------- copy x -> h ----------------
__global__ void copy_kernel(const float* __restrict__ in, float* __restrict__ out){
    int idx = blockIdx.x * blockDim.x + threadIdx.x;
    float4 v = ((const float4*)in)[idx];
    ((float4*)out)[idx] = v;
}

// ---------------- LayerNorm (bf16 hi/lo out; fp32 out optional) ----------------
template<bool WF32>
__global__ void ln_kernel(const float* __restrict__ in,
                          const float* __restrict__ w,
                          const float* __restrict__ b,
                          float* __restrict__ out,
                          __nv_bfloat16* __restrict__ out_hi,
                          __nv_bfloat16* __restrict__ out_lo){
    int row = blockIdx.x;
    int t   = threadIdx.x;
    const float* x = in + (size_t)row * DMODEL;
    float4 v = *(const float4*)&x[t*4];
    float s  = v.x + v.y + v.z + v.w;
    float sq = v.x*v.x + v.y*v.y + v.z*v.z + v.w*v.w;
    s  = warp_sum(s);
    sq = warp_sum(sq);
    __shared__ float sh1[8], sh2[8];
    int warp = t >> 5, lane = t & 31;
    if (lane == 0){ sh1[warp] = s; sh2[warp] = sq; }
    __syncthreads();
    float tot = 0.f, tot2 = 0.f;
    #pragma unroll
    for (int i = 0; i < 8; i++){ tot += sh1[i]; tot2 += sh2[i]; }
    float mu   = tot  * (1.0f/DMODEL);
    float var  = tot2 * (1.0f/DMODEL) - mu*mu;
    float rstd = rsqrtf(var + EPS);
    float4 wv = *(const float4*)&w[t*4];
    float4 bv = *(const float4*)&b[t*4];
    float4 ov;
    ov.x = (v.x - mu)*rstd*wv.x + bv.x;
    ov.y = (v.y - mu)*rstd*wv.y + bv.y;
    ov.z = (v.z - mu)*rstd*wv.z + bv.z;
    ov.w = (v.w - mu)*rstd*wv.w + bv.w;
    size_t base = (size_t)row*DMODEL + t*4;
    if (WF32) *(float4*)&out[base] = ov;
    uint2 H, L;
    H.x = pack_hi2(ov.x, ov.y); H.y = pack_hi2(ov.z, ov.w);
    L.x = pack_lo2(ov.x, ov.y); L.y = pack_lo2(ov.z, ov.w);
    *(uint2*)&out_hi[base] = H;
    *(uint2*)&out_lo[base] = L;
}

// ---------------- final projection ----------------
__global__ __launch_bounds__(256)
void pred_kernel(const float* __restrict__ hn, const float* __restrict__ Wp,
                 const float* __restrict__ bp, float* __restrict__ out){
    int row = blockIdx.x;
    int t = threadIdx.x;
    float local[WIN] = {0,0,0,0,0};
    const float* x = hn + (size_t)row * DMODEL;
    for (int k = t; k < DMODEL; k += 256){
        float xv = x[k];
        const float* wr = Wp + (size_t)k * WIN;
        #pragma unroll
        for (int w = 0; w < WIN; w++) local[w] = fmaf(xv, wr[w], local[w]);
    }
    __shared__ float red[WIN][256];
    #pragma unroll
    for (int w = 0; w < WIN; w++) red[w][t] = local[w];
    __syncthreads();
    for (int s = 128; s > 0; s >>= 1){
        if (t < s){
            #pragma unroll
            for (int w = 0; w < WIN; w++) red[w][t] += red[w][t + s];
        }
        __syncthreads();
    }
    if (t < WIN) out[(size_t)row * WIN + t] = red[t][0] + bp[t];
}

// ---------------- host orchestration ----------------
extern "C" void kernel_launch(void* const* d_in, const int* in_sizes, int n_in,
                              void* d_out, int out_size){
    const float* x     = (const float*)d_in[0];
    const float* Wqkv  = (const float*)d_in[1];
    const float* bqkv  = (const float*)d_in[2];
    const float* Wo    = (const float*)d_in[3];
    const float* bo    = (const float*)d_in[4];
    const float* ln1w  = (const float*)d_in[5];
    const float* ln1b  = (const float*)d_in[6];
    const float* W1    = (const float*)d_in[7];
    const float* b1    = (const float*)d_in[8];
    const float* W2    = (const float*)d_in[9];
    const float* b2    = (const float*)d_in[10];
    const float* ln2w  = (const float*)d_in[11];
    const float* ln2b  = (const float*)d_in[12];
    const float* lnfw  = (const float*)d_in[13];
    const float* lnfb  = (const float*)d_in[14];
    const float* Wp    = (const float*)d_in[15];
    const float* bp    = (const float*)d_in[16];
    float* out = (float*)d_out;

    float *g_h, *g_hn;
    __nv_bfloat16 *g_hn_hi, *g_hn_lo, *g_qkv_hi, *g_qkv_lo,
                  *g_o_hi, *g_o_lo, *g_ff_hi, *g_ff_lo, *g_w_hi, *g_w_lo;
    cudaGetSymbolAddress((void**)&g_h,      d_h);
    cudaGetSymbolAddress((void**)&g_hn,     d_hn);
    cudaGetSymbolAddress((void**)&g_hn_hi,  d_hn_hi);
    cudaGetSymbolAddress((void**)&g_hn_lo,  d_hn_lo);
    cudaGetSymbolAddress((void**)&g_qkv_hi, d_qkv_hi);
    cudaGetSymbolAddress((void**)&g_qkv_lo, d_qkv_lo);
    cudaGetSymbolAddress((void**)&g_o_hi,   d_o_hi);
    cudaGetSymbolAddress((void**)&g_o_lo,   d_o_lo);
    cudaGetSymbolAddress((void**)&g_ff_hi,  d_ff_hi);
    cudaGetSymbolAddress((void**)&g_ff_lo,  d_ff_lo);
    cudaGetSymbolAddress((void**)&g_w_hi,   d_w_hi);
    cudaGetSymbolAddress((void**)&g_w_lo,   d_w_lo);

    cudaFuncSetAttribute(gemm_bf16x3<0>, cudaFuncAttributeMaxDynamicSharedMemorySize, GEMM_SMEM);
    cudaFuncSetAttribute(gemm_bf16x3<1>, cudaFuncAttributeMaxDynamicSharedMemorySize, GEMM_SMEM);
    cudaFuncSetAttribute(gemm_bf16x3<2>, cudaFuncAttributeMaxDynamicSharedMemorySize, GEMM_SMEM);
    cudaFuncSetAttribute(gemm_bf16x3<3>, cudaFuncAttributeMaxDynamicSharedMemorySize, GEMM_SMEM);
    cudaFuncSetAttribute(flash_kernel,   cudaFuncAttributeMaxDynamicSharedMemorySize, FL_SMEM);

    wsplit_kernel<<<QKV_ELEMS/4/256, 256>>>((const float4*)Wqkv,
        (uint2*)(g_w_hi + QKV_OFF), (uint2*)(g_w_lo + QKV_OFF), QKV_ELEMS/4);
    wsplit_kernel<<<WO_ELEMS/4/256, 256>>>((const float4*)Wo,
        (uint2*)(g_w_hi + WO_OFF),  (uint2*)(g_w_lo + WO_OFF),  WO_ELEMS/4);
    wsplit_kernel<<<W1_ELEMS/4/256, 256>>>((const float4*)W1,
        (uint2*)(g_w_hi + W1_OFF),  (uint2*)(g_w_lo + W1_OFF),  W1_ELEMS/4);
    wsplit_kernel<<<W2_ELEMS/4/256, 256>>>((const float4*)W2,
        (uint2*)(g_w_hi + W2_OFF),  (uint2*)(g_w_lo + W2_OFF),  W2_ELEMS/4);

    copy_kernel<<<TOKENS*DMODEL/4/256, 256>>>(x, g_h);

    for (int l = 0; l < LAYERS; l++){
        const __nv_bfloat16* wqkv_h = g_w_hi + QKV_OFF + (size_t)l * DMODEL * 3*DMODEL;
        const __nv_bfloat16* wqkv_l = g_w_lo + QKV_OFF + (size_t)l * DMODEL * 3*DMODEL;
        const __nv_bfloat16* wo_h   = g_w_hi + WO_OFF  + (size_t)l * DMODEL * DMODEL;
        const __nv_bfloat16* wo_l   = g_w_lo + WO_OFF  + (size_t)l * DMODEL * DMODEL;
        const __nv_bfloat16* w1_h   = g_w_hi + W1_OFF  + (size_t)l * DMODEL * DFF;
        const __nv_bfloat16* w1_l   = g_w_lo + W1_OFF  + (size_t)l * DMODEL * DFF;
        const __nv_bfloat16* w2_h   = g_w_hi + W2_OFF  + (size_t)l * DFF * DMODEL;
        const __nv_bfloat16* w2_l   = g_w_lo + W2_OFF  + (size_t)l * DFF * DMODEL;
        const float* bq = bqkv + (size_t)l * 3*DMODEL;
        const float* bO = bo   + (size_t)l * DMODEL;
        const float* B1 = b1   + (size_t)l * DFF;
        const float* B2 = b2   + (size_t)l * DMODEL;

        // pre-norm attention
        ln_kernel<false><<<TOKENS, 256>>>(g_h, ln1w + l*DMODEL, ln1b + l*DMODEL,
                                          nullptr, g_hn_hi, g_hn_lo);
        gemm_bf16x3<3><<<dim3(3*DMODEL/128, TOKENS/128), 256, GEMM_SMEM>>>(
            g_hn_hi, g_hn_lo, wqkv_h, wqkv_l, bq, nullptr,
            nullptr, g_qkv_hi, g_qkv_lo, TOKENS, 3*DMODEL, DMODEL);
        flash_kernel<<<dim3(BATCH*NHEAD, SEQ/128), 256, FL_SMEM>>>(
            g_qkv_hi, g_qkv_lo, g_o_hi, g_o_lo);
        gemm_bf16x3<1><<<dim3(DMODEL/128, TOKENS/128), 256, GEMM_SMEM>>>(
            g_o_hi, g_o_lo, wo_h, wo_l, bO, g_h,
            g_h, nullptr, nullptr, TOKENS, DMODEL, DMODEL);

        // pre-norm FFN
        ln_kernel<false><<<TOKENS, 256>>>(g_h, ln2w + l*DMODEL, ln2b + l*DMODEL,
                                          nullptr, g_hn_hi, g_hn_lo);
        gemm_bf16x3<2><<<dim3(DFF/128, TOKENS/128), 256, GEMM_SMEM>>>(
            g_hn_hi, g_hn_lo, w1_h, w1_l, B1, nullptr,
            nullptr, g_ff_hi, g_ff_lo, TOKENS, DFF, DMODEL);
        gemm_bf16x3<1><<<dim3(DMODEL/128, TOKENS/128), 256, GEMM_SMEM>>>(
            g_ff_hi, g_ff_lo, w2_h, w2_l, B2, g_h,
            g_h, nullptr, nullptr, TOKENS, DMODEL, DFF);
    }

    // final LN + projection
    ln_kernel<true><<<TOKENS, 256>>>(g_h, lnfw, lnfb, g_hn, g_hn_hi, g_hn_lo);
    pred_kernel<<<TOKENS, 256>>>(g_hn, Wp, bp, out);
    (void)in_sizes; (void)n_in; (void)out_size;
}

// round 8
// speedup vs baseline: 1.1961x; 1.1688x over previous
#include <cuda_runtime.h>
#include <cuda_bf16.h>
#include <cuda_fp16.h>
#include <math.h>
#include <stdint.h>

// ---------------- problem constants ----------------
#define LAYERS 6
#define BATCH  2
#define SEQ    1024
#define DMODEL 1024
#define NHEAD  16
#define HDIM   64
#define DFF    4096
#define WIN    5
#define TOKENS (BATCH*SEQ)          // 2048
#define EPS    1e-5f

// weight scratch layout
#define QKV_ELEMS  (LAYERS*DMODEL*3*DMODEL)
#define WO_ELEMS   (LAYERS*DMODEL*DMODEL)
#define W1_ELEMS   (LAYERS*DMODEL*DFF)
#define W2_ELEMS   (LAYERS*DFF*DMODEL)
#define QKV_OFF 0
#define WO_OFF  (QKV_ELEMS)
#define WTOT_BF (QKV_ELEMS + WO_ELEMS)

// ---------------- device scratch (no allocation allowed) ----------------
__device__ float d_h   [TOKENS*DMODEL];
__device__ float d_hn  [TOKENS*DMODEL];
__device__ __nv_bfloat16 d_hn_hi[TOKENS*DMODEL];   // bf16 OR fp16 bits (2B slots)
__device__ __nv_bfloat16 d_hn_lo[TOKENS*DMODEL];
__device__ __nv_bfloat16 d_qkv_hi[TOKENS*3*DMODEL];
__device__ __nv_bfloat16 d_qkv_lo[TOKENS*3*DMODEL];
__device__ __nv_bfloat16 d_o_hi[TOKENS*DMODEL];
__device__ __nv_bfloat16 d_o_lo[TOKENS*DMODEL];
__device__ __half d_ff_hi[TOKENS*DFF];             // fp16 split GELU output
__device__ __half d_ff_lo[TOKENS*DFF];
__device__ __nv_bfloat16 d_w_hi[WTOT_BF];
__device__ __nv_bfloat16 d_w_lo[WTOT_BF];
__device__ __half d_wf16[W1_ELEMS + W2_ELEMS];     // fp16 single weights (W1, W2)

// ---------------- small helpers ----------------
__device__ __forceinline__ float warp_sum(float v){
    #pragma unroll
    for (int o = 16; o; o >>= 1) v += __shfl_xor_sync(0xffffffffu, v, o);
    return v;
}
__device__ __forceinline__ float gelu_exact(float x){
    return 0.5f * x * (1.0f + erff(x * 0.70710678118654752440f));
}
__device__ __forceinline__ uint32_t smem_u32(const void* p){
    uint32_t a;
    asm("{ .reg .u64 t; cvta.to.shared.u64 t, %1; cvt.u32.u64 %0, t; }" : "=r"(a) : "l"(p));
    return a;
}
__device__ __forceinline__ uint32_t pack_hi2(float x, float y){
    return (__float_as_uint(x) >> 16) | (__float_as_uint(y) & 0xFFFF0000u);
}
__device__ __forceinline__ uint32_t pack_lo2(float x, float y){
    float lx = x - __uint_as_float(__float_as_uint(x) & 0xFFFF0000u);
    float ly = y - __uint_as_float(__float_as_uint(y) & 0xFFFF0000u);
    __nv_bfloat162 t = __floats2bfloat162_rn(lx, ly);
    return *reinterpret_cast<uint32_t*>(&t);
}
// fp16 split: x = hi + lo (hi = rn(x), lo = rn(x - hi)); packed pairs
__device__ __forceinline__ void split_f16_2(float x, float y, uint32_t& hi, uint32_t& lo){
    __half hx = __float2half_rn(x), hy = __float2half_rn(y);
    __half2 h2; h2.x = hx; h2.y = hy;
    hi = *reinterpret_cast<uint32_t*>(&h2);
    __half2 l2 = __floats2half2_rn(x - __half2float(hx), y - __half2float(hy));
    lo = *reinterpret_cast<uint32_t*>(&l2);
}

// ---------------- mma.sync / ldmatrix / cp.async wrappers ----------------
__device__ __forceinline__ void mma_bf16(float* d, const uint32_t* a, const uint32_t* b){
    asm volatile(
      "mma.sync.aligned.m16n8k16.row.col.f32.bf16.bf16.f32 "
      "{%0,%1,%2,%3}, {%4,%5,%6,%7}, {%8,%9}, {%0,%1,%2,%3};\n"
      : "+f"(d[0]), "+f"(d[1]), "+f"(d[2]), "+f"(d[3])
      : "r"(a[0]), "r"(a[1]), "r"(a[2]), "r"(a[3]), "r"(b[0]), "r"(b[1]));
}
__device__ __forceinline__ void mma_f16(float* d, const uint32_t* a, const uint32_t* b){
    asm volatile(
      "mma.sync.aligned.m16n8k16.row.col.f32.f16.f16.f32 "
      "{%0,%1,%2,%3}, {%4,%5,%6,%7}, {%8,%9}, {%0,%1,%2,%3};\n"
      : "+f"(d[0]), "+f"(d[1]), "+f"(d[2]), "+f"(d[3])
      : "r"(a[0]), "r"(a[1]), "r"(a[2]), "r"(a[3]), "r"(b[0]), "r"(b[1]));
}
__device__ __forceinline__ void ldsm_x4(uint32_t* r, uint32_t addr){
    asm volatile("ldmatrix.sync.aligned.m8n8.x4.shared.b16 {%0,%1,%2,%3}, [%4];"
      : "=r"(r[0]), "=r"(r[1]), "=r"(r[2]), "=r"(r[3]) : "r"(addr));
}
__device__ __forceinline__ void ldsm_x2(uint32_t* r, uint32_t addr){
    asm volatile("ldmatrix.sync.aligned.m8n8.x2.shared.b16 {%0,%1}, [%2];"
      : "=r"(r[0]), "=r"(r[1]) : "r"(addr));
}
__device__ __forceinline__ void ldsm_x2t(uint32_t* r, uint32_t addr){
    asm volatile("ldmatrix.sync.aligned.m8n8.x2.trans.shared.b16 {%0,%1}, [%2];"
      : "=r"(r[0]), "=r"(r[1]) : "r"(addr));
}
__device__ __forceinline__ void cp16(uint32_t s, const void* g){
    asm volatile("cp.async.cg.shared.global [%0], [%1], 16;\n" :: "r"(s), "l"(g));
}

// ---------------- bf16x3 GEMM smem layout (3 stages, 2 CTAs/SM) ----------------
#define KC          32
#define A_STRIDE    80
#define B_STRIDE    272
#define A_LO_OFF    10240
#define B_OFF       20480
#define B_LO_OFF    8704
#define STAGE_BYTES 37888
#define GEMM_SMEM   (3*STAGE_BYTES)   // 113664

__device__ __forceinline__ void issue_stage(
    const __nv_bfloat16* __restrict__ Ah, const __nv_bfloat16* __restrict__ Al,
    const __nv_bfloat16* __restrict__ Bh, const __nv_bfloat16* __restrict__ Bl,
    uint32_t sb0, int tid, int m0, int n0, int K, int N, int c)
{
    uint32_t sb = sb0 + (uint32_t)(c % 3) * STAGE_BYTES;
    int k0 = c * KC;
    #pragma unroll
    for (int i = 0; i < 2; i++){
        int idx = tid + i*256;
        int r = idx >> 2, cc = idx & 3;
        uint32_t sa = sb + r*A_STRIDE + cc*16;
        size_t g = (size_t)(m0 + r) * K + k0 + cc*8;
        cp16(sa,            Ah + g);
        cp16(sa + A_LO_OFF, Al + g);
    }
    #pragma unroll
    for (int i = 0; i < 2; i++){
        int idx = tid + i*256;
        int r = idx >> 4, cc = idx & 15;
        uint32_t sa = sb + B_OFF + r*B_STRIDE + cc*16;
        size_t g = (size_t)(k0 + r) * N + n0 + cc*8;
        cp16(sa,            Bh + g);
        cp16(sa + B_LO_OFF, Bl + g);
    }
    asm volatile("cp.async.commit_group;");
}

// =====================================================================
// bf16x3 GEMM (QKV / Wo): C = epi(A @ B + bias)
// EPI: 1 = bias+residual (f32)  3 = bias -> split bf16 hi/lo
// =====================================================================
template<int EPI>
__global__ __launch_bounds__(256, 2)
void gemm_bf16x3(const __nv_bfloat16* __restrict__ Ah, const __nv_bfloat16* __restrict__ Al,
                 const __nv_bfloat16* __restrict__ Bh, const __nv_bfloat16* __restrict__ Bl,
                 const float* __restrict__ bias, const float* __restrict__ res,
                 float* __restrict__ C,
                 __nv_bfloat16* __restrict__ Chi, __nv_bfloat16* __restrict__ Clo,
                 int M, int N, int K)
{
    extern __shared__ char smem[];
    const uint32_t sb0 = smem_u32(smem);
    const int tid  = threadIdx.x;
    const int lane = tid & 31, wid = tid >> 5;
    const int m0 = blockIdx.y * 128, n0 = blockIdx.x * 128;
    const int wm = (wid >> 2) * 64, wn = (wid & 3) * 32;

    float acc[4][4][4];
    #pragma unroll
    for (int a = 0; a < 4; a++)
        #pragma unroll
        for (int b = 0; b < 4; b++)
            #pragma unroll
            for (int cc = 0; cc < 4; cc++) acc[a][b][cc] = 0.f;

    const int nch = K / KC;
    issue_stage(Ah, Al, Bh, Bl, sb0, tid, m0, n0, K, N, 0);
    issue_stage(Ah, Al, Bh, Bl, sb0, tid, m0, n0, K, N, 1);

    const uint32_t a_lrow = wm + (lane & 15);
    const uint32_t a_lcol = (lane >> 4) * 8;
    const uint32_t b_lrow = (lane & 15);

    for (int c = 0; c < nch; c++){
        asm volatile("cp.async.wait_group %0;" :: "n"(1));
        __syncthreads();
        if (c + 2 < nch) issue_stage(Ah, Al, Bh, Bl, sb0, tid, m0, n0, K, N, c + 2);
        else asm volatile("cp.async.commit_group;");

        uint32_t sb = sb0 + (uint32_t)(c % 3) * STAGE_BYTES;
        #pragma unroll
        for (int ks = 0; ks < 2; ks++){
            uint32_t ah[4][4], al[4][4];
            #pragma unroll
            for (int mt = 0; mt < 4; mt++){
                uint32_t ad = sb + (a_lrow + mt*16)*A_STRIDE + (ks*16 + a_lcol)*2;
                ldsm_x4(ah[mt], ad);
                ldsm_x4(al[mt], ad + A_LO_OFF);
            }
            {
                uint32_t bh[4][2];
                #pragma unroll
                for (int nt = 0; nt < 4; nt++)
                    ldsm_x2t(bh[nt], sb + B_OFF + (ks*16 + b_lrow)*B_STRIDE + (wn + nt*8)*2);
                #pragma unroll
                for (int mt = 0; mt < 4; mt++)
                    #pragma unroll
                    for (int nt = 0; nt < 4; nt++)
                        mma_bf16(acc[mt][nt], ah[mt], bh[nt]);
                #pragma unroll
                for (int mt = 0; mt < 4; mt++)
                    #pragma unroll
                    for (int nt = 0; nt < 4; nt++)
                        mma_bf16(acc[mt][nt], al[mt], bh[nt]);
            }
            {
                uint32_t bl[4][2];
                #pragma unroll
                for (int nt = 0; nt < 4; nt++)
                    ldsm_x2t(bl[nt], sb + B_OFF + B_LO_OFF + (ks*16 + b_lrow)*B_STRIDE + (wn + nt*8)*2);
                #pragma unroll
                for (int mt = 0; mt < 4; mt++)
                    #pragma unroll
                    for (int nt = 0; nt < 4; nt++)
                        mma_bf16(acc[mt][nt], ah[mt], bl[nt]);
            }
        }
    }

    const int g  = lane >> 2;
    const int tq = (lane & 3) * 2;
    #pragma unroll
    for (int mt = 0; mt < 4; mt++){
        #pragma unroll
        for (int half = 0; half < 2; half++){
            int m = m0 + wm + mt*16 + g + half*8;
            #pragma unroll
            for (int nt = 0; nt < 4; nt++){
                int n = n0 + wn + nt*8 + tq;
                float v0 = acc[mt][nt][half*2+0] + bias[n];
                float v1 = acc[mt][nt][half*2+1] + bias[n+1];
                size_t gi = (size_t)m * N + n;
                if (EPI == 1){
                    v0 += res[gi]; v1 += res[gi+1];
                    float2 o; o.x = v0; o.y = v1;
                    *(float2*)&C[gi] = o;
                } else {
                    *(uint32_t*)&Chi[gi] = pack_hi2(v0, v1);
                    *(uint32_t*)&Clo[gi] = pack_lo2(v0, v1);
                }
            }
        }
    }
}

// ---------------- fp16x2 GEMM smem layout ----------------
#define F_A_LO   10240
#define F_B_OFF  20480
#define F_STAGE  29184
#define FGEMM_SMEM (3*F_STAGE)   // 87552

__device__ __forceinline__ void issue_stage_f16(
    const __half* __restrict__ Ah, const __half* __restrict__ Al,
    const __half* __restrict__ B,
    uint32_t sb0, int tid, int m0, int n0, int K, int N, int c)
{
    uint32_t sb = sb0 + (uint32_t)(c % 3) * F_STAGE;
    int k0 = c * KC;
    #pragma unroll
    for (int i = 0; i < 2; i++){
        int idx = tid + i*256;
        int r = idx >> 2, cc = idx & 3;
        uint32_t sa = sb + r*A_STRIDE + cc*16;
        size_t g = (size_t)(m0 + r) * K + k0 + cc*8;
        cp16(sa,          Ah + g);
        cp16(sa + F_A_LO, Al + g);
    }
    #pragma unroll
    for (int i = 0; i < 2; i++){
        int idx = tid + i*256;
        int r = idx >> 4, cc = idx & 15;
        uint32_t sa = sb + F_B_OFF + r*B_STRIDE + cc*16;
        size_t g = (size_t)(k0 + r) * N + n0 + cc*8;
        cp16(sa, B + g);
    }
    asm volatile("cp.async.commit_group;");
}

// =====================================================================
// fp16x2 GEMM (FFN): C = epi(A @ B + bias); A = fp16 hi+lo pair (exact),
// B = single rounded fp16. 2 MMA sweeps per k-step.
// EPI: 1 = bias+residual (f32 out)   2 = bias+GELU -> fp16 hi/lo split out
// =====================================================================
template<int EPI>
__global__ __launch_bounds__(256, 2)
void gemm_f16x2(const __half* __restrict__ Ah, const __half* __restrict__ Al,
                const __half* __restrict__ B,
                const float* __restrict__ bias, const float* __restrict__ res,
                float* __restrict__ C,
                __half* __restrict__ Chi, __half* __restrict__ Clo,
                int M, int N, int K)
{
    extern __shared__ char smem[];
    const uint32_t sb0 = smem_u32(smem);
    const int tid  = threadIdx.x;
    const int lane = tid & 31, wid = tid >> 5;
    const int m0 = blockIdx.y * 128, n0 = blockIdx.x * 128;
    const int wm = (wid >> 2) * 64, wn = (wid & 3) * 32;

    float acc[4][4][4];
    #pragma unroll
    for (int a = 0; a < 4; a++)
        #pragma unroll
        for (int b = 0; b < 4; b++)
            #pragma unroll
            for (int cc = 0; cc < 4; cc++) acc[a][b][cc] = 0.f;

    const int nch = K / KC;
    issue_stage_f16(Ah, Al, B, sb0, tid, m0, n0, K, N, 0);
    issue_stage_f16(Ah, Al, B, sb0, tid, m0, n0, K, N, 1);

    const uint32_t a_lrow = wm + (lane & 15);
    const uint32_t a_lcol = (lane >> 4) * 8;
    const uint32_t b_lrow = (lane & 15);

    for (int c = 0; c < nch; c++){
        asm volatile("cp.async.wait_group %0;" :: "n"(1));
        __syncthreads();
        if (c + 2 < nch) issue_stage_f16(Ah, Al, B, sb0, tid, m0, n0, K, N, c + 2);
        else asm volatile("cp.async.commit_group;");

        uint32_t sb = sb0 + (uint32_t)(c % 3) * F_STAGE;
        #pragma unroll
        for (int ks = 0; ks < 2; ks++){
            uint32_t ah[4][4], al[4][4], bb[4][2];
            #pragma unroll
            for (int mt = 0; mt < 4; mt++){
                uint32_t ad = sb + (a_lrow + mt*16)*A_STRIDE + (ks*16 + a_lcol)*2;
                ldsm_x4(ah[mt], ad);
                ldsm_x4(al[mt], ad + F_A_LO);
            }
            #pragma unroll
            for (int nt = 0; nt < 4; nt++)
                ldsm_x2t(bb[nt], sb + F_B_OFF + (ks*16 + b_lrow)*B_STRIDE + (wn + nt*8)*2);
            #pragma unroll
            for (int mt = 0; mt < 4; mt++)
                #pragma unroll
                for (int nt = 0; nt < 4; nt++)
                    mma_f16(acc[mt][nt], ah[mt], bb[nt]);
            #pragma unroll
            for (int mt = 0; mt < 4; mt++)
                #pragma unroll
                for (int nt = 0; nt < 4; nt++)
                    mma_f16(acc[mt][nt], al[mt], bb[nt]);
        }
    }

    const int g  = lane >> 2;
    const int tq = (lane & 3) * 2;
    #pragma unroll
    for (int mt = 0; mt < 4; mt++){
        #pragma unroll
        for (int half = 0; half < 2; half++){
            int m = m0 + wm + mt*16 + g + half*8;
            #pragma unroll
            for (int nt = 0; nt < 4; nt++){
                int n = n0 + wn + nt*8 + tq;
                float v0 = acc[mt][nt][half*2+0] + bias[n];
                float v1 = acc[mt][nt][half*2+1] + bias[n+1];
                size_t gi = (size_t)m * N + n;
                if (EPI == 1){
                    v0 += res[gi]; v1 += res[gi+1];
                    float2 o; o.x = v0; o.y = v1;
                    *(float2*)&C[gi] = o;
                } else {
                    v0 = gelu_exact(v0); v1 = gelu_exact(v1);
                    uint32_t H, L;
                    split_f16_2(v0, v1, H, L);
                    *(uint32_t*)&Chi[gi] = H;
                    *(uint32_t*)&Clo[gi] = L;
                }
            }
        }
    }
}

// =====================================================================
// Flash attention, bf16x3, causal.  Bq=128 (8 warps x 16 rows), Bc=64.
// =====================================================================
#define FL_SMEM 110592

__global__ __launch_bounds__(256)
void flash_kernel(const __nv_bfloat16* __restrict__ qkv_hi,
                  const __nv_bfloat16* __restrict__ qkv_lo,
                  __nv_bfloat16* __restrict__ o_hi,
                  __nv_bfloat16* __restrict__ o_lo)
{
    extern __shared__ char fsm[];
    const uint32_t sb = smem_u32(fsm);
    const int tid = threadIdx.x, lane = tid & 31, w = tid >> 5;
    const int bh = blockIdx.x;
    const int it = 7 - blockIdx.y;
    const int b = bh >> 4, h = bh & 15;
    const int nk = 2*(it+1);
    const size_t rs = 3*DMODEL;

    {
        const size_t tok0 = (size_t)(b*SEQ + it*128);
        #pragma unroll
        for (int i = 0; i < 4; i++){
            int idx = tid + i*256;
            int r = idx >> 3, c = idx & 7;
            size_t g = (tok0 + r)*rs + h*64 + c*8;
            uint32_t sa = sb + r*144 + c*16;
            cp16(sa,         qkv_hi + g);
            cp16(sa + 18432, qkv_lo + g);
        }
        asm volatile("cp.async.commit_group;");
    }
    #define ISSUE_KV(jt_) do {                                               \
        uint32_t st_ = sb + 36864u + (uint32_t)((jt_)&1)*36864u;             \
        const size_t tok0_ = (size_t)(b*SEQ + (jt_)*64);                     \
        _Pragma("unroll")                                                    \
        for (int i_ = 0; i_ < 2; i_++){                                      \
            int idx_ = tid + i_*256;                                         \
            int r_ = idx_ >> 3, c_ = idx_ & 7;                               \
            size_t gk_ = (tok0_ + r_)*rs + DMODEL   + h*64 + c_*8;           \
            size_t gv_ = (tok0_ + r_)*rs + 2*DMODEL + h*64 + c_*8;           \
            uint32_t sa_ = st_ + r_*144 + c_*16;                             \
            cp16(sa_,         qkv_hi + gk_);                                 \
            cp16(sa_ + 9216,  qkv_lo + gk_);                                 \
            cp16(sa_ + 18432, qkv_hi + gv_);                                 \
            cp16(sa_ + 27648, qkv_lo + gv_);                                 \
        }                                                                    \
        asm volatile("cp.async.commit_group;");                              \
    } while(0)

    ISSUE_KV(0);
    asm volatile("cp.async.wait_group 1;");
    __syncthreads();

    uint32_t qh[4][4], ql[4][4];
    {
        uint32_t rbase = sb + (w*16 + (lane & 15))*144 + ((lane >> 4)*8)*2;
        #pragma unroll
        for (int ks = 0; ks < 4; ks++){
            ldsm_x4(qh[ks], rbase + ks*32);
            ldsm_x4(ql[ks], rbase + ks*32 + 18432);
        }
    }

    float O[8][4];
    #pragma unroll
    for (int nt = 0; nt < 8; nt++)
        #pragma unroll
        for (int c = 0; c < 4; c++) O[nt][c] = 0.f;
    float m0 = -INFINITY, m1 = -INFINITY, l0 = 0.f, l1 = 0.f;
    const int r0g = it*128 + w*16 + (lane >> 2);

    for (int jt = 0; jt < nk; jt++){
        if (jt + 1 < nk){ ISSUE_KV(jt+1); asm volatile("cp.async.wait_group 1;"); }
        else            { asm volatile("cp.async.wait_group 0;"); }
        __syncthreads();
        const uint32_t st = sb + 36864u + (uint32_t)(jt&1)*36864u;

        float S[8][4];
        #pragma unroll
        for (int nt = 0; nt < 8; nt++)
            #pragma unroll
            for (int c = 0; c < 4; c++) S[nt][c] = 0.f;

        const uint32_t kb = st + (lane & 7)*144 + (((lane >> 3) & 1)*8)*2;
        #pragma unroll
        for (int nt = 0; nt < 8; nt++){
            #pragma unroll
            for (int ks = 0; ks < 4; ks++){
                uint32_t a = kb + nt*8*144 + ks*32;
                uint32_t kh[2], kl[2];
                ldsm_x2(kh, a);
                ldsm_x2(kl, a + 9216);
                mma_bf16(S[nt], qh[ks], kh);
                mma_bf16(S[nt], qh[ks], kl);
                mma_bf16(S[nt], ql[ks], kh);
            }
        }

        const bool diag = (jt >= 2*it);
        float mx0 = -INFINITY, mx1 = -INFINITY;
        #pragma unroll
        for (int nt = 0; nt < 8; nt++){
            int colb = jt*64 + nt*8 + (lane & 3)*2;
            #pragma unroll
            for (int q = 0; q < 2; q++){
                float v0 = S[nt][q]   * 0.125f;
                float v1 = S[nt][2+q] * 0.125f;
                if (diag){
                    if (colb + q > r0g)     v0 = -INFINITY;
                    if (colb + q > r0g + 8) v1 = -INFINITY;
                }
                S[nt][q] = v0; S[nt][2+q] = v1;
                mx0 = fmaxf(mx0, v0); mx1 = fmaxf(mx1, v1);
            }
        }
        mx0 = fmaxf(mx0, __shfl_xor_sync(0xffffffffu, mx0, 1));
        mx0 = fmaxf(mx0, __shfl_xor_sync(0xffffffffu, mx0, 2));
        mx1 = fmaxf(mx1, __shfl_xor_sync(0xffffffffu, mx1, 1));
        mx1 = fmaxf(mx1, __shfl_xor_sync(0xffffffffu, mx1, 2));
        float mn0 = fmaxf(m0, mx0), mn1 = fmaxf(m1, mx1);
        float f0 = __expf(m0 - mn0), f1 = __expf(m1 - mn1);
        m0 = mn0; m1 = mn1;
        float ls0 = 0.f, ls1 = 0.f;
        #pragma unroll
        for (int nt = 0; nt < 8; nt++){
            #pragma unroll
            for (int q = 0; q < 2; q++){
                float e0 = __expf(S[nt][q]   - m0);
                float e1 = __expf(S[nt][2+q] - m1);
                S[nt][q] = e0; S[nt][2+q] = e1;
                ls0 += e0; ls1 += e1;
            }
        }
        l0 = l0*f0 + ls0;
        l1 = l1*f1 + ls1;
        #pragma unroll
        for (int nt = 0; nt < 8; nt++){
            O[nt][0] *= f0; O[nt][1] *= f0;
            O[nt][2] *= f1; O[nt][3] *= f1;
        }

        #pragma unroll
        for (int ks = 0; ks < 4; ks++){
            uint32_t ph[4], pl[4];
            ph[0] = pack_hi2(S[2*ks][0],   S[2*ks][1]);
            ph[1] = pack_hi2(S[2*ks][2],   S[2*ks][3]);
            ph[2] = pack_hi2(S[2*ks+1][0], S[2*ks+1][1]);
            ph[3] = pack_hi2(S[2*ks+1][2], S[2*ks+1][3]);
            pl[0] = pack_lo2(S[2*ks][0],   S[2*ks][1]);
            pl[1] = pack_lo2(S[2*ks][2],   S[2*ks][3]);
            pl[2] = pack_lo2(S[2*ks+1][0], S[2*ks+1][1]);
            pl[3] = pack_lo2(S[2*ks+1][2], S[2*ks+1][3]);
            uint32_t vb = st + 18432u + (ks*16 + (lane & 15))*144;
            #pragma unroll
            for (int nt = 0; nt < 8; nt++){
                uint32_t vh[2], vl[2];
                ldsm_x2t(vh, vb + nt*16);
                ldsm_x2t(vl, vb + nt*16 + 9216);
                mma_bf16(O[nt], ph, vh);
                mma_bf16(O[nt], ph, vl);
                mma_bf16(O[nt], pl, vh);
            }
        }
        __syncthreads();
    }

    l0 += __shfl_xor_sync(0xffffffffu, l0, 1);
    l0 += __shfl_xor_sync(0xffffffffu, l0, 2);
    l1 += __shfl_xor_sync(0xffffffffu, l1, 1);
    l1 += __shfl_xor_sync(0xffffffffu, l1, 2);
    float inv0 = 1.0f / l0, inv1 = 1.0f / l1;
    const size_t tok0 = (size_t)(b*SEQ + it*128 + w*16 + (lane >> 2));
    const int colb = h*64 + (lane & 3)*2;
    #pragma unroll
    for (int nt = 0; nt < 8; nt++){
        #pragma unroll
        for (int rh = 0; rh < 2; rh++){
            float inv = rh ? inv1 : inv0;
            float v0 = O[nt][rh*2+0] * inv;
            float v1 = O[nt][rh*2+1] * inv;
            size_t gi = (tok0 + rh*8)*DMODEL + colb + nt*8;
            *(uint32_t*)&o_hi[gi] = pack_hi2(v0, v1);
            *(uint32_t*)&o_lo[gi] = pack_lo2(v0, v1);
        }
    }
}

// ---------------- weight split kernels ----------------
__global__ void wsplit_kernel(const float4* __restrict__ in,
                              uint2* __restrict__ hi, uint2* __restrict__ lo, int n4){
    int i = blockIdx.x * blockDim.x + threadIdx.x;
    if (i >= n4) return;
    float4 v = in[i];
    uint2 H, L;
    H.x = pack_hi2(v.x, v.y); H.y = pack_hi2(v.z, v.w);
    L.x = pack_lo2(v.x, v.y); L.y = pack_lo2(v.z, v.w);
    hi[i] = H; lo[i] = L;
}
__global__ void wconv_f16_kernel(const float4* __restrict__ in,
                                 uint2* __restrict__ out, int n4){
    int i = blockIdx.x * blockDim.x + threadIdx.x;
    if (i >= n4) return;
    float4 v = in[i];
    __half2 a = __floats2half2_rn(v.x, v.y);
    __half2 b = __floats2half2_rn(v.z, v.w);
    uint2 o;
    o.x = *reinterpret_cast<uint32_t*>(&a);
    o.y = *reinterpret_cast<uint32_t*>(&b);
    out[i] = o;
}

// ---------------- copy x -> h ----------------
__global__ void copy_kernel(const float* __restrict__ in, float* __restrict__ out){
    int idx = blockIdx.x * blockDim.x + threadIdx.x;
    float4 v = ((const float4*)in)[idx];
    ((float4*)out)[idx] = v;
}

// ---------------- LayerNorm ----------------
// FMT: 0 = bf16 hi/lo split, 1 = fp16 hi/lo split.  WF32: also write fp32.
template<int FMT, bool WF32>
__global__ void ln_kernel(const float* __restrict__ in,
                          const float* __restrict__ w,
                          const float* __restrict__ b,
                          float* __restrict__ out,
                          __nv_bfloat16* __restrict__ out_hi,
                          __nv_bfloat16* __restrict__ out_lo){
    int row = blockIdx.x;
    int t   = threadIdx.x;
    const float* x = in + (size_t)row * DMODEL;
    float4 v = *(const float4*)&x[t*4];
    float s  = v.x + v.y + v.z + v.w;
    float sq = v.x*v.x + v.y*v.y + v.z*v.z + v.w*v.w;
    s  = warp_sum(s);
    sq = warp_sum(sq);
    __shared__ float sh1[8], sh2[8];
    int warp = t >> 5, lane = t & 31;
    if (lane == 0){ sh1[warp] = s; sh2[warp] = sq; }
    __syncthreads();
    float tot = 0.f, tot2 = 0.f;
    #pragma unroll
    for (int i = 0; i < 8; i++){ tot += sh1[i]; tot2 += sh2[i]; }
    float mu   = tot  * (1.0f/DMODEL);
    float var  = tot2 * (1.0f/DMODEL) - mu*mu;
    float rstd = rsqrtf(var + EPS);
    float4 wv = *(const float4*)&w[t*4];
    float4 bv = *(const float4*)&b[t*4];
    float4 ov;
    ov.x = (v.x - mu)*rstd*wv.x + bv.x;
    ov.y = (v.y - mu)*rstd*wv.y + bv.y;
    ov.z = (v.z - mu)*rstd*wv.z + bv.z;
    ov.w = (v.w - mu)*rstd*wv.w + bv.w;
    size_t base = (size_t)row*DMODEL + t*4;
    if (WF32) *(float4*)&out[base] = ov;
    uint2 H, L;
    if (FMT == 0){
        H.x = pack_hi2(ov.x, ov.y); H.y = pack_hi2(ov.z, ov.w);
        L.x = pack_lo2(ov.x, ov.y); L.y = pack_lo2(ov.z, ov.w);
    } else {
        split_f16_2(ov.x, ov.y, H.x, L.x);
        split_f16_2(ov.z, ov.w, H.y, L.y);
    }
    *(uint2*)&out_hi[base] = H;
    *(uint2*)&out_lo[base] = L;
}

// ---------------- final projection ----------------
__global__ __launch_bounds__(256)
void pred_kernel(const float* __restrict__ hn, const float* __restrict__ Wp,
                 const float* __restrict__ bp, float* __restrict__ out){
    int row = blockIdx.x;
    int t = threadIdx.x;
    float local[WIN] = {0,0,0,0,0};
    const float* x = hn + (size_t)row * DMODEL;
    for (int k = t; k < DMODEL; k += 256){
        float xv = x[k];
        const float* wr = Wp + (size_t)k * WIN;
        #pragma unroll
        for (int w = 0; w < WIN; w++) local[w] = fmaf(xv, wr[w], local[w]);
    }
    __shared__ float red[WIN][256];
    #pragma unroll
    for (int w = 0; w < WIN; w++) red[w][t] = local[w];
    __syncthreads();
    for (int s = 128; s > 0; s >>= 1){
        if (t < s){
            #pragma unroll
            for (int w = 0; w < WIN; w++) red[w][t] += red[w][t + s];
        }
        __syncthreads();
    }
    if (t < WIN) out[(size_t)row * WIN + t] = red[t][0] + bp[t];
}

// ---------------- host orchestration ----------------
extern "C" void kernel_launch(void* const* d_in, const int* in_sizes, int n_in,
                              void* d_out, int out_size){
    const float* x     = (const float*)d_in[0];
    const float* Wqkv  = (const float*)d_in[1];
    const float* bqkv  = (const float*)d_in[2];
    const float* Wo    = (const float*)d_in[3];
    const float* bo    = (const float*)d_in[4];
    const float* ln1w  = (const float*)d_in[5];
    const float* ln1b  = (const float*)d_in[6];
    const float* W1    = (const float*)d_in[7];
    const float* b1    = (const float*)d_in[8];
    const float* W2    = (const float*)d_in[9];
    const float* b2    = (const float*)d_in[10];
    const float* ln2w  = (const float*)d_in[11];
    const float* ln2b  = (const float*)d_in[12];
    const float* lnfw  = (const float*)d_in[13];
    const float* lnfb  = (const float*)d_in[14];
    const float* Wp    = (const float*)d_in[15];
    const float* bp    = (const float*)d_in[16];
    float* out = (float*)d_out;

    float *g_h, *g_hn;
    __nv_bfloat16 *g_hn_hi, *g_hn_lo, *g_qkv_hi, *g_qkv_lo,
                  *g_o_hi, *g_o_lo, *g_w_hi, *g_w_lo;
    __half *g_ff_hi, *g_ff_lo, *g_wf16;
    cudaGetSymbolAddress((void**)&g_h,      d_h);
    cudaGetSymbolAddress((void**)&g_hn,     d_hn);
    cudaGetSymbolAddress((void**)&g_hn_hi,  d_hn_hi);
    cudaGetSymbolAddress((void**)&g_hn_lo,  d_hn_lo);
    cudaGetSymbolAddress((void**)&g_qkv_hi, d_qkv_hi);
    cudaGetSymbolAddress((void**)&g_qkv_lo, d_qkv_lo);
    cudaGetSymbolAddress((void**)&g_o_hi,   d_o_hi);
    cudaGetSymbolAddress((void**)&g_o_lo,   d_o_lo);
    cudaGetSymbolAddress((void**)&g_ff_hi,  d_ff_hi);
    cudaGetSymbolAddress((void**)&g_ff_lo,  d_ff_lo);
    cudaGetSymbolAddress((void**)&g_w_hi,   d_w_hi);
    cudaGetSymbolAddress((void**)&g_w_lo,   d_w_lo);
    cudaGetSymbolAddress((void**)&g_wf16,   d_wf16);

    cudaFuncSetAttribute(gemm_bf16x3<1>, cudaFuncAttributeMaxDynamicSharedMemorySize, GEMM_SMEM);
    cudaFuncSetAttribute(gemm_bf16x3<3>, cudaFuncAttributeMaxDynamicSharedMemorySize, GEMM_SMEM);
    cudaFuncSetAttribute(gemm_f16x2<1>,  cudaFuncAttributeMaxDynamicSharedMemorySize, FGEMM_SMEM);
    cudaFuncSetAttribute(gemm_f16x2<2>,  cudaFuncAttributeMaxDynamicSharedMemorySize, FGEMM_SMEM);
    cudaFuncSetAttribute(flash_kernel,   cudaFuncAttributeMaxDynamicSharedMemorySize, FL_SMEM);

    // weight preprocessing
    wsplit_kernel<<<QKV_ELEMS/4/256, 256>>>((const float4*)Wqkv,
        (uint2*)(g_w_hi + QKV_OFF), (uint2*)(g_w_lo + QKV_OFF), QKV_ELEMS/4);
    wsplit_kernel<<<WO_ELEMS/4/256, 256>>>((const float4*)Wo,
        (uint2*)(g_w_hi + WO_OFF),  (uint2*)(g_w_lo + WO_OFF),  WO_ELEMS/4);
    wconv_f16_kernel<<<W1_ELEMS/4/256, 256>>>((const float4*)W1,
        (uint2*)(g_wf16),            W1_ELEMS/4);
    wconv_f16_kernel<<<W2_ELEMS/4/256, 256>>>((const float4*)W2,
        (uint2*)(g_wf16 + W1_ELEMS), W2_ELEMS/4);

    copy_kernel<<<TOKENS*DMODEL/4/256, 256>>>(x, g_h);

    for (int l = 0; l < LAYERS; l++){
        const __nv_bfloat16* wqkv_h = g_w_hi + QKV_OFF + (size_t)l * DMODEL * 3*DMODEL;
        const __nv_bfloat16* wqkv_l = g_w_lo + QKV_OFF + (size_t)l * DMODEL * 3*DMODEL;
        const __nv_bfloat16* wo_h   = g_w_hi + WO_OFF  + (size_t)l * DMODEL * DMODEL;
        const __nv_bfloat16* wo_l   = g_w_lo + WO_OFF  + (size_t)l * DMODEL * DMODEL;
        const __half* w1f = g_wf16 + (size_t)l * DMODEL * DFF;
        const __half* w2f = g_wf16 + W1_ELEMS + (size_t)l * DFF * DMODEL;
        const float* bq = bqkv + (size_t)l * 3*DMODEL;
        const float* bO = bo   + (size_t)l * DMODEL;
        const float* B1 = b1   + (size_t)l * DFF;
        const float* B2 = b2   + (size_t)l * DMODEL;

        // pre-norm attention (bf16x3 path)
        ln_kernel<0,false><<<TOKENS, 256>>>(g_h, ln1w + l*DMODEL, ln1b + l*DMODEL,
                                            nullptr, g_hn_hi, g_hn_lo);
        gemm_bf16x3<3><<<dim3(3*DMODEL/128, TOKENS/128), 256, GEMM_SMEM>>>(
            g_hn_hi, g_hn_lo, wqkv_h, wqkv_l, bq, nullptr,
            nullptr, g_qkv_hi, g_qkv_lo, TOKENS, 3*DMODEL, DMODEL);
        flash_kernel<<<dim3(BATCH*NHEAD, SEQ/128), 256, FL_SMEM>>>(
            g_qkv_hi, g_qkv_lo, g_o_hi, g_o_lo);
        gemm_bf16x3<1><<<dim3(DMODEL/128, TOKENS/128), 256, GEMM_SMEM>>>(
            g_o_hi, g_o_lo, wo_h, wo_l, bO, g_h,
            g_h, nullptr, nullptr, TOKENS, DMODEL, DMODEL);

        // pre-norm FFN (fp16x2 path)
        ln_kernel<1,false><<<TOKENS, 256>>>(g_h, ln2w + l*DMODEL, ln2b + l*DMODEL,
                                            nullptr, g_hn_hi, g_hn_lo);
        gemm_f16x2<2><<<dim3(DFF/128, TOKENS/128), 256, FGEMM_SMEM>>>(
            (const __half*)g_hn_hi, (const __half*)g_hn_lo, w1f, B1, nullptr,
            nullptr, g_ff_hi, g_ff_lo, TOKENS, DFF, DMODEL);
        gemm_f16x2<1><<<dim3(DMODEL/128, TOKENS/128), 256, FGEMM_SMEM>>>(
            g_ff_hi, g_ff_lo, w2f, B2, g_h,
            g_h, nullptr, nullptr, TOKENS, DMODEL, DFF);
    }

    // final LN + projection
    ln_kernel<0,true><<<TOKENS, 256>>>(g_h, lnfw, lnfb, g_hn, g_hn_hi, g_hn_lo);
    pred_kernel<<<TOKENS, 256>>>(g_hn, Wp, bp, out);
    (void)in_sizes; (void)n_in; (void)out_size;
}

// round 9
// speedup vs baseline: 1.3031x; 1.0895x over previous
#include <cuda_runtime.h>
#include <cuda_bf16.h>
#include <cuda_fp16.h>
#include <math.h>
#include <stdint.h>

// ---------------- problem constants ----------------
#define LAYERS 6
#define BATCH  2
#define SEQ    1024
#define DMODEL 1024
#define NHEAD  16
#define HDIM   64
#define DFF    4096
#define WIN    5
#define TOKENS (BATCH*SEQ)          // 2048
#define EPS    1e-5f

// fp16 weight scratch layout (elements)
#define QKV_ELEMS  (LAYERS*DMODEL*3*DMODEL)
#define WO_ELEMS   (LAYERS*DMODEL*DMODEL)
#define W1_ELEMS   (LAYERS*DMODEL*DFF)
#define W2_ELEMS   (LAYERS*DFF*DMODEL)
#define WF_QKV 0
#define WF_WO  (QKV_ELEMS)
#define WF_W1  (WF_WO + WO_ELEMS)
#define WF_W2  (WF_W1 + W1_ELEMS)
#define WF_TOT (WF_W2 + W2_ELEMS)

// ---------------- device scratch (no allocation allowed) ----------------
__device__ float d_h   [TOKENS*DMODEL];
__device__ float d_hn  [TOKENS*DMODEL];
__device__ __half d_hn_hi[TOKENS*DMODEL];          // fp16 split LN output
__device__ __half d_hn_lo[TOKENS*DMODEL];
__device__ __nv_bfloat16 d_qkv_hi[TOKENS*3*DMODEL];// bf16 split (flash input)
__device__ __nv_bfloat16 d_qkv_lo[TOKENS*3*DMODEL];
__device__ __half d_o_hi[TOKENS*DMODEL];           // fp16 split attn output
__device__ __half d_o_lo[TOKENS*DMODEL];
__device__ __half d_ff_hi[TOKENS*DFF];             // fp16 split GELU output
__device__ __half d_ff_lo[TOKENS*DFF];
__device__ __half d_wf16[WF_TOT];                  // all weights, single fp16

// ---------------- small helpers ----------------
__device__ __forceinline__ float warp_sum(float v){
    #pragma unroll
    for (int o = 16; o; o >>= 1) v += __shfl_xor_sync(0xffffffffu, v, o);
    return v;
}
__device__ __forceinline__ float gelu_exact(float x){
    return 0.5f * x * (1.0f + erff(x * 0.70710678118654752440f));
}
__device__ __forceinline__ uint32_t smem_u32(const void* p){
    uint32_t a;
    asm("{ .reg .u64 t; cvta.to.shared.u64 t, %1; cvt.u32.u64 %0, t; }" : "=r"(a) : "l"(p));
    return a;
}
__device__ __forceinline__ uint32_t pack_hi2(float x, float y){
    return (__float_as_uint(x) >> 16) | (__float_as_uint(y) & 0xFFFF0000u);
}
__device__ __forceinline__ uint32_t pack_lo2(float x, float y){
    float lx = x - __uint_as_float(__float_as_uint(x) & 0xFFFF0000u);
    float ly = y - __uint_as_float(__float_as_uint(y) & 0xFFFF0000u);
    __nv_bfloat162 t = __floats2bfloat162_rn(lx, ly);
    return *reinterpret_cast<uint32_t*>(&t);
}
// fp16 split: x = hi + lo (hi = rn(x), lo = rn(x - hi)); packed pairs
__device__ __forceinline__ void split_f16_2(float x, float y, uint32_t& hi, uint32_t& lo){
    __half hx = __float2half_rn(x), hy = __float2half_rn(y);
    __half2 h2; h2.x = hx; h2.y = hy;
    hi = *reinterpret_cast<uint32_t*>(&h2);
    __half2 l2 = __floats2half2_rn(x - __half2float(hx), y - __half2float(hy));
    lo = *reinterpret_cast<uint32_t*>(&l2);
}

// ---------------- mma.sync / ldmatrix / cp.async wrappers ----------------
__device__ __forceinline__ void mma_bf16(float* d, const uint32_t* a, const uint32_t* b){
    asm volatile(
      "mma.sync.aligned.m16n8k16.row.col.f32.bf16.bf16.f32 "
      "{%0,%1,%2,%3}, {%4,%5,%6,%7}, {%8,%9}, {%0,%1,%2,%3};\n"
      : "+f"(d[0]), "+f"(d[1]), "+f"(d[2]), "+f"(d[3])
      : "r"(a[0]), "r"(a[1]), "r"(a[2]), "r"(a[3]), "r"(b[0]), "r"(b[1]));
}
__device__ __forceinline__ void mma_f16(float* d, const uint32_t* a, const uint32_t* b){
    asm volatile(
      "mma.sync.aligned.m16n8k16.row.col.f32.f16.f16.f32 "
      "{%0,%1,%2,%3}, {%4,%5,%6,%7}, {%8,%9}, {%0,%1,%2,%3};\n"
      : "+f"(d[0]), "+f"(d[1]), "+f"(d[2]), "+f"(d[3])
      : "r"(a[0]), "r"(a[1]), "r"(a[2]), "r"(a[3]), "r"(b[0]), "r"(b[1]));
}
__device__ __forceinline__ void ldsm_x4(uint32_t* r, uint32_t addr){
    asm volatile("ldmatrix.sync.aligned.m8n8.x4.shared.b16 {%0,%1,%2,%3}, [%4];"
      : "=r"(r[0]), "=r"(r[1]), "=r"(r[2]), "=r"(r[3]) : "r"(addr));
}
__device__ __forceinline__ void ldsm_x2(uint32_t* r, uint32_t addr){
    asm volatile("ldmatrix.sync.aligned.m8n8.x2.shared.b16 {%0,%1}, [%2];"
      : "=r"(r[0]), "=r"(r[1]) : "r"(addr));
}
__device__ __forceinline__ void ldsm_x2t(uint32_t* r, uint32_t addr){
    asm volatile("ldmatrix.sync.aligned.m8n8.x2.trans.shared.b16 {%0,%1}, [%2];"
      : "=r"(r[0]), "=r"(r[1]) : "r"(addr));
}
__device__ __forceinline__ void cp16(uint32_t s, const void* g){
    asm volatile("cp.async.cg.shared.global [%0], [%1], 16;\n" :: "r"(s), "l"(g));
}

// ---------------- fp16x2 GEMM smem layout (3 stages) ----------------
#define KC       32
#define A_STRIDE 80
#define B_STRIDE 272
#define F_A_LO   10240
#define F_B_OFF  20480
#define F_STAGE  29184
#define FGEMM_SMEM (3*F_STAGE)   // 87552

__device__ __forceinline__ void issue_stage_f16(
    const __half* __restrict__ Ah, const __half* __restrict__ Al,
    const __half* __restrict__ B,
    uint32_t sb0, int tid, int m0, int n0, int K, int N, int c)
{
    uint32_t sb = sb0 + (uint32_t)(c % 3) * F_STAGE;
    int k0 = c * KC;
    #pragma unroll
    for (int i = 0; i < 2; i++){
        int idx = tid + i*256;
        int r = idx >> 2, cc = idx & 3;
        uint32_t sa = sb + r*A_STRIDE + cc*16;
        size_t g = (size_t)(m0 + r) * K + k0 + cc*8;
        cp16(sa,          Ah + g);
        cp16(sa + F_A_LO, Al + g);
    }
    #pragma unroll
    for (int i = 0; i < 2; i++){
        int idx = tid + i*256;
        int r = idx >> 4, cc = idx & 15;
        uint32_t sa = sb + F_B_OFF + r*B_STRIDE + cc*16;
        size_t g = (size_t)(k0 + r) * N + n0 + cc*8;
        cp16(sa, B + g);
    }
    asm volatile("cp.async.commit_group;");
}

// =====================================================================
// fp16x2 GEMM: C = epi(A @ B + bias); A = fp16 hi+lo pair (exact),
// B = single rounded fp16. 2 MMA sweeps per k-step.
// EPI: 1 = bias+residual (f32 out)
//      2 = bias+GELU -> fp16 hi/lo split out
//      3 = bias -> bf16 hi/lo split out (flash input)
// =====================================================================
template<int EPI>
__global__ __launch_bounds__(256, 2)
void gemm_f16x2(const __half* __restrict__ Ah, const __half* __restrict__ Al,
                const __half* __restrict__ B,
                const float* __restrict__ bias, const float* __restrict__ res,
                float* __restrict__ C,
                __half* __restrict__ Chi, __half* __restrict__ Clo,
                int M, int N, int K)
{
    extern __shared__ char smem[];
    const uint32_t sb0 = smem_u32(smem);
    const int tid  = threadIdx.x;
    const int lane = tid & 31, wid = tid >> 5;
    const int m0 = blockIdx.y * 128, n0 = blockIdx.x * 128;
    const int wm = (wid >> 2) * 64, wn = (wid & 3) * 32;

    float acc[4][4][4];
    #pragma unroll
    for (int a = 0; a < 4; a++)
        #pragma unroll
        for (int b = 0; b < 4; b++)
            #pragma unroll
            for (int cc = 0; cc < 4; cc++) acc[a][b][cc] = 0.f;

    const int nch = K / KC;
    issue_stage_f16(Ah, Al, B, sb0, tid, m0, n0, K, N, 0);
    issue_stage_f16(Ah, Al, B, sb0, tid, m0, n0, K, N, 1);

    const uint32_t a_lrow = wm + (lane & 15);
    const uint32_t a_lcol = (lane >> 4) * 8;
    const uint32_t b_lrow = (lane & 15);

    for (int c = 0; c < nch; c++){
        asm volatile("cp.async.wait_group %0;" :: "n"(1));
        __syncthreads();
        if (c + 2 < nch) issue_stage_f16(Ah, Al, B, sb0, tid, m0, n0, K, N, c + 2);
        else asm volatile("cp.async.commit_group;");

        uint32_t sb = sb0 + (uint32_t)(c % 3) * F_STAGE;
        #pragma unroll
        for (int ks = 0; ks < 2; ks++){
            uint32_t ah[4][4], al[4][4], bb[4][2];
            #pragma unroll
            for (int mt = 0; mt < 4; mt++){
                uint32_t ad = sb + (a_lrow + mt*16)*A_STRIDE + (ks*16 + a_lcol)*2;
                ldsm_x4(ah[mt], ad);
                ldsm_x4(al[mt], ad + F_A_LO);
            }
            #pragma unroll
            for (int nt = 0; nt < 4; nt++)
                ldsm_x2t(bb[nt], sb + F_B_OFF + (ks*16 + b_lrow)*B_STRIDE + (wn + nt*8)*2);
            #pragma unroll
            for (int mt = 0; mt < 4; mt++)
                #pragma unroll
                for (int nt = 0; nt < 4; nt++)
                    mma_f16(acc[mt][nt], ah[mt], bb[nt]);
            #pragma unroll
            for (int mt = 0; mt < 4; mt++)
                #pragma unroll
                for (int nt = 0; nt < 4; nt++)
                    mma_f16(acc[mt][nt], al[mt], bb[nt]);
        }
    }

    const int g  = lane >> 2;
    const int tq = (lane & 3) * 2;
    #pragma unroll
    for (int mt = 0; mt < 4; mt++){
        #pragma unroll
        for (int half = 0; half < 2; half++){
            int m = m0 + wm + mt*16 + g + half*8;
            #pragma unroll
            for (int nt = 0; nt < 4; nt++){
                int n = n0 + wn + nt*8 + tq;
                float v0 = acc[mt][nt][half*2+0] + bias[n];
                float v1 = acc[mt][nt][half*2+1] + bias[n+1];
                size_t gi = (size_t)m * N + n;
                if (EPI == 1){
                    v0 += res[gi]; v1 += res[gi+1];
                    float2 o; o.x = v0; o.y = v1;
                    *(float2*)&C[gi] = o;
                } else if (EPI == 2){
                    v0 = gelu_exact(v0); v1 = gelu_exact(v1);
                    uint32_t H, L;
                    split_f16_2(v0, v1, H, L);
                    *(uint32_t*)&Chi[gi] = H;
                    *(uint32_t*)&Clo[gi] = L;
                } else {
                    *(uint32_t*)&Chi[gi] = pack_hi2(v0, v1);   // bf16 bits
                    *(uint32_t*)&Clo[gi] = pack_lo2(v0, v1);
                }
            }
        }
    }
}

// =====================================================================
// Flash attention, bf16x3, causal.  Bq=128 (8 warps x 16 rows), Bc=64.
// Input: qkv bf16 hi/lo split. Output: o fp16 hi/lo split (Wo input).
// =====================================================================
#define FL_SMEM 110592

__global__ __launch_bounds__(256)
void flash_kernel(const __nv_bfloat16* __restrict__ qkv_hi,
                  const __nv_bfloat16* __restrict__ qkv_lo,
                  __half* __restrict__ o_hi,
                  __half* __restrict__ o_lo)
{
    extern __shared__ char fsm[];
    const uint32_t sb = smem_u32(fsm);
    const int tid = threadIdx.x, lane = tid & 31, w = tid >> 5;
    const int bh = blockIdx.x;
    const int it = 7 - blockIdx.y;
    const int b = bh >> 4, h = bh & 15;
    const int nk = 2*(it+1);
    const size_t rs = 3*DMODEL;

    {
        const size_t tok0 = (size_t)(b*SEQ + it*128);
        #pragma unroll
        for (int i = 0; i < 4; i++){
            int idx = tid + i*256;
            int r = idx >> 3, c = idx & 7;
            size_t g = (tok0 + r)*rs + h*64 + c*8;
            uint32_t sa = sb + r*144 + c*16;
            cp16(sa,         qkv_hi + g);
            cp16(sa + 18432, qkv_lo + g);
        }
        asm volatile("cp.async.commit_group;");
    }
    #define ISSUE_KV(jt_) do {                                               \
        uint32_t st_ = sb + 36864u + (uint32_t)((jt_)&1)*36864u;             \
        const size_t tok0_ = (size_t)(b*SEQ + (jt_)*64);                     \
        _Pragma("unroll")                                                    \
        for (int i_ = 0; i_ < 2; i_++){                                      \
            int idx_ = tid + i_*256;                                         \
            int r_ = idx_ >> 3, c_ = idx_ & 7;                               \
            size_t gk_ = (tok0_ + r_)*rs + DMODEL   + h*64 + c_*8;           \
            size_t gv_ = (tok0_ + r_)*rs + 2*DMODEL + h*64 + c_*8;           \
            uint32_t sa_ = st_ + r_*144 + c_*16;                             \
            cp16(sa_,         qkv_hi + gk_);                                 \
            cp16(sa_ + 9216,  qkv_lo + gk_);                                 \
            cp16(sa_ + 18432, qkv_hi + gv_);                                 \
            cp16(sa_ + 27648, qkv_lo + gv_);                                 \
        }                                                                    \
        asm volatile("cp.async.commit_group;");                              \
    } while(0)

    ISSUE_KV(0);
    asm volatile("cp.async.wait_group 1;");
    __syncthreads();

    uint32_t qh[4][4], ql[4][4];
    {
        uint32_t rbase = sb + (w*16 + (lane & 15))*144 + ((lane >> 4)*8)*2;
        #pragma unroll
        for (int ks = 0; ks < 4; ks++){
            ldsm_x4(qh[ks], rbase + ks*32);
            ldsm_x4(ql[ks], rbase + ks*32 + 18432);
        }
    }

    float O[8][4];
    #pragma unroll
    for (int nt = 0; nt < 8; nt++)
        #pragma unroll
        for (int c = 0; c < 4; c++) O[nt][c] = 0.f;
    float m0 = -INFINITY, m1 = -INFINITY, l0 = 0.f, l1 = 0.f;
    const int r0g = it*128 + w*16 + (lane >> 2);

    for (int jt = 0; jt < nk; jt++){
        if (jt + 1 < nk){ ISSUE_KV(jt+1); asm volatile("cp.async.wait_group 1;"); }
        else            { asm volatile("cp.async.wait_group 0;"); }
        __syncthreads();
        const uint32_t st = sb + 36864u + (uint32_t)(jt&1)*36864u;

        float S[8][4];
        #pragma unroll
        for (int nt = 0; nt < 8; nt++)
            #pragma unroll
            for (int c = 0; c < 4; c++) S[nt][c] = 0.f;

        const uint32_t kb = st + (lane & 7)*144 + (((lane >> 3) & 1)*8)*2;
        #pragma unroll
        for (int nt = 0; nt < 8; nt++){
            #pragma unroll
            for (int ks = 0; ks < 4; ks++){
                uint32_t a = kb + nt*8*144 + ks*32;
                uint32_t kh[2], kl[2];
                ldsm_x2(kh, a);
                ldsm_x2(kl, a + 9216);
                mma_bf16(S[nt], qh[ks], kh);
                mma_bf16(S[nt], qh[ks], kl);
                mma_bf16(S[nt], ql[ks], kh);
            }
        }

        const bool diag = (jt >= 2*it);
        float mx0 = -INFINITY, mx1 = -INFINITY;
        #pragma unroll
        for (int nt = 0; nt < 8; nt++){
            int colb = jt*64 + nt*8 + (lane & 3)*2;
            #pragma unroll
            for (int q = 0; q < 2; q++){
                float v0 = S[nt][q]   * 0.125f;
                float v1 = S[nt][2+q] * 0.125f;
                if (diag){
                    if (colb + q > r0g)     v0 = -INFINITY;
                    if (colb + q > r0g + 8) v1 = -INFINITY;
                }
                S[nt][q] = v0; S[nt][2+q] = v1;
                mx0 = fmaxf(mx0, v0); mx1 = fmaxf(mx1, v1);
            }
        }
        mx0 = fmaxf(mx0, __shfl_xor_sync(0xffffffffu, mx0, 1));
        mx0 = fmaxf(mx0, __shfl_xor_sync(0xffffffffu, mx0, 2));
        mx1 = fmaxf(mx1, __shfl_xor_sync(0xffffffffu, mx1, 1));
        mx1 = fmaxf(mx1, __shfl_xor_sync(0xffffffffu, mx1, 2));
        float mn0 = fmaxf(m0, mx0), mn1 = fmaxf(m1, mx1);
        float f0 = __expf(m0 - mn0), f1 = __expf(m1 - mn1);
        m0 = mn0; m1 = mn1;
        float ls0 = 0.f, ls1 = 0.f;
        #pragma unroll
        for (int nt = 0; nt < 8; nt++){
            #pragma unroll
            for (int q = 0; q < 2; q++){
                float e0 = __expf(S[nt][q]   - m0);
                float e1 = __expf(S[nt][2+q] - m1);
                S[nt][q] = e0; S[nt][2+q] = e1;
                ls0 += e0; ls1 += e1;
            }
        }
        l0 = l0*f0 + ls0;
        l1 = l1*f1 + ls1;
        #pragma unroll
        for (int nt = 0; nt < 8; nt++){
            O[nt][0] *= f0; O[nt][1] *= f0;
            O[nt][2] *= f1; O[nt][3] *= f1;
        }

        #pragma unroll
        for (int ks = 0; ks < 4; ks++){
            uint32_t ph[4], pl[4];
            ph[0] = pack_hi2(S[2*ks][0],   S[2*ks][1]);
            ph[1] = pack_hi2(S[2*ks][2],   S[2*ks][3]);
            ph[2] = pack_hi2(S[2*ks+1][0], S[2*ks+1][1]);
            ph[3] = pack_hi2(S[2*ks+1][2], S[2*ks+1][3]);
            pl[0] = pack_lo2(S[2*ks][0],   S[2*ks][1]);
            pl[1] = pack_lo2(S[2*ks][2],   S[2*ks][3]);
            pl[2] = pack_lo2(S[2*ks+1][0], S[2*ks+1][1]);
            pl[3] = pack_lo2(S[2*ks+1][2], S[2*ks+1][3]);
            uint32_t vb = st + 18432u + (ks*16 + (lane & 15))*144;
            #pragma unroll
            for (int nt = 0; nt < 8; nt++){
                uint32_t vh[2], vl[2];
                ldsm_x2t(vh, vb + nt*16);
                ldsm_x2t(vl, vb + nt*16 + 9216);
                mma_bf16(O[nt], ph, vh);
                mma_bf16(O[nt], ph, vl);
                mma_bf16(O[nt], pl, vh);
            }
        }
        __syncthreads();
    }

    l0 += __shfl_xor_sync(0xffffffffu, l0, 1);
    l0 += __shfl_xor_sync(0xffffffffu, l0, 2);
    l1 += __shfl_xor_sync(0xffffffffu, l1, 1);
    l1 += __shfl_xor_sync(0xffffffffu, l1, 2);
    float inv0 = 1.0f / l0, inv1 = 1.0f / l1;
    const size_t tok0 = (size_t)(b*SEQ + it*128 + w*16 + (lane >> 2));
    const int colb = h*64 + (lane & 3)*2;
    #pragma unroll
    for (int nt = 0; nt < 8; nt++){
        #pragma unroll
        for (int rh = 0; rh < 2; rh++){
            float inv = rh ? inv1 : inv0;
            float v0 = O[nt][rh*2+0] * inv;
            float v1 = O[nt][rh*2+1] * inv;
            size_t gi = (tok0 + rh*8)*DMODEL + colb + nt*8;
            uint32_t H, L;
            split_f16_2(v0, v1, H, L);
            *(uint32_t*)&o_hi[gi] = H;
            *(uint32_t*)&o_lo[gi] = L;
        }
    }
}

// ---------------- weight convert: fp32 -> fp16 ----------------
__global__ void wconv_f16_kernel(const float4* __restrict__ in,
                                 uint2* __restrict__ out, int n4){
    int i = blockIdx.x * blockDim.x + threadIdx.x;
    if (i >= n4) return;
    float4 v = in[i];
    __half2 a = __floats2half2_rn(v.x, v.y);
    __half2 b = __floats2half2_rn(v.z, v.w);
    uint2 o;
    o.x = *reinterpret_cast<uint32_t*>(&a);
    o.y = *reinterpret_cast<uint32_t*>(&b);
    out[i] = o;
}

// ---------------- copy x -> h ----------------
__global__ void copy_kernel(const float* __restrict__ in, float* __restrict__ out){
    int idx = blockIdx.x * blockDim.x + threadIdx.x;
    float4 v = ((const float4*)in)[idx];
    ((float4*)out)[idx] = v;
}

// ---------------- LayerNorm: fp16 hi/lo split out (+ optional f32) ----------------
template<bool WF32>
__global__ void ln_kernel(const float* __restrict__ in,
                          const float* __restrict__ w,
                          const float* __restrict__ b,
                          float* __restrict__ out,
                          __half* __restrict__ out_hi,
                          __half* __restrict__ out_lo){
    int row = blockIdx.x;
    int t   = threadIdx.x;
    const float* x = in + (size_t)row * DMODEL;
    float4 v = *(const float4*)&x[t*4];
    float s  = v.x + v.y + v.z + v.w;
    float sq = v.x*v.x + v.y*v.y + v.z*v.z + v.w*v.w;
    s  = warp_sum(s);
    sq = warp_sum(sq);
    __shared__ float sh1[8], sh2[8];
    int warp = t >> 5, lane = t & 31;
    if (lane == 0){ sh1[warp] = s; sh2[warp] = sq; }
    __syncthreads();
    float tot = 0.f, tot2 = 0.f;
    #pragma unroll
    for (int i = 0; i < 8; i++){ tot += sh1[i]; tot2 += sh2[i]; }
    float mu   = tot  * (1.0f/DMODEL);
    float var  = tot2 * (1.0f/DMODEL) - mu*mu;
    float rstd = rsqrtf(var + EPS);
    float4 wv = *(const float4*)&w[t*4];
    float4 bv = *(const float4*)&b[t*4];
    float4 ov;
    ov.x = (v.x - mu)*rstd*wv.x + bv.x;
    ov.y = (v.y - mu)*rstd*wv.y + bv.y;
    ov.z = (v.z - mu)*rstd*wv.z + bv.z;
    ov.w = (v.w - mu)*rstd*wv.w + bv.w;
    size_t base = (size_t)row*DMODEL + t*4;
    if (WF32) *(float4*)&out[base] = ov;
    uint2 H, L;
    split_f16_2(ov.x, ov.y, H.x, L.x);
    split_f16_2(ov.z, ov.w, H.y, L.y);
    *(uint2*)&out_hi[base] = H;
    *(uint2*)&out_lo[base] = L;
}

// ---------------- final projection ----------------
__global__ __launch_bounds__(256)
void pred_kernel(const float* __restrict__ hn, const float* __restrict__ Wp,
                 const float* __restrict__ bp, float* __restrict__ out){
    int row = blockIdx.x;
    int t = threadIdx.x;
    float local[WIN] = {0,0,0,0,0};
    const float* x = hn + (size_t)row * DMODEL;
    for (int k = t; k < DMODEL; k += 256){
        float xv = x[k];
        const float* wr = Wp + (size_t)k * WIN;
        #pragma unroll
        for (int w = 0; w < WIN; w++) local[w] = fmaf(xv, wr[w], local[w]);
    }
    __shared__ float red[WIN][256];
    #pragma unroll
    for (int w = 0; w < WIN; w++) red[w][t] = local[w];
    __syncthreads();
    for (int s = 128; s > 0; s >>= 1){
        if (t < s){
            #pragma unroll
            for (int w = 0; w < WIN; w++) red[w][t] += red[w][t + s];
        }
        __syncthreads();
    }
    if (t < WIN) out[(size_t)row * WIN + t] = red[t][0] + bp[t];
}

// ---------------- host orchestration ----------------
extern "C" void kernel_launch(void* const* d_in, const int* in_sizes, int n_in,
                              void* d_out, int out_size){
    const float* x     = (const float*)d_in[0];
    const float* Wqkv  = (const float*)d_in[1];
    const float* bqkv  = (const float*)d_in[2];
    const float* Wo    = (const float*)d_in[3];
    const float* bo    = (const float*)d_in[4];
    const float* ln1w  = (const float*)d_in[5];
    const float* ln1b  = (const float*)d_in[6];
    const float* W1    = (const float*)d_in[7];
    const float* b1    = (const float*)d_in[8];
    const float* W2    = (const float*)d_in[9];
    const float* b2    = (const float*)d_in[10];
    const float* ln2w  = (const float*)d_in[11];
    const float* ln2b  = (const float*)d_in[12];
    const float* lnfw  = (const float*)d_in[13];
    const float* lnfb  = (const float*)d_in[14];
    const float* Wp    = (const float*)d_in[15];
    const float* bp    = (const float*)d_in[16];
    float* out = (float*)d_out;

    float *g_h, *g_hn;
    __nv_bfloat16 *g_qkv_hi, *g_qkv_lo;
    __half *g_hn_hi, *g_hn_lo, *g_o_hi, *g_o_lo, *g_ff_hi, *g_ff_lo, *g_wf16;
    cudaGetSymbolAddress((void**)&g_h,      d_h);
    cudaGetSymbolAddress((void**)&g_hn,     d_hn);
    cudaGetSymbolAddress((void**)&g_hn_hi,  d_hn_hi);
    cudaGetSymbolAddress((void**)&g_hn_lo,  d_hn_lo);
    cudaGetSymbolAddress((void**)&g_qkv_hi, d_qkv_hi);
    cudaGetSymbolAddress((void**)&g_qkv_lo, d_qkv_lo);
    cudaGetSymbolAddress((void**)&g_o_hi,   d_o_hi);
    cudaGetSymbolAddress((void**)&g_o_lo,   d_o_lo);
    cudaGetSymbolAddress((void**)&g_ff_hi,  d_ff_hi);
    cudaGetSymbolAddress((void**)&g_ff_lo,  d_ff_lo);
    cudaGetSymbolAddress((void**)&g_wf16,   d_wf16);

    cudaFuncSetAttribute(gemm_f16x2<1>, cudaFuncAttributeMaxDynamicSharedMemorySize, FGEMM_SMEM);
    cudaFuncSetAttribute(gemm_f16x2<2>, cudaFuncAttributeMaxDynamicSharedMemorySize, FGEMM_SMEM);
    cudaFuncSetAttribute(gemm_f16x2<3>, cudaFuncAttributeMaxDynamicSharedMemorySize, FGEMM_SMEM);
    cudaFuncSetAttribute(flash_kernel,  cudaFuncAttributeMaxDynamicSharedMemorySize, FL_SMEM);

    // weight preprocessing: everything to fp16
    wconv_f16_kernel<<<QKV_ELEMS/4/256, 256>>>((const float4*)Wqkv,
        (uint2*)(g_wf16 + WF_QKV), QKV_ELEMS/4);
    wconv_f16_kernel<<<WO_ELEMS/4/256, 256>>>((const float4*)Wo,
        (uint2*)(g_wf16 + WF_WO),  WO_ELEMS/4);
    wconv_f16_kernel<<<W1_ELEMS/4/256, 256>>>((const float4*)W1,
        (uint2*)(g_wf16 + WF_W1),  W1_ELEMS/4);
    wconv_f16_kernel<<<W2_ELEMS/4/256, 256>>>((const float4*)W2,
        (uint2*)(g_wf16 + WF_W2),  W2_ELEMS/4);

    copy_kernel<<<TOKENS*DMODEL/4/256, 256>>>(x, g_h);

    for (int l = 0; l < LAYERS; l++){
        const __half* wqkv = g_wf16 + WF_QKV + (size_t)l * DMODEL * 3*DMODEL;
        const __half* wo   = g_wf16 + WF_WO  + (size_t)l * DMODEL * DMODEL;
        const __half* w1   = g_wf16 + WF_W1  + (size_t)l * DMODEL * DFF;
        const __half* w2   = g_wf16 + WF_W2  + (size_t)l * DFF * DMODEL;
        const float* bq = bqkv + (size_t)l * 3*DMODEL;
        const float* bO = bo   + (size_t)l * DMODEL;
        const float* B1 = b1   + (size_t)l * DFF;
        const float* B2 = b2   + (size_t)l * DMODEL;

        // pre-norm attention
        ln_kernel<false><<<TOKENS, 256>>>(g_h, ln1w + l*DMODEL, ln1b + l*DMODEL,
                                          nullptr, g_hn_hi, g_hn_lo);
        gemm_f16x2<3><<<dim3(3*DMODEL/128, TOKENS/128), 256, FGEMM_SMEM>>>(
            g_hn_hi, g_hn_lo, wqkv, bq, nullptr,
            nullptr, (__half*)g_qkv_hi, (__half*)g_qkv_lo, TOKENS, 3*DMODEL, DMODEL);
        flash_kernel<<<dim3(BATCH*NHEAD, SEQ/128), 256, FL_SMEM>>>(
            g_qkv_hi, g_qkv_lo, g_o_hi, g_o_lo);
        gemm_f16x2<1><<<dim3(DMODEL/128, TOKENS/128), 256, FGEMM_SMEM>>>(
            g_o_hi, g_o_lo, wo, bO, g_h,
            g_h, nullptr, nullptr, TOKENS, DMODEL, DMODEL);

        // pre-norm FFN
        ln_kernel<false><<<TOKENS, 256>>>(g_h, ln2w + l*DMODEL, ln2b + l*DMODEL,
                                          nullptr, g_hn_hi, g_hn_lo);
        gemm_f16x2<2><<<dim3(DFF/128, TOKENS/128), 256, FGEMM_SMEM>>>(
            g_hn_hi, g_hn_lo, w1, B1, nullptr,
            nullptr, g_ff_hi, g_ff_lo, TOKENS, DFF, DMODEL);
        gemm_f16x2<1><<<dim3(DMODEL/128, TOKENS/128), 256, FGEMM_SMEM>>>(
            g_ff_hi, g_ff_lo, w2, B2, g_h,
            g_h, nullptr, nullptr, TOKENS, DMODEL, DFF);
    }

    // final LN + projection
    ln_kernel<true><<<TOKENS, 256>>>(g_h, lnfw, lnfb, g_hn, g_hn_hi, g_hn_lo);
    pred_kernel<<<TOKENS, 256>>>(g_hn, Wp, bp, out);
    (void)in_sizes; (void)n_in; (void)out_size;
}

// round 10
// speedup vs baseline: 1.9768x; 1.5170x over previous
#include <cuda_runtime.h>
#include <cuda_bf16.h>
#include <cuda_fp16.h>
#include <math.h>
#include <stdint.h>

// ---------------- problem constants ----------------
#define LAYERS 6
#define BATCH  2
#define SEQ    1024
#define DMODEL 1024
#define NHEAD  16
#define HDIM   64
#define DFF    4096
#define WIN    5
#define TOKENS (BATCH*SEQ)          // 2048
#define EPS    1e-5f

// fp16 weight scratch layout (elements)
#define QKV_ELEMS  (LAYERS*DMODEL*3*DMODEL)
#define WO_ELEMS   (LAYERS*DMODEL*DMODEL)
#define W1_ELEMS   (LAYERS*DMODEL*DFF)
#define W2_ELEMS   (LAYERS*DFF*DMODEL)
#define WF_QKV 0
#define WF_WO  (QKV_ELEMS)
#define WF_W1  (WF_WO + WO_ELEMS)
#define WF_W2  (WF_W1 + W1_ELEMS)
#define WF_TOT (WF_W2 + W2_ELEMS)

// ---------------- device scratch (no allocation allowed) ----------------
__device__ float d_h   [TOKENS*DMODEL];
__device__ float d_hn  [TOKENS*DMODEL];
__device__ __half d_hnf [TOKENS*DMODEL];            // fp16 LN output
__device__ __nv_bfloat16 d_qkv_hi[TOKENS*3*DMODEL]; // bf16 split (flash input)
__device__ __nv_bfloat16 d_qkv_lo[TOKENS*3*DMODEL];
__device__ __half d_of  [TOKENS*DMODEL];            // fp16 attn output
__device__ __half d_fff [TOKENS*DFF];               // fp16 GELU output
__device__ __half d_wf16[WF_TOT];                   // all weights, fp16

// ---------------- small helpers ----------------
__device__ __forceinline__ float warp_sum(float v){
    #pragma unroll
    for (int o = 16; o; o >>= 1) v += __shfl_xor_sync(0xffffffffu, v, o);
    return v;
}
__device__ __forceinline__ float gelu_exact(float x){
    return 0.5f * x * (1.0f + erff(x * 0.70710678118654752440f));
}
__device__ __forceinline__ uint32_t smem_u32(const void* p){
    uint32_t a;
    asm("{ .reg .u64 t; cvta.to.shared.u64 t, %1; cvt.u32.u64 %0, t; }" : "=r"(a) : "l"(p));
    return a;
}
__device__ __forceinline__ uint32_t pack_hi2(float x, float y){
    return (__float_as_uint(x) >> 16) | (__float_as_uint(y) & 0xFFFF0000u);
}
__device__ __forceinline__ uint32_t pack_lo2(float x, float y){
    float lx = x - __uint_as_float(__float_as_uint(x) & 0xFFFF0000u);
    float ly = y - __uint_as_float(__float_as_uint(y) & 0xFFFF0000u);
    __nv_bfloat162 t = __floats2bfloat162_rn(lx, ly);
    return *reinterpret_cast<uint32_t*>(&t);
}
__device__ __forceinline__ uint32_t pack_f16_2(float x, float y){
    __half2 h = __floats2half2_rn(x, y);
    return *reinterpret_cast<uint32_t*>(&h);
}

// ---------------- mma.sync / ldmatrix / cp.async wrappers ----------------
__device__ __forceinline__ void mma_bf16(float* d, const uint32_t* a, const uint32_t* b){
    asm volatile(
      "mma.sync.aligned.m16n8k16.row.col.f32.bf16.bf16.f32 "
      "{%0,%1,%2,%3}, {%4,%5,%6,%7}, {%8,%9}, {%0,%1,%2,%3};\n"
      : "+f"(d[0]), "+f"(d[1]), "+f"(d[2]), "+f"(d[3])
      : "r"(a[0]), "r"(a[1]), "r"(a[2]), "r"(a[3]), "r"(b[0]), "r"(b[1]));
}
__device__ __forceinline__ void mma_f16(float* d, const uint32_t* a, const uint32_t* b){
    asm volatile(
      "mma.sync.aligned.m16n8k16.row.col.f32.f16.f16.f32 "
      "{%0,%1,%2,%3}, {%4,%5,%6,%7}, {%8,%9}, {%0,%1,%2,%3};\n"
      : "+f"(d[0]), "+f"(d[1]), "+f"(d[2]), "+f"(d[3])
      : "r"(a[0]), "r"(a[1]), "r"(a[2]), "r"(a[3]), "r"(b[0]), "r"(b[1]));
}
__device__ __forceinline__ void ldsm_x4(uint32_t* r, uint32_t addr){
    asm volatile("ldmatrix.sync.aligned.m8n8.x4.shared.b16 {%0,%1,%2,%3}, [%4];"
      : "=r"(r[0]), "=r"(r[1]), "=r"(r[2]), "=r"(r[3]) : "r"(addr));
}
__device__ __forceinline__ void ldsm_x2(uint32_t* r, uint32_t addr){
    asm volatile("ldmatrix.sync.aligned.m8n8.x2.shared.b16 {%0,%1}, [%2];"
      : "=r"(r[0]), "=r"(r[1]) : "r"(addr));
}
__device__ __forceinline__ void ldsm_x2t(uint32_t* r, uint32_t addr){
    asm volatile("ldmatrix.sync.aligned.m8n8.x2.trans.shared.b16 {%0,%1}, [%2];"
      : "=r"(r[0]), "=r"(r[1]) : "r"(addr));
}
__device__ __forceinline__ void cp16(uint32_t s, const void* g){
    asm volatile("cp.async.cg.shared.global [%0], [%1], 16;\n" :: "r"(s), "l"(g));
}

// ---------------- fp16 1-pass GEMM smem layout (3 stages) ----------------
#define KC       32
#define A_STRIDE 80
#define B_STRIDE 272
#define F_B_OFF  10240
#define F_STAGE  18944
#define FGEMM_SMEM (3*F_STAGE)   // 56832

__device__ __forceinline__ void issue_stage_f16(
    const __half* __restrict__ A, const __half* __restrict__ B,
    uint32_t sb0, int tid, int m0, int n0, int K, int N, int c)
{
    uint32_t sb = sb0 + (uint32_t)(c % 3) * F_STAGE;
    int k0 = c * KC;
    #pragma unroll
    for (int i = 0; i < 2; i++){
        int idx = tid + i*256;               // 512 chunks: A 128x32 fp16
        int r = idx >> 2, cc = idx & 3;
        cp16(sb + r*A_STRIDE + cc*16, A + (size_t)(m0 + r) * K + k0 + cc*8);
    }
    #pragma unroll
    for (int i = 0; i < 2; i++){
        int idx = tid + i*256;               // 512 chunks: B 32x128 fp16
        int r = idx >> 4, cc = idx & 15;
        cp16(sb + F_B_OFF + r*B_STRIDE + cc*16, B + (size_t)(k0 + r) * N + n0 + cc*8);
    }
    asm volatile("cp.async.commit_group;");
}

// =====================================================================
// fp16 1-pass GEMM: C = epi(A @ B + bias); A, B single fp16.
// EPI: 1 = bias+residual (f32 out)
//      2 = bias+GELU -> fp16 out
//      3 = bias -> bf16 hi/lo split out (flash input)
// =====================================================================
template<int EPI>
__global__ __launch_bounds__(256, 2)
void gemm_f16(const __half* __restrict__ A, const __half* __restrict__ B,
              const float* __restrict__ bias, const float* __restrict__ res,
              float* __restrict__ C, __half* __restrict__ Cf,
              __nv_bfloat16* __restrict__ Chi, __nv_bfloat16* __restrict__ Clo,
              int M, int N, int K)
{
    extern __shared__ char smem[];
    const uint32_t sb0 = smem_u32(smem);
    const int tid  = threadIdx.x;
    const int lane = tid & 31, wid = tid >> 5;
    const int m0 = blockIdx.y * 128, n0 = blockIdx.x * 128;
    const int wm = (wid >> 2) * 64, wn = (wid & 3) * 32;

    float acc[4][4][4];
    #pragma unroll
    for (int a = 0; a < 4; a++)
        #pragma unroll
        for (int b = 0; b < 4; b++)
            #pragma unroll
            for (int cc = 0; cc < 4; cc++) acc[a][b][cc] = 0.f;

    const int nch = K / KC;
    issue_stage_f16(A, B, sb0, tid, m0, n0, K, N, 0);
    issue_stage_f16(A, B, sb0, tid, m0, n0, K, N, 1);

    const uint32_t a_lrow = wm + (lane & 15);
    const uint32_t a_lcol = (lane >> 4) * 8;
    const uint32_t b_lrow = (lane & 15);

    for (int c = 0; c < nch; c++){
        asm volatile("cp.async.wait_group %0;" :: "n"(1));
        __syncthreads();
        if (c + 2 < nch) issue_stage_f16(A, B, sb0, tid, m0, n0, K, N, c + 2);
        else asm volatile("cp.async.commit_group;");

        uint32_t sb = sb0 + (uint32_t)(c % 3) * F_STAGE;
        #pragma unroll
        for (int ks = 0; ks < 2; ks++){
            uint32_t ah[4][4], bb[4][2];
            #pragma unroll
            for (int mt = 0; mt < 4; mt++)
                ldsm_x4(ah[mt], sb + (a_lrow + mt*16)*A_STRIDE + (ks*16 + a_lcol)*2);
            #pragma unroll
            for (int nt = 0; nt < 4; nt++)
                ldsm_x2t(bb[nt], sb + F_B_OFF + (ks*16 + b_lrow)*B_STRIDE + (wn + nt*8)*2);
            #pragma unroll
            for (int mt = 0; mt < 4; mt++)
                #pragma unroll
                for (int nt = 0; nt < 4; nt++)
                    mma_f16(acc[mt][nt], ah[mt], bb[nt]);
        }
    }

    const int g  = lane >> 2;
    const int tq = (lane & 3) * 2;
    #pragma unroll
    for (int mt = 0; mt < 4; mt++){
        #pragma unroll
        for (int half = 0; half < 2; half++){
            int m = m0 + wm + mt*16 + g + half*8;
            #pragma unroll
            for (int nt = 0; nt < 4; nt++){
                int n = n0 + wn + nt*8 + tq;
                float v0 = acc[mt][nt][half*2+0] + bias[n];
                float v1 = acc[mt][nt][half*2+1] + bias[n+1];
                size_t gi = (size_t)m * N + n;
                if (EPI == 1){
                    v0 += res[gi]; v1 += res[gi+1];
                    float2 o; o.x = v0; o.y = v1;
                    *(float2*)&C[gi] = o;
                } else if (EPI == 2){
                    v0 = gelu_exact(v0); v1 = gelu_exact(v1);
                    *(uint32_t*)&Cf[gi] = pack_f16_2(v0, v1);
                } else {
                    *(uint32_t*)&Chi[gi] = pack_hi2(v0, v1);
                    *(uint32_t*)&Clo[gi] = pack_lo2(v0, v1);
                }
            }
        }
    }
}

// =====================================================================
// Flash attention, bf16x3, causal.  Bq=128 (8 warps x 16 rows), Bc=64.
// Input: qkv bf16 hi/lo split. Output: o single fp16 (Wo input).
// =====================================================================
#define FL_SMEM 110592

__global__ __launch_bounds__(256)
void flash_kernel(const __nv_bfloat16* __restrict__ qkv_hi,
                  const __nv_bfloat16* __restrict__ qkv_lo,
                  __half* __restrict__ of)
{
    extern __shared__ char fsm[];
    const uint32_t sb = smem_u32(fsm);
    const int tid = threadIdx.x, lane = tid & 31, w = tid >> 5;
    const int bh = blockIdx.x;
    const int it = 7 - blockIdx.y;
    const int b = bh >> 4, h = bh & 15;
    const int nk = 2*(it+1);
    const size_t rs = 3*DMODEL;

    {
        const size_t tok0 = (size_t)(b*SEQ + it*128);
        #pragma unroll
        for (int i = 0; i < 4; i++){
            int idx = tid + i*256;
            int r = idx >> 3, c = idx & 7;
            size_t g = (tok0 + r)*rs + h*64 + c*8;
            uint32_t sa = sb + r*144 + c*16;
            cp16(sa,         qkv_hi + g);
            cp16(sa + 18432, qkv_lo + g);
        }
        asm volatile("cp.async.commit_group;");
    }
    #define ISSUE_KV(jt_) do {                                               \
        uint32_t st_ = sb + 36864u + (uint32_t)((jt_)&1)*36864u;             \
        const size_t tok0_ = (size_t)(b*SEQ + (jt_)*64);                     \
        _Pragma("unroll")                                                    \
        for (int i_ = 0; i_ < 2; i_++){                                      \
            int idx_ = tid + i_*256;                                         \
            int r_ = idx_ >> 3, c_ = idx_ & 7;                               \
            size_t gk_ = (tok0_ + r_)*rs + DMODEL   + h*64 + c_*8;           \
            size_t gv_ = (tok0_ + r_)*rs + 2*DMODEL + h*64 + c_*8;           \
            uint32_t sa_ = st_ + r_*144 + c_*16;                             \
            cp16(sa_,         qkv_hi + gk_);                                 \
            cp16(sa_ + 9216,  qkv_lo + gk_);                                 \
            cp16(sa_ + 18432, qkv_hi + gv_);                                 \
            cp16(sa_ + 27648, qkv_lo + gv_);                                 \
        }                                                                    \
        asm volatile("cp.async.commit_group;");                              \
    } while(0)

    ISSUE_KV(0);
    asm volatile("cp.async.wait_group 1;");
    __syncthreads();

    uint32_t qh[4][4], ql[4][4];
    {
        uint32_t rbase = sb + (w*16 + (lane & 15))*144 + ((lane >> 4)*8)*2;
        #pragma unroll
        for (int ks = 0; ks < 4; ks++){
            ldsm_x4(qh[ks], rbase + ks*32);
            ldsm_x4(ql[ks], rbase + ks*32 + 18432);
        }
    }

    float O[8][4];
    #pragma unroll
    for (int nt = 0; nt < 8; nt++)
        #pragma unroll
        for (int c = 0; c < 4; c++) O[nt][c] = 0.f;
    float m0 = -INFINITY, m1 = -INFINITY, l0 = 0.f, l1 = 0.f;
    const int r0g = it*128 + w*16 + (lane >> 2);

    for (int jt = 0; jt < nk; jt++){
        if (jt + 1 < nk){ ISSUE_KV(jt+1); asm volatile("cp.async.wait_group 1;"); }
        else            { asm volatile("cp.async.wait_group 0;"); }
        __syncthreads();
        const uint32_t st = sb + 36864u + (uint32_t)(jt&1)*36864u;

        float S[8][4];
        #pragma unroll
        for (int nt = 0; nt < 8; nt++)
            #pragma unroll
            for (int c = 0; c < 4; c++) S[nt][c] = 0.f;

        const uint32_t kb = st + (lane & 7)*144 + (((lane >> 3) & 1)*8)*2;
        #pragma unroll
        for (int nt = 0; nt < 8; nt++){
            #pragma unroll
            for (int ks = 0; ks < 4; ks++){
                uint32_t a = kb + nt*8*144 + ks*32;
                uint32_t kh[2], kl[2];
                ldsm_x2(kh, a);
                ldsm_x2(kl, a + 9216);
                mma_bf16(S[nt], qh[ks], kh);
                mma_bf16(S[nt], qh[ks], kl);
                mma_bf16(S[nt], ql[ks], kh);
            }
        }

        const bool diag = (jt >= 2*it);
        float mx0 = -INFINITY, mx1 = -INFINITY;
        #pragma unroll
        for (int nt = 0; nt < 8; nt++){
            int colb = jt*64 + nt*8 + (lane & 3)*2;
            #pragma unroll
            for (int q = 0; q < 2; q++){
                float v0 = S[nt][q]   * 0.125f;
                float v1 = S[nt][2+q] * 0.125f;
                if (diag){
                    if (colb + q > r0g)     v0 = -INFINITY;
                    if (colb + q > r0g + 8) v1 = -INFINITY;
                }
                S[nt][q] = v0; S[nt][2+q] = v1;
                mx0 = fmaxf(mx0, v0); mx1 = fmaxf(mx1, v1);
            }
        }
        mx0 = fmaxf(mx0, __shfl_xor_sync(0xffffffffu, mx0, 1));
        mx0 = fmaxf(mx0, __shfl_xor_sync(0xffffffffu, mx0, 2));
        mx1 = fmaxf(mx1, __shfl_xor_sync(0xffffffffu, mx1, 1));
        mx1 = fmaxf(mx1, __shfl_xor_sync(0xffffffffu, mx1, 2));
        float mn0 = fmaxf(m0, mx0), mn1 = fmaxf(m1, mx1);
        float f0 = __expf(m0 - mn0), f1 = __expf(m1 - mn1);
        m0 = mn0; m1 = mn1;
        float ls0 = 0.f, ls1 = 0.f;
        #pragma unroll
        for (int nt = 0; nt < 8; nt++){
            #pragma unroll
            for (int q = 0; q < 2; q++){
                float e0 = __expf(S[nt][q]   - m0);
                float e1 = __expf(S[nt][2+q] - m1);
                S[nt][q] = e0; S[nt][2+q] = e1;
                ls0 += e0; ls1 += e1;
            }
        }
        l0 = l0*f0 + ls0;
        l1 = l1*f1 + ls1;
        #pragma unroll
        for (int nt = 0; nt < 8; nt++){
            O[nt][0] *= f0; O[nt][1] *= f0;
            O[nt][2] *= f1; O[nt][3] *= f1;
        }

        #pragma unroll
        for (int ks = 0; ks < 4; ks++){
            uint32_t ph[4], pl[4];
            ph[0] = pack_hi2(S[2*ks][0],   S[2*ks][1]);
            ph[1] = pack_hi2(S[2*ks][2],   S[2*ks][3]);
            ph[2] = pack_hi2(S[2*ks+1][0], S[2*ks+1][1]);
            ph[3] = pack_hi2(S[2*ks+1][2], S[2*ks+1][3]);
            pl[0] = pack_lo2(S[2*ks][0],   S[2*ks][1]);
            pl[1] = pack_lo2(S[2*ks][2],   S[2*ks][3]);
            pl[2] = pack_lo2(S[2*ks+1][0], S[2*ks+1][1]);
            pl[3] = pack_lo2(S[2*ks+1][2], S[2*ks+1][3]);
            uint32_t vb = st + 18432u + (ks*16 + (lane & 15))*144;
            #pragma unroll
            for (int nt = 0; nt < 8; nt++){
                uint32_t vh[2], vl[2];
                ldsm_x2t(vh, vb + nt*16);
                ldsm_x2t(vl, vb + nt*16 + 9216);
                mma_bf16(O[nt], ph, vh);
                mma_bf16(O[nt], ph, vl);
                mma_bf16(O[nt], pl, vh);
            }
        }
        __syncthreads();
    }

    l0 += __shfl_xor_sync(0xffffffffu, l0, 1);
    l0 += __shfl_xor_sync(0xffffffffu, l0, 2);
    l1 += __shfl_xor_sync(0xffffffffu, l1, 1);
    l1 += __shfl_xor_sync(0xffffffffu, l1, 2);
    float inv0 = 1.0f / l0, inv1 = 1.0f / l1;
    const size_t tok0 = (size_t)(b*SEQ + it*128 + w*16 + (lane >> 2));
    const int colb = h*64 + (lane & 3)*2;
    #pragma unroll
    for (int nt = 0; nt < 8; nt++){
        #pragma unroll
        for (int rh = 0; rh < 2; rh++){
            float inv = rh ? inv1 : inv0;
            float v0 = O[nt][rh*2+0] * inv;
            float v1 = O[nt][rh*2+1] * inv;
            size_t gi = (tok0 + rh*8)*DMODEL + colb + nt*8;
            *(uint32_t*)&of[gi] = pack_f16_2(v0, v1);
        }
    }
}

// ---------------- weight convert: fp32 -> fp16 ----------------
__global__ void wconv_f16_kernel(const float4* __restrict__ in,
                                 uint2* __restrict__ out, int n4){
    int i = blockIdx.x * blockDim.x + threadIdx.x;
    if (i >= n4) return;
    float4 v = in[i];
    uint2 o;
    o.x = pack_f16_2(v.x, v.y);
    o.y = pack_f16_2(v.z, v.w);
    out[i] = o;
}

// ---------------- copy x -> h ----------------
__global__ void copy_kernel(const float* __restrict__ in, float* __restrict__ out){
    int idx = blockIdx.x * blockDim.x + threadIdx.x;
    float4 v = ((const float4*)in)[idx];
    ((float4*)out)[idx] = v;
}

// ---------------- LayerNorm: single fp16 out (+ optional f32) ----------------
template<bool WF32>
__global__ void ln_kernel(const float* __restrict__ in,
                          const float* __restrict__ w,
                          const float* __restrict__ b,
                          float* __restrict__ out,
                          __half* __restrict__ outf){
    int row = blockIdx.x;
    int t   = threadIdx.x;
    const float* x = in + (size_t)row * DMODEL;
    float4 v = *(const float4*)&x[t*4];
    float s  = v.x + v.y + v.z + v.w;
    float sq = v.x*v.x + v.y*v.y + v.z*v.z + v.w*v.w;
    s  = warp_sum(s);
    sq = warp_sum(sq);
    __shared__ float sh1[8], sh2[8];
    int warp = t >> 5, lane = t & 31;
    if (lane == 0){ sh1[warp] = s; sh2[warp] = sq; }
    __syncthreads();
    float tot = 0.f, tot2 = 0.f;
    #pragma unroll
    for (int i = 0; i < 8; i++){ tot += sh1[i]; tot2 += sh2[i]; }
    float mu   = tot  * (1.0f/DMODEL);
    float var  = tot2 * (1.0f/DMODEL) - mu*mu;
    float rstd = rsqrtf(var + EPS);
    float4 wv = *(const float4*)&w[t*4];
    float4 bv = *(const float4*)&b[t*4];
    float4 ov;
    ov.x = (v.x - mu)*rstd*wv.x + bv.x;
    ov.y = (v.y - mu)*rstd*wv.y + bv.y;
    ov.z = (v.z - mu)*rstd*wv.z + bv.z;
    ov.w = (v.w - mu)*rstd*wv.w + bv.w;
    size_t base = (size_t)row*DMODEL + t*4;
    if (WF32) *(float4*)&out[base] = ov;
    uint2 H;
    H.x = pack_f16_2(ov.x, ov.y);
    H.y = pack_f16_2(ov.z, ov.w);
    *(uint2*)&outf[base] = H;
}

// ---------------- final projection ----------------
__global__ __launch_bounds__(256)
void pred_kernel(const float* __restrict__ hn, const float* __restrict__ Wp,
                 const float* __restrict__ bp, float* __restrict__ out){
    int row = blockIdx.x;
    int t = threadIdx.x;
    float local[WIN] = {0,0,0,0,0};
    const float* x = hn + (size_t)row * DMODEL;
    for (int k = t; k < DMODEL; k += 256){
        float xv = x[k];
        const float* wr = Wp + (size_t)k * WIN;
        #pragma unroll
        for (int w = 0; w < WIN; w++) local[w] = fmaf(xv, wr[w], local[w]);
    }
    __shared__ float red[WIN][256];
    #pragma unroll
    for (int w = 0; w < WIN; w++) red[w][t] = local[w];
    __syncthreads();
    for (int s = 128; s > 0; s >>= 1){
        if (t < s){
            #pragma unroll
            for (int w = 0; w < WIN; w++) red[w][t] += red[w][t + s];
        }
        __syncthreads();
    }
    if (t < WIN) out[(size_t)row * WIN + t] = red[t][0] + bp[t];
}

// ---------------- host orchestration ----------------
extern "C" void kernel_launch(void* const* d_in, const int* in_sizes, int n_in,
                              void* d_out, int out_size){
    const float* x     = (const float*)d_in[0];
    const float* Wqkv  = (const float*)d_in[1];
    const float* bqkv  = (const float*)d_in[2];
    const float* Wo    = (const float*)d_in[3];
    const float* bo    = (const float*)d_in[4];
    const float* ln1w  = (const float*)d_in[5];
    const float* ln1b  = (const float*)d_in[6];
    const float* W1    = (const float*)d_in[7];
    const float* b1    = (const float*)d_in[8];
    const float* W2    = (const float*)d_in[9];
    const float* b2    = (const float*)d_in[10];
    const float* ln2w  = (const float*)d_in[11];
    const float* ln2b  = (const float*)d_in[12];
    const float* lnfw  = (const float*)d_in[13];
    const float* lnfb  = (const float*)d_in[14];
    const float* Wp    = (const float*)d_in[15];
    const float* bp    = (const float*)d_in[16];
    float* out = (float*)d_out;

    float *g_h, *g_hn;
    __nv_bfloat16 *g_qkv_hi, *g_qkv_lo;
    __half *g_hnf, *g_of, *g_fff, *g_wf16;
    cudaGetSymbolAddress((void**)&g_h,      d_h);
    cudaGetSymbolAddress((void**)&g_hn,     d_hn);
    cudaGetSymbolAddress((void**)&g_hnf,    d_hnf);
    cudaGetSymbolAddress((void**)&g_qkv_hi, d_qkv_hi);
    cudaGetSymbolAddress((void**)&g_qkv_lo, d_qkv_lo);
    cudaGetSymbolAddress((void**)&g_of,     d_of);
    cudaGetSymbolAddress((void**)&g_fff,    d_fff);
    cudaGetSymbolAddress((void**)&g_wf16,   d_wf16);

    cudaFuncSetAttribute(gemm_f16<1>, cudaFuncAttributeMaxDynamicSharedMemorySize, FGEMM_SMEM);
    cudaFuncSetAttribute(gemm_f16<2>, cudaFuncAttributeMaxDynamicSharedMemorySize, FGEMM_SMEM);
    cudaFuncSetAttribute(gemm_f16<3>, cudaFuncAttributeMaxDynamicSharedMemorySize, FGEMM_SMEM);
    cudaFuncSetAttribute(flash_kernel, cudaFuncAttributeMaxDynamicSharedMemorySize, FL_SMEM);

    // weight preprocessing: everything to fp16
    wconv_f16_kernel<<<QKV_ELEMS/4/256, 256>>>((const float4*)Wqkv,
        (uint2*)(g_wf16 + WF_QKV), QKV_ELEMS/4);
    wconv_f16_kernel<<<WO_ELEMS/4/256, 256>>>((const float4*)Wo,
        (uint2*)(g_wf16 + WF_WO),  WO_ELEMS/4);
    wconv_f16_kernel<<<W1_ELEMS/4/256, 256>>>((const float4*)W1,
        (uint2*)(g_wf16 + WF_W1),  W1_ELEMS/4);
    wconv_f16_kernel<<<W2_ELEMS/4/256, 256>>>((const float4*)W2,
        (uint2*)(g_wf16 + WF_W2),  W2_ELEMS/4);

    copy_kernel<<<TOKENS*DMODEL/4/256, 256>>>(x, g_h);

    for (int l = 0; l < LAYERS; l++){
        const __half* wqkv = g_wf16 + WF_QKV + (size_t)l * DMODEL * 3*DMODEL;
        const __half* wo   = g_wf16 + WF_WO  + (size_t)l * DMODEL * DMODEL;
        const __half* w1   = g_wf16 + WF_W1  + (size_t)l * DMODEL * DFF;
        const __half* w2   = g_wf16 + WF_W2  + (size_t)l * DFF * DMODEL;
        const float* bq = bqkv + (size_t)l * 3*DMODEL;
        const float* bO = bo   + (size_t)l * DMODEL;
        const float* B1 = b1   + (size_t)l * DFF;
        const float* B2 = b2   + (size_t)l * DMODEL;

        // pre-norm attention
        ln_kernel<false><<<TOKENS, 256>>>(g_h, ln1w + l*DMODEL, ln1b + l*DMODEL,
                                          nullptr, g_hnf);
        gemm_f16<3><<<dim3(3*DMODEL/128, TOKENS/128), 256, FGEMM_SMEM>>>(
            g_hnf, wqkv, bq, nullptr,
            nullptr, nullptr, g_qkv_hi, g_qkv_lo, TOKENS, 3*DMODEL, DMODEL);
        flash_kernel<<<dim3(BATCH*NHEAD, SEQ/128), 256, FL_SMEM>>>(
            g_qkv_hi, g_qkv_lo, g_of);
        gemm_f16<1><<<dim3(DMODEL/128, TOKENS/128), 256, FGEMM_SMEM>>>(
            g_of, wo, bO, g_h,
            g_h, nullptr, nullptr, nullptr, TOKENS, DMODEL, DMODEL);

        // pre-norm FFN
        ln_kernel<false><<<TOKENS, 256>>>(g_h, ln2w + l*DMODEL, ln2b + l*DMODEL,
                                          nullptr, g_hnf);
        gemm_f16<2><<<dim3(DFF/128, TOKENS/128), 256, FGEMM_SMEM>>>(
            g_hnf, w1, B1, nullptr,
            nullptr, g_fff, nullptr, nullptr, TOKENS, DFF, DMODEL);
        gemm_f16<1><<<dim3(DMODEL/128, TOKENS/128), 256, FGEMM_SMEM>>>(
            g_fff, w2, B2, g_h,
            g_h, nullptr, nullptr, nullptr, TOKENS, DMODEL, DFF);
    }

    // final LN + projection
    ln_kernel<true><<<TOKENS, 256>>>(g_h, lnfw, lnfb, g_hn, g_hnf);
    pred_kernel<<<TOKENS, 256>>>(g_hn, Wp, bp, out);
    (void)in_sizes; (void)n_in; (void)out_size;
}

// round 11
// speedup vs baseline: 2.1573x; 1.0913x over previous
#include <cuda_runtime.h>
#include <cuda_bf16.h>
#include <cuda_fp16.h>
#include <math.h>
#include <stdint.h>

// ---------------- problem constants ----------------
#define LAYERS 6
#define BATCH  2
#define SEQ    1024
#define DMODEL 1024
#define NHEAD  16
#define HDIM   64
#define DFF    4096
#define WIN    5
#define TOKENS (BATCH*SEQ)          // 2048
#define EPS    1e-5f

// fp16 weight scratch layout (elements)
#define QKV_ELEMS  (LAYERS*DMODEL*3*DMODEL)
#define WO_ELEMS   (LAYERS*DMODEL*DMODEL)
#define W1_ELEMS   (LAYERS*DMODEL*DFF)
#define W2_ELEMS   (LAYERS*DFF*DMODEL)
#define WF_QKV 0
#define WF_WO  (QKV_ELEMS)
#define WF_W1  (WF_WO + WO_ELEMS)
#define WF_W2  (WF_W1 + W1_ELEMS)
#define WF_TOT (WF_W2 + W2_ELEMS)

// ---------------- device scratch (no allocation allowed) ----------------
__device__ float d_h   [TOKENS*DMODEL];
__device__ float d_hn  [TOKENS*DMODEL];
__device__ __half d_hnf [TOKENS*DMODEL];   // fp16 LN output
__device__ __half d_qkvf[TOKENS*3*DMODEL]; // fp16 qkv (flash input)
__device__ __half d_of  [TOKENS*DMODEL];   // fp16 attn output
__device__ __half d_fff [TOKENS*DFF];      // fp16 GELU output
__device__ __half d_wf16[WF_TOT];          // all weights, fp16

// ---------------- small helpers ----------------
__device__ __forceinline__ float warp_sum(float v){
    #pragma unroll
    for (int o = 16; o; o >>= 1) v += __shfl_xor_sync(0xffffffffu, v, o);
    return v;
}
__device__ __forceinline__ float gelu_exact(float x){
    return 0.5f * x * (1.0f + erff(x * 0.70710678118654752440f));
}
__device__ __forceinline__ uint32_t smem_u32(const void* p){
    uint32_t a;
    asm("{ .reg .u64 t; cvta.to.shared.u64 t, %1; cvt.u32.u64 %0, t; }" : "=r"(a) : "l"(p));
    return a;
}
__device__ __forceinline__ uint32_t pack_f16_2(float x, float y){
    __half2 h = __floats2half2_rn(x, y);
    return *reinterpret_cast<uint32_t*>(&h);
}

// ---------------- mma.sync / ldmatrix / cp.async wrappers ----------------
__device__ __forceinline__ void mma_f16(float* d, const uint32_t* a, const uint32_t* b){
    asm volatile(
      "mma.sync.aligned.m16n8k16.row.col.f32.f16.f16.f32 "
      "{%0,%1,%2,%3}, {%4,%5,%6,%7}, {%8,%9}, {%0,%1,%2,%3};\n"
      : "+f"(d[0]), "+f"(d[1]), "+f"(d[2]), "+f"(d[3])
      : "r"(a[0]), "r"(a[1]), "r"(a[2]), "r"(a[3]), "r"(b[0]), "r"(b[1]));
}
__device__ __forceinline__ void ldsm_x4(uint32_t* r, uint32_t addr){
    asm volatile("ldmatrix.sync.aligned.m8n8.x4.shared.b16 {%0,%1,%2,%3}, [%4];"
      : "=r"(r[0]), "=r"(r[1]), "=r"(r[2]), "=r"(r[3]) : "r"(addr));
}
__device__ __forceinline__ void ldsm_x2(uint32_t* r, uint32_t addr){
    asm volatile("ldmatrix.sync.aligned.m8n8.x2.shared.b16 {%0,%1}, [%2];"
      : "=r"(r[0]), "=r"(r[1]) : "r"(addr));
}
__device__ __forceinline__ void ldsm_x2t(uint32_t* r, uint32_t addr){
    asm volatile("ldmatrix.sync.aligned.m8n8.x2.trans.shared.b16 {%0,%1}, [%2];"
      : "=r"(r[0]), "=r"(r[1]) : "r"(addr));
}
__device__ __forceinline__ void cp16(uint32_t s, const void* g){
    asm volatile("cp.async.cg.shared.global [%0], [%1], 16;\n" :: "r"(s), "l"(g));
}

// ---------------- fp16 1-pass GEMM smem layout (3 stages) ----------------
#define KC       32
#define A_STRIDE 80
#define B_STRIDE 272
#define F_B_OFF  10240
#define F_STAGE  18944
#define FGEMM_SMEM (3*F_STAGE)   // 56832

__device__ __forceinline__ void issue_stage_f16(
    const __half* __restrict__ A, const __half* __restrict__ B,
    uint32_t sb0, int tid, int m0, int n0, int K, int N, int c)
{
    uint32_t sb = sb0 + (uint32_t)(c % 3) * F_STAGE;
    int k0 = c * KC;
    #pragma unroll
    for (int i = 0; i < 2; i++){
        int idx = tid + i*256;               // 512 chunks: A 128x32 fp16
        int r = idx >> 2, cc = idx & 3;
        cp16(sb + r*A_STRIDE + cc*16, A + (size_t)(m0 + r) * K + k0 + cc*8);
    }
    #pragma unroll
    for (int i = 0; i < 2; i++){
        int idx = tid + i*256;               // 512 chunks: B 32x128 fp16
        int r = idx >> 4, cc = idx & 15;
        cp16(sb + F_B_OFF + r*B_STRIDE + cc*16, B + (size_t)(k0 + r) * N + n0 + cc*8);
    }
    asm volatile("cp.async.commit_group;");
}

// =====================================================================
// fp16 1-pass GEMM: C = epi(A @ B + bias); A, B single fp16.
// EPI: 0 = bias -> fp16 out
//      1 = bias+residual (f32 out)
//      2 = bias+GELU -> fp16 out
// =====================================================================
template<int EPI>
__global__ __launch_bounds__(256, 2)
void gemm_f16(const __half* __restrict__ A, const __half* __restrict__ B,
              const float* __restrict__ bias, const float* __restrict__ res,
              float* __restrict__ C, __half* __restrict__ Cf,
              int M, int N, int K)
{
    extern __shared__ char smem[];
    const uint32_t sb0 = smem_u32(smem);
    const int tid  = threadIdx.x;
    const int lane = tid & 31, wid = tid >> 5;
    const int m0 = blockIdx.y * 128, n0 = blockIdx.x * 128;
    const int wm = (wid >> 2) * 64, wn = (wid & 3) * 32;

    float acc[4][4][4];
    #pragma unroll
    for (int a = 0; a < 4; a++)
        #pragma unroll
        for (int b = 0; b < 4; b++)
            #pragma unroll
            for (int cc = 0; cc < 4; cc++) acc[a][b][cc] = 0.f;

    const int nch = K / KC;
    issue_stage_f16(A, B, sb0, tid, m0, n0, K, N, 0);
    issue_stage_f16(A, B, sb0, tid, m0, n0, K, N, 1);

    const uint32_t a_lrow = wm + (lane & 15);
    const uint32_t a_lcol = (lane >> 4) * 8;
    const uint32_t b_lrow = (lane & 15);

    for (int c = 0; c < nch; c++){
        asm volatile("cp.async.wait_group %0;" :: "n"(1));
        __syncthreads();
        if (c + 2 < nch) issue_stage_f16(A, B, sb0, tid, m0, n0, K, N, c + 2);
        else asm volatile("cp.async.commit_group;");

        uint32_t sb = sb0 + (uint32_t)(c % 3) * F_STAGE;
        #pragma unroll
        for (int ks = 0; ks < 2; ks++){
            uint32_t ah[4][4], bb[4][2];
            #pragma unroll
            for (int mt = 0; mt < 4; mt++)
                ldsm_x4(ah[mt], sb + (a_lrow + mt*16)*A_STRIDE + (ks*16 + a_lcol)*2);
            #pragma unroll
            for (int nt = 0; nt < 4; nt++)
                ldsm_x2t(bb[nt], sb + F_B_OFF + (ks*16 + b_lrow)*B_STRIDE + (wn + nt*8)*2);
            #pragma unroll
            for (int mt = 0; mt < 4; mt++)
                #pragma unroll
                for (int nt = 0; nt < 4; nt++)
                    mma_f16(acc[mt][nt], ah[mt], bb[nt]);
        }
    }

    const int g  = lane >> 2;
    const int tq = (lane & 3) * 2;
    #pragma unroll
    for (int mt = 0; mt < 4; mt++){
        #pragma unroll
        for (int half = 0; half < 2; half++){
            int m = m0 + wm + mt*16 + g + half*8;
            #pragma unroll
            for (int nt = 0; nt < 4; nt++){
                int n = n0 + wn + nt*8 + tq;
                float v0 = acc[mt][nt][half*2+0] + bias[n];
                float v1 = acc[mt][nt][half*2+1] + bias[n+1];
                size_t gi = (size_t)m * N + n;
                if (EPI == 1){
                    v0 += res[gi]; v1 += res[gi+1];
                    float2 o; o.x = v0; o.y = v1;
                    *(float2*)&C[gi] = o;
                } else {
                    if (EPI == 2){ v0 = gelu_exact(v0); v1 = gelu_exact(v1); }
                    *(uint32_t*)&Cf[gi] = pack_f16_2(v0, v1);
                }
            }
        }
    }
}

// =====================================================================
// Flash attention, single fp16, causal.  Bq=128 (8 warps x 16 rows), Bc=64.
// smem: Q 0..18432 | stage s at 18432+s*18432: K +0, V +9216
// =====================================================================
#define FL_SMEM 55296

__global__ __launch_bounds__(256)
void flash_kernel(const __half* __restrict__ qkvf, __half* __restrict__ of)
{
    extern __shared__ char fsm[];
    const uint32_t sb = smem_u32(fsm);
    const int tid = threadIdx.x, lane = tid & 31, w = tid >> 5;
    const int bh = blockIdx.x;
    const int it = 7 - blockIdx.y;           // heavy q-tiles first
    const int b = bh >> 4, h = bh & 15;
    const int nk = 2*(it+1);
    const size_t rs = 3*DMODEL;

    // ---- Q loads (group 0): 1024 x 16B chunks ----
    {
        const size_t tok0 = (size_t)(b*SEQ + it*128);
        #pragma unroll
        for (int i = 0; i < 4; i++){
            int idx = tid + i*256;
            int r = idx >> 3, c = idx & 7;
            cp16(sb + r*144 + c*16, qkvf + (tok0 + r)*rs + h*64 + c*8);
        }
        asm volatile("cp.async.commit_group;");
    }
    #define ISSUE_KV(jt_) do {                                               \
        uint32_t st_ = sb + 18432u + (uint32_t)((jt_)&1)*18432u;             \
        const size_t tok0_ = (size_t)(b*SEQ + (jt_)*64);                     \
        _Pragma("unroll")                                                    \
        for (int i_ = 0; i_ < 2; i_++){                                      \
            int idx_ = tid + i_*256;                                         \
            int r_ = idx_ >> 3, c_ = idx_ & 7;                               \
            uint32_t sa_ = st_ + r_*144 + c_*16;                             \
            cp16(sa_,        qkvf + (tok0_ + r_)*rs + DMODEL   + h*64 + c_*8); \
            cp16(sa_ + 9216, qkvf + (tok0_ + r_)*rs + 2*DMODEL + h*64 + c_*8); \
        }                                                                    \
        asm volatile("cp.async.commit_group;");                              \
    } while(0)

    ISSUE_KV(0);
    asm volatile("cp.async.wait_group 1;");   // Q ready
    __syncthreads();

    // ---- Q fragments (registers for whole kernel) ----
    uint32_t qh[4][4];
    {
        uint32_t rbase = sb + (w*16 + (lane & 15))*144 + ((lane >> 4)*8)*2;
        #pragma unroll
        for (int ks = 0; ks < 4; ks++)
            ldsm_x4(qh[ks], rbase + ks*32);
    }

    float O[8][4];
    #pragma unroll
    for (int nt = 0; nt < 8; nt++)
        #pragma unroll
        for (int c = 0; c < 4; c++) O[nt][c] = 0.f;
    float m0 = -INFINITY, m1 = -INFINITY, l0 = 0.f, l1 = 0.f;
    const int r0g = it*128 + w*16 + (lane >> 2);

    for (int jt = 0; jt < nk; jt++){
        if (jt + 1 < nk){ ISSUE_KV(jt+1); asm volatile("cp.async.wait_group 1;"); }
        else            { asm volatile("cp.async.wait_group 0;"); }
        __syncthreads();
        const uint32_t st = sb + 18432u + (uint32_t)(jt&1)*18432u;

        // ---- S = Q K^T (1 pass) ----
        float S[8][4];
        #pragma unroll
        for (int nt = 0; nt < 8; nt++)
            #pragma unroll
            for (int c = 0; c < 4; c++) S[nt][c] = 0.f;

        const uint32_t kb = st + (lane & 7)*144 + (((lane >> 3) & 1)*8)*2;
        #pragma unroll
        for (int nt = 0; nt < 8; nt++){
            #pragma unroll
            for (int ks = 0; ks < 4; ks++){
                uint32_t kh[2];
                ldsm_x2(kh, kb + nt*8*144 + ks*32);
                mma_f16(S[nt], qh[ks], kh);
            }
        }

        // ---- mask + scale + online softmax ----
        const bool diag = (jt >= 2*it);
        float mx0 = -INFINITY, mx1 = -INFINITY;
        #pragma unroll
        for (int nt = 0; nt < 8; nt++){
            int colb = jt*64 + nt*8 + (lane & 3)*2;
            #pragma unroll
            for (int q = 0; q < 2; q++){
                float v0 = S[nt][q]   * 0.125f;
                float v1 = S[nt][2+q] * 0.125f;
                if (diag){
                    if (colb + q > r0g)     v0 = -INFINITY;
                    if (colb + q > r0g + 8) v1 = -INFINITY;
                }
                S[nt][q] = v0; S[nt][2+q] = v1;
                mx0 = fmaxf(mx0, v0); mx1 = fmaxf(mx1, v1);
            }
        }
        mx0 = fmaxf(mx0, __shfl_xor_sync(0xffffffffu, mx0, 1));
        mx0 = fmaxf(mx0, __shfl_xor_sync(0xffffffffu, mx0, 2));
        mx1 = fmaxf(mx1, __shfl_xor_sync(0xffffffffu, mx1, 1));
        mx1 = fmaxf(mx1, __shfl_xor_sync(0xffffffffu, mx1, 2));
        float mn0 = fmaxf(m0, mx0), mn1 = fmaxf(m1, mx1);
        float f0 = __expf(m0 - mn0), f1 = __expf(m1 - mn1);
        m0 = mn0; m1 = mn1;
        float ls0 = 0.f, ls1 = 0.f;
        #pragma unroll
        for (int nt = 0; nt < 8; nt++){
            #pragma unroll
            for (int q = 0; q < 2; q++){
                float e0 = __expf(S[nt][q]   - m0);
                float e1 = __expf(S[nt][2+q] - m1);
                S[nt][q] = e0; S[nt][2+q] = e1;
                ls0 += e0; ls1 += e1;
            }
        }
        l0 = l0*f0 + ls0;
        l1 = l1*f1 + ls1;
        #pragma unroll
        for (int nt = 0; nt < 8; nt++){
            O[nt][0] *= f0; O[nt][1] *= f0;
            O[nt][2] *= f1; O[nt][3] *= f1;
        }

        // ---- O += P V (1 pass) ----
        #pragma unroll
        for (int ks = 0; ks < 4; ks++){
            uint32_t ph[4];
            ph[0] = pack_f16_2(S[2*ks][0],   S[2*ks][1]);
            ph[1] = pack_f16_2(S[2*ks][2],   S[2*ks][3]);
            ph[2] = pack_f16_2(S[2*ks+1][0], S[2*ks+1][1]);
            ph[3] = pack_f16_2(S[2*ks+1][2], S[2*ks+1][3]);
            uint32_t vb = st + 9216u + (ks*16 + (lane & 15))*144;
            #pragma unroll
            for (int nt = 0; nt < 8; nt++){
                uint32_t vh[2];
                ldsm_x2t(vh, vb + nt*16);
                mma_f16(O[nt], ph, vh);
            }
        }
        __syncthreads();   // protect buffer (jt&1) before re-issue
    }

    l0 += __shfl_xor_sync(0xffffffffu, l0, 1);
    l0 += __shfl_xor_sync(0xffffffffu, l0, 2);
    l1 += __shfl_xor_sync(0xffffffffu, l1, 1);
    l1 += __shfl_xor_sync(0xffffffffu, l1, 2);
    float inv0 = 1.0f / l0, inv1 = 1.0f / l1;
    const size_t tok0 = (size_t)(b*SEQ + it*128 + w*16 + (lane >> 2));
    const int colb = h*64 + (lane & 3)*2;
    #pragma unroll
    for (int nt = 0; nt < 8; nt++){
        #pragma unroll
        for (int rh = 0; rh < 2; rh++){
            float inv = rh ? inv1 : inv0;
            float v0 = O[nt][rh*2+0] * inv;
            float v1 = O[nt][rh*2+1] * inv;
            size_t gi = (tok0 + rh*8)*DMODEL + colb + nt*8;
            *(uint32_t*)&of[gi] = pack_f16_2(v0, v1);
        }
    }
}

// ---------------- weight convert: fp32 -> fp16 ----------------
__global__ void wconv_f16_kernel(const float4* __restrict__ in,
                                 uint2* __restrict__ out, int n4){
    int i = blockIdx.x * blockDim.x + threadIdx.x;
    if (i >= n4) return;
    float4 v = in[i];
    uint2 o;
    o.x = pack_f16_2(v.x, v.y);
    o.y = pack_f16_2(v.z, v.w);
    out[i] = o;
}

// ---------------- copy x -> h ----------------
__global__ void copy_kernel(const float* __restrict__ in, float* __restrict__ out){
    int idx = blockIdx.x * blockDim.x + threadIdx.x;
    float4 v = ((const float4*)in)[idx];
    ((float4*)out)[idx] = v;
}

// ---------------- LayerNorm: single fp16 out (+ optional f32) ----------------
template<bool WF32>
__global__ void ln_kernel(const float* __restrict__ in,
                          const float* __restrict__ w,
                          const float* __restrict__ b,
                          float* __restrict__ out,
                          __half* __restrict__ outf){
    int row = blockIdx.x;
    int t   = threadIdx.x;
    const float* x = in + (size_t)row * DMODEL;
    float4 v = *(const float4*)&x[t*4];
    float s  = v.x + v.y + v.z + v.w;
    float sq = v.x*v.x + v.y*v.y + v.z*v.z + v.w*v.w;
    s  = warp_sum(s);
    sq = warp_sum(sq);
    __shared__ float sh1[8], sh2[8];
    int warp = t >> 5, lane = t & 31;
    if (lane == 0){ sh1[warp] = s; sh2[warp] = sq; }
    __syncthreads();
    float tot = 0.f, tot2 = 0.f;
    #pragma unroll
    for (int i = 0; i < 8; i++){ tot += sh1[i]; tot2 += sh2[i]; }
    float mu   = tot  * (1.0f/DMODEL);
    float var  = tot2 * (1.0f/DMODEL) - mu*mu;
    float rstd = rsqrtf(var + EPS);
    float4 wv = *(const float4*)&w[t*4];
    float4 bv = *(const float4*)&b[t*4];
    float4 ov;
    ov.x = (v.x - mu)*rstd*wv.x + bv.x;
    ov.y = (v.y - mu)*rstd*wv.y + bv.y;
    ov.z = (v.z - mu)*rstd*wv.z + bv.z;
    ov.w = (v.w - mu)*rstd*wv.w + bv.w;
    size_t base = (size_t)row*DMODEL + t*4;
    if (WF32) *(float4*)&out[base] = ov;
    uint2 H;
    H.x = pack_f16_2(ov.x, ov.y);
    H.y = pack_f16_2(ov.z, ov.w);
    *(uint2*)&outf[base] = H;
}

// ---------------- final projection ----------------
__global__ __launch_bounds__(256)
void pred_kernel(const float* __restrict__ hn, const float* __restrict__ Wp,
                 const float* __restrict__ bp, float* __restrict__ out){
    int row = blockIdx.x;
    int t = threadIdx.x;
    float local[WIN] = {0,0,0,0,0};
    const float* x = hn + (size_t)row * DMODEL;
    for (int k = t; k < DMODEL; k += 256){
        float xv = x[k];
        const float* wr = Wp + (size_t)k * WIN;
        #pragma unroll
        for (int w = 0; w < WIN; w++) local[w] = fmaf(xv, wr[w], local[w]);
    }
    __shared__ float red[WIN][256];
    #pragma unroll
    for (int w = 0; w < WIN; w++) red[w][t] = local[w];
    __syncthreads();
    for (int s = 128; s > 0; s >>= 1){
        if (t < s){
            #pragma unroll
            for (int w = 0; w < WIN; w++) red[w][t] += red[w][t + s];
        }
        __syncthreads();
    }
    if (t < WIN) out[(size_t)row * WIN + t] = red[t][0] + bp[t];
}

// ---------------- host orchestration ----------------
extern "C" void kernel_launch(void* const* d_in, const int* in_sizes, int n_in,
                              void* d_out, int out_size){
    const float* x     = (const float*)d_in[0];
    const float* Wqkv  = (const float*)d_in[1];
    const float* bqkv  = (const float*)d_in[2];
    const float* Wo    = (const float*)d_in[3];
    const float* bo    = (const float*)d_in[4];
    const float* ln1w  = (const float*)d_in[5];
    const float* ln1b  = (const float*)d_in[6];
    const float* W1    = (const float*)d_in[7];
    const float* b1    = (const float*)d_in[8];
    const float* W2    = (const float*)d_in[9];
    const float* b2    = (const float*)d_in[10];
    const float* ln2w  = (const float*)d_in[11];
    const float* ln2b  = (const float*)d_in[12];
    const float* lnfw  = (const float*)d_in[13];
    const float* lnfb  = (const float*)d_in[14];
    const float* Wp    = (const float*)d_in[15];
    const float* bp    = (const float*)d_in[16];
    float* out = (float*)d_out;

    float *g_h, *g_hn;
    __half *g_hnf, *g_qkvf, *g_of, *g_fff, *g_wf16;
    cudaGetSymbolAddress((void**)&g_h,    d_h);
    cudaGetSymbolAddress((void**)&g_hn,   d_hn);
    cudaGetSymbolAddress((void**)&g_hnf,  d_hnf);
    cudaGetSymbolAddress((void**)&g_qkvf, d_qkvf);
    cudaGetSymbolAddress((void**)&g_of,   d_of);
    cudaGetSymbolAddress((void**)&g_fff,  d_fff);
    cudaGetSymbolAddress((void**)&g_wf16, d_wf16);

    cudaFuncSetAttribute(gemm_f16<0>, cudaFuncAttributeMaxDynamicSharedMemorySize, FGEMM_SMEM);
    cudaFuncSetAttribute(gemm_f16<1>, cudaFuncAttributeMaxDynamicSharedMemorySize, FGEMM_SMEM);
    cudaFuncSetAttribute(gemm_f16<2>, cudaFuncAttributeMaxDynamicSharedMemorySize, FGEMM_SMEM);
    cudaFuncSetAttribute(flash_kernel, cudaFuncAttributeMaxDynamicSharedMemorySize, FL_SMEM);

    // weight preprocessing: everything to fp16
    wconv_f16_kernel<<<QKV_ELEMS/4/256, 256>>>((const float4*)Wqkv,
        (uint2*)(g_wf16 + WF_QKV), QKV_ELEMS/4);
    wconv_f16_kernel<<<WO_ELEMS/4/256, 256>>>((const float4*)Wo,
        (uint2*)(g_wf16 + WF_WO),  WO_ELEMS/4);
    wconv_f16_kernel<<<W1_ELEMS/4/256, 256>>>((const float4*)W1,
        (uint2*)(g_wf16 + WF_W1),  W1_ELEMS/4);
    wconv_f16_kernel<<<W2_ELEMS/4/256, 256>>>((const float4*)W2,
        (uint2*)(g_wf16 + WF_W2),  W2_ELEMS/4);

    copy_kernel<<<TOKENS*DMODEL/4/256, 256>>>(x, g_h);

    for (int l = 0; l < LAYERS; l++){
        const __half* wqkv = g_wf16 + WF_QKV + (size_t)l * DMODEL * 3*DMODEL;
        const __half* wo   = g_wf16 + WF_WO  + (size_t)l * DMODEL * DMODEL;
        const __half* w1   = g_wf16 + WF_W1  + (size_t)l * DMODEL * DFF;
        const __half* w2   = g_wf16 + WF_W2  + (size_t)l * DFF * DMODEL;
        const float* bq = bqkv + (size_t)l * 3*DMODEL;
        const float* bO = bo   + (size_t)l * DMODEL;
        const float* B1 = b1   + (size_t)l * DFF;
        const float* B2 = b2   + (size_t)l * DMODEL;

        // pre-norm attention
        ln_kernel<false><<<TOKENS, 256>>>(g_h, ln1w + l*DMODEL, ln1b + l*DMODEL,
                                          nullptr, g_hnf);
        gemm_f16<0><<<dim3(3*DMODEL/128, TOKENS/128), 256, FGEMM_SMEM>>>(
            g_hnf, wqkv, bq, nullptr, nullptr, g_qkvf, TOKENS, 3*DMODEL, DMODEL);
        flash_kernel<<<dim3(BATCH*NHEAD, SEQ/128), 256, FL_SMEM>>>(g_qkvf, g_of);
        gemm_f16<1><<<dim3(DMODEL/128, TOKENS/128), 256, FGEMM_SMEM>>>(
            g_of, wo, bO, g_h, g_h, nullptr, TOKENS, DMODEL, DMODEL);

        // pre-norm FFN
        ln_kernel<false><<<TOKENS, 256>>>(g_h, ln2w + l*DMODEL, ln2b + l*DMODEL,
                                          nullptr, g_hnf);
        gemm_f16<2><<<dim3(DFF/128, TOKENS/128), 256, FGEMM_SMEM>>>(
            g_hnf, w1, B1, nullptr, nullptr, g_fff, TOKENS, DFF, DMODEL);
        gemm_f16<1><<<dim3(DMODEL/128, TOKENS/128), 256, FGEMM_SMEM>>>(
            g_fff, w2, B2, g_h, g_h, nullptr, TOKENS, DMODEL, DFF);
    }

    // final LN + projection
    ln_kernel<true><<<TOKENS, 256>>>(g_h, lnfw, lnfb, g_hn, g_hnf);
    pred_kernel<<<TOKENS, 256>>>(g_hn, Wp, bp, out);
    (void)in_sizes; (void)n_in; (void)out_size;
}

// round 12
// speedup vs baseline: 2.1608x; 1.0016x over previous
#include <cuda_runtime.h>
#include <cuda_bf16.h>
#include <cuda_fp16.h>
#include <math.h>
#include <stdint.h>

// ---------------- problem constants ----------------
#define LAYERS 6
#define BATCH  2
#define SEQ    1024
#define DMODEL 1024
#define NHEAD  16
#define HDIM   64
#define DFF    4096
#define WIN    5
#define TOKENS (BATCH*SEQ)          // 2048
#define EPS    1e-5f

// fp16 weight scratch layout (elements)
#define QKV_ELEMS  (LAYERS*DMODEL*3*DMODEL)
#define WO_ELEMS   (LAYERS*DMODEL*DMODEL)
#define W1_ELEMS   (LAYERS*DMODEL*DFF)
#define W2_ELEMS   (LAYERS*DFF*DMODEL)
#define WF_QKV 0
#define WF_WO  (QKV_ELEMS)
#define WF_W1  (WF_WO + WO_ELEMS)
#define WF_W2  (WF_W1 + W1_ELEMS)
#define WF_TOT (WF_W2 + W2_ELEMS)

// ---------------- device scratch (no allocation allowed) ----------------
__device__ float d_h   [TOKENS*DMODEL];
__device__ float d_hn  [TOKENS*DMODEL];
__device__ __half d_hnf [TOKENS*DMODEL];
__device__ __half d_qkvf[TOKENS*3*DMODEL];
__device__ __half d_of  [TOKENS*DMODEL];
__device__ __half d_fff [TOKENS*DFF];
__device__ __half d_wf16[WF_TOT];

// ---------------- small helpers ----------------
__device__ __forceinline__ float warp_sum(float v){
    #pragma unroll
    for (int o = 16; o; o >>= 1) v += __shfl_xor_sync(0xffffffffu, v, o);
    return v;
}
__device__ __forceinline__ float gelu_exact(float x){
    return 0.5f * x * (1.0f + erff(x * 0.70710678118654752440f));
}
__device__ __forceinline__ uint32_t smem_u32(const void* p){
    uint32_t a;
    asm("{ .reg .u64 t; cvta.to.shared.u64 t, %1; cvt.u32.u64 %0, t; }" : "=r"(a) : "l"(p));
    return a;
}
__device__ __forceinline__ uint32_t pack_f16_2(float x, float y){
    __half2 h = __floats2half2_rn(x, y);
    return *reinterpret_cast<uint32_t*>(&h);
}

// ---------------- mma.sync / ldmatrix / cp.async wrappers ----------------
__device__ __forceinline__ void mma_f16(float* d, const uint32_t* a, const uint32_t* b){
    asm volatile(
      "mma.sync.aligned.m16n8k16.row.col.f32.f16.f16.f32 "
      "{%0,%1,%2,%3}, {%4,%5,%6,%7}, {%8,%9}, {%0,%1,%2,%3};\n"
      : "+f"(d[0]), "+f"(d[1]), "+f"(d[2]), "+f"(d[3])
      : "r"(a[0]), "r"(a[1]), "r"(a[2]), "r"(a[3]), "r"(b[0]), "r"(b[1]));
}
__device__ __forceinline__ void ldsm_x4(uint32_t* r, uint32_t addr){
    asm volatile("ldmatrix.sync.aligned.m8n8.x4.shared.b16 {%0,%1,%2,%3}, [%4];"
      : "=r"(r[0]), "=r"(r[1]), "=r"(r[2]), "=r"(r[3]) : "r"(addr));
}
__device__ __forceinline__ void ldsm_x2(uint32_t* r, uint32_t addr){
    asm volatile("ldmatrix.sync.aligned.m8n8.x2.shared.b16 {%0,%1}, [%2];"
      : "=r"(r[0]), "=r"(r[1]) : "r"(addr));
}
__device__ __forceinline__ void ldsm_x2t(uint32_t* r, uint32_t addr){
    asm volatile("ldmatrix.sync.aligned.m8n8.x2.trans.shared.b16 {%0,%1}, [%2];"
      : "=r"(r[0]), "=r"(r[1]) : "r"(addr));
}
__device__ __forceinline__ void cp16(uint32_t s, const void* g){
    asm volatile("cp.async.cg.shared.global [%0], [%1], 16;\n" :: "r"(s), "l"(g));
}

// ---------------- fp16 GEMM smem layouts (4 stages) ----------------
#define KC       32
#define A_STRIDE 80
#define B_STRIDE 272
// 128x128 tile
#define F_B_OFF  10240
#define F_STAGE  18944
#define FGEMM_SMEM (4*F_STAGE)    // 75776
// 64x128 tile
#define G_B_OFF  5120
#define G_STAGE  13824
#define GGEMM_SMEM (4*G_STAGE)    // 55296

__device__ __forceinline__ void issue_stage_f16(
    const __half* __restrict__ A, const __half* __restrict__ B,
    uint32_t sb0, int tid, int m0, int n0, int K, int N, int c)
{
    uint32_t sb = sb0 + (uint32_t)(c & 3) * F_STAGE;
    int k0 = c * KC;
    #pragma unroll
    for (int i = 0; i < 2; i++){
        int idx = tid + i*256;
        int r = idx >> 2, cc = idx & 3;
        cp16(sb + r*A_STRIDE + cc*16, A + (size_t)(m0 + r) * K + k0 + cc*8);
    }
    #pragma unroll
    for (int i = 0; i < 2; i++){
        int idx = tid + i*256;
        int r = idx >> 4, cc = idx & 15;
        cp16(sb + F_B_OFF + r*B_STRIDE + cc*16, B + (size_t)(k0 + r) * N + n0 + cc*8);
    }
    asm volatile("cp.async.commit_group;");
}

__device__ __forceinline__ void issue_stage_g16(
    const __half* __restrict__ A, const __half* __restrict__ B,
    uint32_t sb0, int tid, int m0, int n0, int K, int N, int c)
{
    uint32_t sb = sb0 + (uint32_t)(c & 3) * G_STAGE;
    int k0 = c * KC;
    {
        int r = tid >> 2, cc = tid & 3;      // A: 64x32 fp16 = 256 chunks
        cp16(sb + r*A_STRIDE + cc*16, A + (size_t)(m0 + r) * K + k0 + cc*8);
    }
    #pragma unroll
    for (int i = 0; i < 2; i++){
        int idx = tid + i*256;
        int r = idx >> 4, cc = idx & 15;
        cp16(sb + G_B_OFF + r*B_STRIDE + cc*16, B + (size_t)(k0 + r) * N + n0 + cc*8);
    }
    asm volatile("cp.async.commit_group;");
}

// =====================================================================
// fp16 1-pass GEMM, 128x128 tile: C = epi(A @ B + bias)
// EPI: 0 = bias -> fp16   1 = bias+residual (f32)   2 = bias+GELU -> fp16
// =====================================================================
template<int EPI>
__global__ __launch_bounds__(256, 2)
void gemm_f16(const __half* __restrict__ A, const __half* __restrict__ B,
              const float* __restrict__ bias, const float* __restrict__ res,
              float* __restrict__ C, __half* __restrict__ Cf,
              int M, int N, int K)
{
    extern __shared__ char smem[];
    const uint32_t sb0 = smem_u32(smem);
    const int tid  = threadIdx.x;
    const int lane = tid & 31, wid = tid >> 5;
    const int m0 = blockIdx.y * 128, n0 = blockIdx.x * 128;
    const int wm = (wid >> 2) * 64, wn = (wid & 3) * 32;

    float acc[4][4][4];
    #pragma unroll
    for (int a = 0; a < 4; a++)
        #pragma unroll
        for (int b = 0; b < 4; b++)
            #pragma unroll
            for (int cc = 0; cc < 4; cc++) acc[a][b][cc] = 0.f;

    const int nch = K / KC;
    issue_stage_f16(A, B, sb0, tid, m0, n0, K, N, 0);
    issue_stage_f16(A, B, sb0, tid, m0, n0, K, N, 1);
    issue_stage_f16(A, B, sb0, tid, m0, n0, K, N, 2);

    const uint32_t a_lrow = wm + (lane & 15);
    const uint32_t a_lcol = (lane >> 4) * 8;
    const uint32_t b_lrow = (lane & 15);

    for (int c = 0; c < nch; c++){
        asm volatile("cp.async.wait_group %0;" :: "n"(2));
        __syncthreads();
        if (c + 3 < nch) issue_stage_f16(A, B, sb0, tid, m0, n0, K, N, c + 3);
        else asm volatile("cp.async.commit_group;");

        uint32_t sb = sb0 + (uint32_t)(c & 3) * F_STAGE;
        #pragma unroll
        for (int ks = 0; ks < 2; ks++){
            uint32_t ah[4][4], bb[4][2];
            #pragma unroll
            for (int mt = 0; mt < 4; mt++)
                ldsm_x4(ah[mt], sb + (a_lrow + mt*16)*A_STRIDE + (ks*16 + a_lcol)*2);
            #pragma unroll
            for (int nt = 0; nt < 4; nt++)
                ldsm_x2t(bb[nt], sb + F_B_OFF + (ks*16 + b_lrow)*B_STRIDE + (wn + nt*8)*2);
            #pragma unroll
            for (int mt = 0; mt < 4; mt++)
                #pragma unroll
                for (int nt = 0; nt < 4; nt++)
                    mma_f16(acc[mt][nt], ah[mt], bb[nt]);
        }
    }

    const int g  = lane >> 2;
    const int tq = (lane & 3) * 2;
    #pragma unroll
    for (int mt = 0; mt < 4; mt++){
        #pragma unroll
        for (int half = 0; half < 2; half++){
            int m = m0 + wm + mt*16 + g + half*8;
            #pragma unroll
            for (int nt = 0; nt < 4; nt++){
                int n = n0 + wn + nt*8 + tq;
                float v0 = acc[mt][nt][half*2+0] + bias[n];
                float v1 = acc[mt][nt][half*2+1] + bias[n+1];
                size_t gi = (size_t)m * N + n;
                if (EPI == 1){
                    v0 += res[gi]; v1 += res[gi+1];
                    float2 o; o.x = v0; o.y = v1;
                    *(float2*)&C[gi] = o;
                } else {
                    if (EPI == 2){ v0 = gelu_exact(v0); v1 = gelu_exact(v1); }
                    *(uint32_t*)&Cf[gi] = pack_f16_2(v0, v1);
                }
            }
        }
    }
}

// =====================================================================
// fp16 1-pass GEMM, 64x128 tile (for N=1024 GEMMs: better wave coverage).
// EPI = 1 only: bias + residual, f32 out.
// 8 warps x (32x32) warp tiles.
// =====================================================================
__global__ __launch_bounds__(256, 2)
void gemm_g16(const __half* __restrict__ A, const __half* __restrict__ B,
              const float* __restrict__ bias, const float* __restrict__ res,
              float* __restrict__ C, int M, int N, int K)
{
    extern __shared__ char smem[];
    const uint32_t sb0 = smem_u32(smem);
    const int tid  = threadIdx.x;
    const int lane = tid & 31, wid = tid >> 5;
    const int m0 = blockIdx.y * 64, n0 = blockIdx.x * 128;
    const int wm = (wid >> 2) * 32, wn = (wid & 3) * 32;

    float acc[2][4][4];
    #pragma unroll
    for (int a = 0; a < 2; a++)
        #pragma unroll
        for (int b = 0; b < 4; b++)
            #pragma unroll
            for (int cc = 0; cc < 4; cc++) acc[a][b][cc] = 0.f;

    const int nch = K / KC;
    issue_stage_g16(A, B, sb0, tid, m0, n0, K, N, 0);
    issue_stage_g16(A, B, sb0, tid, m0, n0, K, N, 1);
    issue_stage_g16(A, B, sb0, tid, m0, n0, K, N, 2);

    const uint32_t a_lrow = wm + (lane & 15);
    const uint32_t a_lcol = (lane >> 4) * 8;
    const uint32_t b_lrow = (lane & 15);

    for (int c = 0; c < nch; c++){
        asm volatile("cp.async.wait_group %0;" :: "n"(2));
        __syncthreads();
        if (c + 3 < nch) issue_stage_g16(A, B, sb0, tid, m0, n0, K, N, c + 3);
        else asm volatile("cp.async.commit_group;");

        uint32_t sb = sb0 + (uint32_t)(c & 3) * G_STAGE;
        #pragma unroll
        for (int ks = 0; ks < 2; ks++){
            uint32_t ah[2][4], bb[4][2];
            #pragma unroll
            for (int mt = 0; mt < 2; mt++)
                ldsm_x4(ah[mt], sb + (a_lrow + mt*16)*A_STRIDE + (ks*16 + a_lcol)*2);
            #pragma unroll
            for (int nt = 0; nt < 4; nt++)
                ldsm_x2t(bb[nt], sb + G_B_OFF + (ks*16 + b_lrow)*B_STRIDE + (wn + nt*8)*2);
            #pragma unroll
            for (int mt = 0; mt < 2; mt++)
                #pragma unroll
                for (int nt = 0; nt < 4; nt++)
                    mma_f16(acc[mt][nt], ah[mt], bb[nt]);
        }
    }

    const int g  = lane >> 2;
    const int tq = (lane & 3) * 2;
    #pragma unroll
    for (int mt = 0; mt < 2; mt++){
        #pragma unroll
        for (int half = 0; half < 2; half++){
            int m = m0 + wm + mt*16 + g + half*8;
            #pragma unroll
            for (int nt = 0; nt < 4; nt++){
                int n = n0 + wn + nt*8 + tq;
                float v0 = acc[mt][nt][half*2+0] + bias[n];
                float v1 = acc[mt][nt][half*2+1] + bias[n+1];
                size_t gi = (size_t)m * N + n;
                v0 += res[gi]; v1 += res[gi+1];
                float2 o; o.x = v0; o.y = v1;
                *(float2*)&C[gi] = o;
            }
        }
    }
}

// =====================================================================
// Flash attention, single fp16, causal.  Bq=128 (8 warps x 16 rows), Bc=64.
// =====================================================================
#define FL_SMEM 55296

__global__ __launch_bounds__(256)
void flash_kernel(const __half* __restrict__ qkvf, __half* __restrict__ of)
{
    extern __shared__ char fsm[];
    const uint32_t sb = smem_u32(fsm);
    const int tid = threadIdx.x, lane = tid & 31, w = tid >> 5;
    const int bh = blockIdx.x;
    const int it = 7 - blockIdx.y;
    const int b = bh >> 4, h = bh & 15;
    const int nk = 2*(it+1);
    const size_t rs = 3*DMODEL;

    {
        const size_t tok0 = (size_t)(b*SEQ + it*128);
        #pragma unroll
        for (int i = 0; i < 4; i++){
            int idx = tid + i*256;
            int r = idx >> 3, c = idx & 7;
            cp16(sb + r*144 + c*16, qkvf + (tok0 + r)*rs + h*64 + c*8);
        }
        asm volatile("cp.async.commit_group;");
    }
    #define ISSUE_KV(jt_) do {                                               \
        uint32_t st_ = sb + 18432u + (uint32_t)((jt_)&1)*18432u;             \
        const size_t tok0_ = (size_t)(b*SEQ + (jt_)*64);                     \
        _Pragma("unroll")                                                    \
        for (int i_ = 0; i_ < 2; i_++){                                      \
            int idx_ = tid + i_*256;                                         \
            int r_ = idx_ >> 3, c_ = idx_ & 7;                               \
            uint32_t sa_ = st_ + r_*144 + c_*16;                             \
            cp16(sa_,        qkvf + (tok0_ + r_)*rs + DMODEL   + h*64 + c_*8); \
            cp16(sa_ + 9216, qkvf + (tok0_ + r_)*rs + 2*DMODEL + h*64 + c_*8); \
        }                                                                    \
        asm volatile("cp.async.commit_group;");                              \
    } while(0)

    ISSUE_KV(0);
    asm volatile("cp.async.wait_group 1;");
    __syncthreads();

    uint32_t qh[4][4];
    {
        uint32_t rbase = sb + (w*16 + (lane & 15))*144 + ((lane >> 4)*8)*2;
        #pragma unroll
        for (int ks = 0; ks < 4; ks++)
            ldsm_x4(qh[ks], rbase + ks*32);
    }

    float O[8][4];
    #pragma unroll
    for (int nt = 0; nt < 8; nt++)
        #pragma unroll
        for (int c = 0; c < 4; c++) O[nt][c] = 0.f;
    float m0 = -INFINITY, m1 = -INFINITY, l0 = 0.f, l1 = 0.f;
    const int r0g = it*128 + w*16 + (lane >> 2);

    for (int jt = 0; jt < nk; jt++){
        if (jt + 1 < nk){ ISSUE_KV(jt+1); asm volatile("cp.async.wait_group 1;"); }
        else            { asm volatile("cp.async.wait_group 0;"); }
        __syncthreads();
        const uint32_t st = sb + 18432u + (uint32_t)(jt&1)*18432u;

        float S[8][4];
        #pragma unroll
        for (int nt = 0; nt < 8; nt++)
            #pragma unroll
            for (int c = 0; c < 4; c++) S[nt][c] = 0.f;

        const uint32_t kb = st + (lane & 7)*144 + (((lane >> 3) & 1)*8)*2;
        #pragma unroll
        for (int nt = 0; nt < 8; nt++){
            #pragma unroll
            for (int ks = 0; ks < 4; ks++){
                uint32_t kh[2];
                ldsm_x2(kh, kb + nt*8*144 + ks*32);
                mma_f16(S[nt], qh[ks], kh);
            }
        }

        const bool diag = (jt >= 2*it);
        float mx0 = -INFINITY, mx1 = -INFINITY;
        #pragma unroll
        for (int nt = 0; nt < 8; nt++){
            int colb = jt*64 + nt*8 + (lane & 3)*2;
            #pragma unroll
            for (int q = 0; q < 2; q++){
                float v0 = S[nt][q]   * 0.125f;
                float v1 = S[nt][2+q] * 0.125f;
                if (diag){
                    if (colb + q > r0g)     v0 = -INFINITY;
                    if (colb + q > r0g + 8) v1 = -INFINITY;
                }
                S[nt][q] = v0; S[nt][2+q] = v1;
                mx0 = fmaxf(mx0, v0); mx1 = fmaxf(mx1, v1);
            }
        }
        mx0 = fmaxf(mx0, __shfl_xor_sync(0xffffffffu, mx0, 1));
        mx0 = fmaxf(mx0, __shfl_xor_sync(0xffffffffu, mx0, 2));
        mx1 = fmaxf(mx1, __shfl_xor_sync(0xffffffffu, mx1, 1));
        mx1 = fmaxf(mx1, __shfl_xor_sync(0xffffffffu, mx1, 2));
        float mn0 = fmaxf(m0, mx0), mn1 = fmaxf(m1, mx1);
        float f0 = __expf(m0 - mn0), f1 = __expf(m1 - mn1);
        m0 = mn0; m1 = mn1;
        float ls0 = 0.f, ls1 = 0.f;
        #pragma unroll
        for (int nt = 0; nt < 8; nt++){
            #pragma unroll
            for (int q = 0; q < 2; q++){
                float e0 = __expf(S[nt][q]   - m0);
                float e1 = __expf(S[nt][2+q] - m1);
                S[nt][q] = e0; S[nt][2+q] = e1;
                ls0 += e0; ls1 += e1;
            }
        }
        l0 = l0*f0 + ls0;
        l1 = l1*f1 + ls1;
        #pragma unroll
        for (int nt = 0; nt < 8; nt++){
            O[nt][0] *= f0; O[nt][1] *= f0;
            O[nt][2] *= f1; O[nt][3] *= f1;
        }

        #pragma unroll
        for (int ks = 0; ks < 4; ks++){
            uint32_t ph[4];
            ph[0] = pack_f16_2(S[2*ks][0],   S[2*ks][1]);
            ph[1] = pack_f16_2(S[2*ks][2],   S[2*ks][3]);
            ph[2] = pack_f16_2(S[2*ks+1][0], S[2*ks+1][1]);
            ph[3] = pack_f16_2(S[2*ks+1][2], S[2*ks+1][3]);
            uint32_t vb = st + 9216u + (ks*16 + (lane & 15))*144;
            #pragma unroll
            for (int nt = 0; nt < 8; nt++){
                uint32_t vh[2];
                ldsm_x2t(vh, vb + nt*16);
                mma_f16(O[nt], ph, vh);
            }
        }
        __syncthreads();
    }

    l0 += __shfl_xor_sync(0xffffffffu, l0, 1);
    l0 += __shfl_xor_sync(0xffffffffu, l0, 2);
    l1 += __shfl_xor_sync(0xffffffffu, l1, 1);
    l1 += __shfl_xor_sync(0xffffffffu, l1, 2);
    float inv0 = 1.0f / l0, inv1 = 1.0f / l1;
    const size_t tok0 = (size_t)(b*SEQ + it*128 + w*16 + (lane >> 2));
    const int colb = h*64 + (lane & 3)*2;
    #pragma unroll
    for (int nt = 0; nt < 8; nt++){
        #pragma unroll
        for (int rh = 0; rh < 2; rh++){
            float inv = rh ? inv1 : inv0;
            float v0 = O[nt][rh*2+0] * inv;
            float v1 = O[nt][rh*2+1] * inv;
            size_t gi = (tok0 + rh*8)*DMODEL + colb + nt*8;
            *(uint32_t*)&of[gi] = pack_f16_2(v0, v1);
        }
    }
}

// ---------------- weight convert: fp32 -> fp16 ----------------
__global__ void wconv_f16_kernel(const float4* __restrict__ in,
                                 uint2* __restrict__ out, int n4){
    int i = blockIdx.x * blockDim.x + threadIdx.x;
    if (i >= n4) return;
    float4 v = in[i];
    uint2 o;
    o.x = pack_f16_2(v.x, v.y);
    o.y = pack_f16_2(v.z, v.w);
    out[i] = o;
}

// ---------------- copy x -> h ----------------
__global__ void copy_kernel(const float* __restrict__ in, float* __restrict__ out){
    int idx = blockIdx.x * blockDim.x + threadIdx.x;
    float4 v = ((const float4*)in)[idx];
    ((float4*)out)[idx] = v;
}

// ---------------- LayerNorm: single fp16 out (+ optional f32) ----------------
template<bool WF32>
__global__ void ln_kernel(const float* __restrict__ in,
                          const float* __restrict__ w,
                          const float* __restrict__ b,
                          float* __restrict__ out,
                          __half* __restrict__ outf){
    int row = blockIdx.x;
    int t   = threadIdx.x;
    const float* x = in + (size_t)row * DMODEL;
    float4 v = *(const float4*)&x[t*4];
    float s  = v.x + v.y + v.z + v.w;
    float sq = v.x*v.x + v.y*v.y + v.z*v.z + v.w*v.w;
    s  = warp_sum(s);
    sq = warp_sum(sq);
    __shared__ float sh1[8], sh2[8];
    int warp = t >> 5, lane = t & 31;
    if (lane == 0){ sh1[warp] = s; sh2[warp] = sq; }
    __syncthreads();
    float tot = 0.f, tot2 = 0.f;
    #pragma unroll
    for (int i = 0; i < 8; i++){ tot += sh1[i]; tot2 += sh2[i]; }
    float mu   = tot  * (1.0f/DMODEL);
    float var  = tot2 * (1.0f/DMODEL) - mu*mu;
    float rstd = rsqrtf(var + EPS);
    float4 wv = *(const float4*)&w[t*4];
    float4 bv = *(const float4*)&b[t*4];
    float4 ov;
    ov.x = (v.x - mu)*rstd*wv.x + bv.x;
    ov.y = (v.y - mu)*rstd*wv.y + bv.y;
    ov.z = (v.z - mu)*rstd*wv.z + bv.z;
    ov.w = (v.w - mu)*rstd*wv.w + bv.w;
    size_t base = (size_t)row*DMODEL + t*4;
    if (WF32) *(float4*)&out[base] = ov;
    uint2 H;
    H.x = pack_f16_2(ov.x, ov.y);
    H.y = pack_f16_2(ov.z, ov.w);
    *(uint2*)&outf[base] = H;
}

// ---------------- final projection ----------------
__global__ __launch_bounds__(256)
void pred_kernel(const float* __restrict__ hn, const float* __restrict__ Wp,
                 const float* __restrict__ bp, float* __restrict__ out){
    int row = blockIdx.x;
    int t = threadIdx.x;
    float local[WIN] = {0,0,0,0,0};
    const float* x = hn + (size_t)row * DMODEL;
    for (int k = t; k < DMODEL; k += 256){
        float xv = x[k];
        const float* wr = Wp + (size_t)k * WIN;
        #pragma unroll
        for (int w = 0; w < WIN; w++) local[w] = fmaf(xv, wr[w], local[w]);
    }
    __shared__ float red[WIN][256];
    #pragma unroll
    for (int w = 0; w < WIN; w++) red[w][t] = local[w];
    __syncthreads();
    for (int s = 128; s > 0; s >>= 1){
        if (t < s){
            #pragma unroll
            for (int w = 0; w < WIN; w++) red[w][t] += red[w][t + s];
        }
        __syncthreads();
    }
    if (t < WIN) out[(size_t)row * WIN + t] = red[t][0] + bp[t];
}

// ---------------- host orchestration ----------------
extern "C" void kernel_launch(void* const* d_in, const int* in_sizes, int n_in,
                              void* d_out, int out_size){
    const float* x     = (const float*)d_in[0];
    const float* Wqkv  = (const float*)d_in[1];
    const float* bqkv  = (const float*)d_in[2];
    const float* Wo    = (const float*)d_in[3];
    const float* bo    = (const float*)d_in[4];
    const float* ln1w  = (const float*)d_in[5];
    const float* ln1b  = (const float*)d_in[6];
    const float* W1    = (const float*)d_in[7];
    const float* b1    = (const float*)d_in[8];
    const float* W2    = (const float*)d_in[9];
    const float* b2    = (const float*)d_in[10];
    const float* ln2w  = (const float*)d_in[11];
    const float* ln2b  = (const float*)d_in[12];
    const float* lnfw  = (const float*)d_in[13];
    const float* lnfb  = (const float*)d_in[14];
    const float* Wp    = (const float*)d_in[15];
    const float* bp    = (const float*)d_in[16];
    float* out = (float*)d_out;

    float *g_h, *g_hn;
    __half *g_hnf, *g_qkvf, *g_of, *g_fff, *g_wf16;
    cudaGetSymbolAddress((void**)&g_h,    d_h);
    cudaGetSymbolAddress((void**)&g_hn,   d_hn);
    cudaGetSymbolAddress((void**)&g_hnf,  d_hnf);
    cudaGetSymbolAddress((void**)&g_qkvf, d_qkvf);
    cudaGetSymbolAddress((void**)&g_of,   d_of);
    cudaGetSymbolAddress((void**)&g_fff,  d_fff);
    cudaGetSymbolAddress((void**)&g_wf16, d_wf16);

    cudaFuncSetAttribute(gemm_f16<0>, cudaFuncAttributeMaxDynamicSharedMemorySize, FGEMM_SMEM);
    cudaFuncSetAttribute(gemm_f16<1>, cudaFuncAttributeMaxDynamicSharedMemorySize, FGEMM_SMEM);
    cudaFuncSetAttribute(gemm_f16<2>, cudaFuncAttributeMaxDynamicSharedMemorySize, FGEMM_SMEM);
    cudaFuncSetAttribute(gemm_g16,    cudaFuncAttributeMaxDynamicSharedMemorySize, GGEMM_SMEM);
    cudaFuncSetAttribute(flash_kernel, cudaFuncAttributeMaxDynamicSharedMemorySize, FL_SMEM);

    // weight preprocessing: everything to fp16
    wconv_f16_kernel<<<QKV_ELEMS/4/256, 256>>>((const float4*)Wqkv,
        (uint2*)(g_wf16 + WF_QKV), QKV_ELEMS/4);
    wconv_f16_kernel<<<WO_ELEMS/4/256, 256>>>((const float4*)Wo,
        (uint2*)(g_wf16 + WF_WO),  WO_ELEMS/4);
    wconv_f16_kernel<<<W1_ELEMS/4/256, 256>>>((const float4*)W1,
        (uint2*)(g_wf16 + WF_W1),  W1_ELEMS/4);
    wconv_f16_kernel<<<W2_ELEMS/4/256, 256>>>((const float4*)W2,
        (uint2*)(g_wf16 + WF_W2),  W2_ELEMS/4);

    copy_kernel<<<TOKENS*DMODEL/4/256, 256>>>(x, g_h);

    for (int l = 0; l < LAYERS; l++){
        const __half* wqkv = g_wf16 + WF_QKV + (size_t)l * DMODEL * 3*DMODEL;
        const __half* wo   = g_wf16 + WF_WO  + (size_t)l * DMODEL * DMODEL;
        const __half* w1   = g_wf16 + WF_W1  + (size_t)l * DMODEL * DFF;
        const __half* w2   = g_wf16 + WF_W2  + (size_t)l * DFF * DMODEL;
        const float* bq = bqkv + (size_t)l * 3*DMODEL;
        const float* bO = bo   + (size_t)l * DMODEL;
        const float* B1 = b1   + (size_t)l * DFF;
        const float* B2 = b2   + (size_t)l * DMODEL;

        // pre-norm attention
        ln_kernel<false><<<TOKENS, 256>>>(g_h, ln1w + l*DMODEL, ln1b + l*DMODEL,
                                          nullptr, g_hnf);
        gemm_f16<0><<<dim3(3*DMODEL/128, TOKENS/128), 256, FGEMM_SMEM>>>(
            g_hnf, wqkv, bq, nullptr, nullptr, g_qkvf, TOKENS, 3*DMODEL, DMODEL);
        flash_kernel<<<dim3(BATCH*NHEAD, SEQ/128), 256, FL_SMEM>>>(g_qkvf, g_of);
        gemm_g16<<<dim3(DMODEL/128, TOKENS/64), 256, GGEMM_SMEM>>>(
            g_of, wo, bO, g_h, g_h, TOKENS, DMODEL, DMODEL);

        // pre-norm FFN
        ln_kernel<false><<<TOKENS, 256>>>(g_h, ln2w + l*DMODEL, ln2b + l*DMODEL,
                                          nullptr, g_hnf);
        gemm_f16<2><<<dim3(DFF/128, TOKENS/128), 256, FGEMM_SMEM>>>(
            g_hnf, w1, B1, nullptr, nullptr, g_fff, TOKENS, DFF, DMODEL);
        gemm_g16<<<dim3(DMODEL/128, TOKENS/64), 256, GGEMM_SMEM>>>(
            g_fff, w2, B2, g_h, g_h, TOKENS, DMODEL, DFF);
    }

    // final LN + projection
    ln_kernel<true><<<TOKENS, 256>>>(g_h, lnfw, lnfb, g_hn, g_hnf);
    pred_kernel<<<TOKENS, 256>>>(g_hn, Wp, bp, out);
    (void)in_sizes; (void)n_in; (void)out_size;
}

// round 13
// speedup vs baseline: 2.2530x; 1.0426x over previous
#include <cuda_runtime.h>
#include <cuda_bf16.h>
#include <cuda_fp16.h>
#include <math.h>
#include <stdint.h>

// ---------------- problem constants ----------------
#define LAYERS 6
#define BATCH  2
#define SEQ    1024
#define DMODEL 1024
#define NHEAD  16
#define HDIM   64
#define DFF    4096
#define WIN    5
#define TOKENS (BATCH*SEQ)          // 2048
#define EPS    1e-5f

// fp16 weight scratch layout (elements)
#define QKV_ELEMS  (LAYERS*DMODEL*3*DMODEL)
#define WO_ELEMS   (LAYERS*DMODEL*DMODEL)
#define W1_ELEMS   (LAYERS*DMODEL*DFF)
#define W2_ELEMS   (LAYERS*DFF*DMODEL)
#define WF_QKV 0
#define WF_WO  (QKV_ELEMS)
#define WF_W1  (WF_WO + WO_ELEMS)
#define WF_W2  (WF_W1 + W1_ELEMS)
#define WF_TOT (WF_W2 + W2_ELEMS)

// ---------------- device scratch (no allocation allowed) ----------------
__device__ float d_h   [TOKENS*DMODEL];
__device__ __half d_hnf [TOKENS*DMODEL];
__device__ __half d_qkvf[TOKENS*3*DMODEL];
__device__ __half d_of  [TOKENS*DMODEL];
__device__ __half d_fff [TOKENS*DFF];
__device__ __half d_wf16[WF_TOT];

// ---------------- small helpers ----------------
__device__ __forceinline__ float warp_sum(float v){
    #pragma unroll
    for (int o = 16; o; o >>= 1) v += __shfl_xor_sync(0xffffffffu, v, o);
    return v;
}
__device__ __forceinline__ float gelu_exact(float x){
    return 0.5f * x * (1.0f + erff(x * 0.70710678118654752440f));
}
__device__ __forceinline__ uint32_t smem_u32(const void* p){
    uint32_t a;
    asm("{ .reg .u64 t; cvta.to.shared.u64 t, %1; cvt.u32.u64 %0, t; }" : "=r"(a) : "l"(p));
    return a;
}
__device__ __forceinline__ uint32_t pack_f16_2(float x, float y){
    __half2 h = __floats2half2_rn(x, y);
    return *reinterpret_cast<uint32_t*>(&h);
}

// ---------------- mma.sync / ldmatrix / cp.async wrappers ----------------
__device__ __forceinline__ void mma_f16(float* d, const uint32_t* a, const uint32_t* b){
    asm volatile(
      "mma.sync.aligned.m16n8k16.row.col.f32.f16.f16.f32 "
      "{%0,%1,%2,%3}, {%4,%5,%6,%7}, {%8,%9}, {%0,%1,%2,%3};\n"
      : "+f"(d[0]), "+f"(d[1]), "+f"(d[2]), "+f"(d[3])
      : "r"(a[0]), "r"(a[1]), "r"(a[2]), "r"(a[3]), "r"(b[0]), "r"(b[1]));
}
__device__ __forceinline__ void ldsm_x4(uint32_t* r, uint32_t addr){
    asm volatile("ldmatrix.sync.aligned.m8n8.x4.shared.b16 {%0,%1,%2,%3}, [%4];"
      : "=r"(r[0]), "=r"(r[1]), "=r"(r[2]), "=r"(r[3]) : "r"(addr));
}
__device__ __forceinline__ void ldsm_x2(uint32_t* r, uint32_t addr){
    asm volatile("ldmatrix.sync.aligned.m8n8.x2.shared.b16 {%0,%1}, [%2];"
      : "=r"(r[0]), "=r"(r[1]) : "r"(addr));
}
__device__ __forceinline__ void ldsm_x2t(uint32_t* r, uint32_t addr){
    asm volatile("ldmatrix.sync.aligned.m8n8.x2.trans.shared.b16 {%0,%1}, [%2];"
      : "=r"(r[0]), "=r"(r[1]) : "r"(addr));
}
__device__ __forceinline__ void cp16(uint32_t s, const void* g){
    asm volatile("cp.async.cg.shared.global [%0], [%1], 16;\n" :: "r"(s), "l"(g));
}

// ---------------- fp16 GEMM smem layouts (KC=64, 3 stages) ----------------
#define KC       64
#define A_STRIDE 144          // 64 fp16 = 128B + 16B pad
#define B_STRIDE 272          // 128 fp16 = 256B + 16B pad
// 128x128 tile
#define F_B_OFF  18432
#define F_STAGE  35840        // 18432 + 64*272
#define FGEMM_SMEM (3*F_STAGE)    // 107520; x2 CTAs = 215040 <= 228KB
// 64x128 tile
#define G_B_OFF  9216
#define G_STAGE  26624
#define GGEMM_SMEM (3*G_STAGE)    // 79872

__device__ __forceinline__ void issue_stage_f16(
    const __half* __restrict__ A, const __half* __restrict__ B,
    uint32_t sb0, int tid, int m0, int n0, int K, int N, int c)
{
    uint32_t sb = sb0 + (uint32_t)(c % 3) * F_STAGE;
    int k0 = c * KC;
    #pragma unroll
    for (int i = 0; i < 4; i++){
        int idx = tid + i*256;               // A: 128 rows x 8 chunks
        int r = idx >> 3, cc = idx & 7;
        cp16(sb + r*A_STRIDE + cc*16, A + (size_t)(m0 + r) * K + k0 + cc*8);
    }
    #pragma unroll
    for (int i = 0; i < 4; i++){
        int idx = tid + i*256;               // B: 64 rows x 16 chunks
        int r = idx >> 4, cc = idx & 15;
        cp16(sb + F_B_OFF + r*B_STRIDE + cc*16, B + (size_t)(k0 + r) * N + n0 + cc*8);
    }
    asm volatile("cp.async.commit_group;");
}

__device__ __forceinline__ void issue_stage_g16(
    const __half* __restrict__ A, const __half* __restrict__ B,
    uint32_t sb0, int tid, int m0, int n0, int K, int N, int c)
{
    uint32_t sb = sb0 + (uint32_t)(c % 3) * G_STAGE;
    int k0 = c * KC;
    #pragma unroll
    for (int i = 0; i < 2; i++){
        int idx = tid + i*256;               // A: 64 rows x 8 chunks
        int r = idx >> 3, cc = idx & 7;
        cp16(sb + r*A_STRIDE + cc*16, A + (size_t)(m0 + r) * K + k0 + cc*8);
    }
    #pragma unroll
    for (int i = 0; i < 4; i++){
        int idx = tid + i*256;               // B: 64 rows x 16 chunks
        int r = idx >> 4, cc = idx & 15;
        cp16(sb + G_B_OFF + r*B_STRIDE + cc*16, B + (size_t)(k0 + r) * N + n0 + cc*8);
    }
    asm volatile("cp.async.commit_group;");
}

// =====================================================================
// fp16 1-pass GEMM, 128x128 tile: C = epi(A @ B + bias)
// EPI: 0 = bias -> fp16   1 = bias+residual (f32)   2 = bias+GELU -> fp16
// =====================================================================
template<int EPI>
__global__ __launch_bounds__(256, 2)
void gemm_f16(const __half* __restrict__ A, const __half* __restrict__ B,
              const float* __restrict__ bias, const float* __restrict__ res,
              float* __restrict__ C, __half* __restrict__ Cf,
              int M, int N, int K)
{
    extern __shared__ char smem[];
    const uint32_t sb0 = smem_u32(smem);
    const int tid  = threadIdx.x;
    const int lane = tid & 31, wid = tid >> 5;
    const int m0 = blockIdx.y * 128, n0 = blockIdx.x * 128;
    const int wm = (wid >> 2) * 64, wn = (wid & 3) * 32;

    float acc[4][4][4];
    #pragma unroll
    for (int a = 0; a < 4; a++)
        #pragma unroll
        for (int b = 0; b < 4; b++)
            #pragma unroll
            for (int cc = 0; cc < 4; cc++) acc[a][b][cc] = 0.f;

    const int nch = K / KC;
    issue_stage_f16(A, B, sb0, tid, m0, n0, K, N, 0);
    issue_stage_f16(A, B, sb0, tid, m0, n0, K, N, 1);

    const uint32_t a_lrow = wm + (lane & 15);
    const uint32_t a_lcol = (lane >> 4) * 8;
    const uint32_t b_lrow = (lane & 15);

    for (int c = 0; c < nch; c++){
        asm volatile("cp.async.wait_group %0;" :: "n"(1));
        __syncthreads();
        if (c + 2 < nch) issue_stage_f16(A, B, sb0, tid, m0, n0, K, N, c + 2);
        else asm volatile("cp.async.commit_group;");

        uint32_t sb = sb0 + (uint32_t)(c % 3) * F_STAGE;
        #pragma unroll
        for (int ks = 0; ks < 4; ks++){
            uint32_t ah[4][4], bb[4][2];
            #pragma unroll
            for (int mt = 0; mt < 4; mt++)
                ldsm_x4(ah[mt], sb + (a_lrow + mt*16)*A_STRIDE + (ks*16 + a_lcol)*2);
            #pragma unroll
            for (int nt = 0; nt < 4; nt++)
                ldsm_x2t(bb[nt], sb + F_B_OFF + (ks*16 + b_lrow)*B_STRIDE + (wn + nt*8)*2);
            #pragma unroll
            for (int mt = 0; mt < 4; mt++)
                #pragma unroll
                for (int nt = 0; nt < 4; nt++)
                    mma_f16(acc[mt][nt], ah[mt], bb[nt]);
        }
    }

    const int g  = lane >> 2;
    const int tq = (lane & 3) * 2;
    #pragma unroll
    for (int mt = 0; mt < 4; mt++){
        #pragma unroll
        for (int half = 0; half < 2; half++){
            int m = m0 + wm + mt*16 + g + half*8;
            #pragma unroll
            for (int nt = 0; nt < 4; nt++){
                int n = n0 + wn + nt*8 + tq;
                float v0 = acc[mt][nt][half*2+0] + bias[n];
                float v1 = acc[mt][nt][half*2+1] + bias[n+1];
                size_t gi = (size_t)m * N + n;
                if (EPI == 1){
                    v0 += res[gi]; v1 += res[gi+1];
                    float2 o; o.x = v0; o.y = v1;
                    *(float2*)&C[gi] = o;
                } else {
                    if (EPI == 2){ v0 = gelu_exact(v0); v1 = gelu_exact(v1); }
                    *(uint32_t*)&Cf[gi] = pack_f16_2(v0, v1);
                }
            }
        }
    }
}

// =====================================================================
// fp16 1-pass GEMM, 64x128 tile: bias + residual, f32 out.
// =====================================================================
__global__ __launch_bounds__(256, 2)
void gemm_g16(const __half* __restrict__ A, const __half* __restrict__ B,
              const float* __restrict__ bias, const float* __restrict__ res,
              float* __restrict__ C, int M, int N, int K)
{
    extern __shared__ char smem[];
    const uint32_t sb0 = smem_u32(smem);
    const int tid  = threadIdx.x;
    const int lane = tid & 31, wid = tid >> 5;
    const int m0 = blockIdx.y * 64, n0 = blockIdx.x * 128;
    const int wm = (wid >> 2) * 32, wn = (wid & 3) * 32;

    float acc[2][4][4];
    #pragma unroll
    for (int a = 0; a < 2; a++)
        #pragma unroll
        for (int b = 0; b < 4; b++)
            #pragma unroll
            for (int cc = 0; cc < 4; cc++) acc[a][b][cc] = 0.f;

    const int nch = K / KC;
    issue_stage_g16(A, B, sb0, tid, m0, n0, K, N, 0);
    issue_stage_g16(A, B, sb0, tid, m0, n0, K, N, 1);

    const uint32_t a_lrow = wm + (lane & 15);
    const uint32_t a_lcol = (lane >> 4) * 8;
    const uint32_t b_lrow = (lane & 15);

    for (int c = 0; c < nch; c++){
        asm volatile("cp.async.wait_group %0;" :: "n"(1));
        __syncthreads();
        if (c + 2 < nch) issue_stage_g16(A, B, sb0, tid, m0, n0, K, N, c + 2);
        else asm volatile("cp.async.commit_group;");

        uint32_t sb = sb0 + (uint32_t)(c % 3) * G_STAGE;
        #pragma unroll
        for (int ks = 0; ks < 4; ks++){
            uint32_t ah[2][4], bb[4][2];
            #pragma unroll
            for (int mt = 0; mt < 2; mt++)
                ldsm_x4(ah[mt], sb + (a_lrow + mt*16)*A_STRIDE + (ks*16 + a_lcol)*2);
            #pragma unroll
            for (int nt = 0; nt < 4; nt++)
                ldsm_x2t(bb[nt], sb + G_B_OFF + (ks*16 + b_lrow)*B_STRIDE + (wn + nt*8)*2);
            #pragma unroll
            for (int mt = 0; mt < 2; mt++)
                #pragma unroll
                for (int nt = 0; nt < 4; nt++)
                    mma_f16(acc[mt][nt], ah[mt], bb[nt]);
        }
    }

    const int g  = lane >> 2;
    const int tq = (lane & 3) * 2;
    #pragma unroll
    for (int mt = 0; mt < 2; mt++){
        #pragma unroll
        for (int half = 0; half < 2; half++){
            int m = m0 + wm + mt*16 + g + half*8;
            #pragma unroll
            for (int nt = 0; nt < 4; nt++){
                int n = n0 + wn + nt*8 + tq;
                float v0 = acc[mt][nt][half*2+0] + bias[n];
                float v1 = acc[mt][nt][half*2+1] + bias[n+1];
                size_t gi = (size_t)m * N + n;
                v0 += res[gi]; v1 += res[gi+1];
                float2 o; o.x = v0; o.y = v1;
                *(float2*)&C[gi] = o;
            }
        }
    }
}

// =====================================================================
// Flash attention, single fp16, causal.  Bq=128 (8 warps x 16 rows), Bc=64.
// =====================================================================
#define FL_SMEM 55296

__global__ __launch_bounds__(256)
void flash_kernel(const __half* __restrict__ qkvf, __half* __restrict__ of)
{
    extern __shared__ char fsm[];
    const uint32_t sb = smem_u32(fsm);
    const int tid = threadIdx.x, lane = tid & 31, w = tid >> 5;
    const int bh = blockIdx.x;
    const int it = 7 - blockIdx.y;
    const int b = bh >> 4, h = bh & 15;
    const int nk = 2*(it+1);
    const size_t rs = 3*DMODEL;

    {
        const size_t tok0 = (size_t)(b*SEQ + it*128);
        #pragma unroll
        for (int i = 0; i < 4; i++){
            int idx = tid + i*256;
            int r = idx >> 3, c = idx & 7;
            cp16(sb + r*144 + c*16, qkvf + (tok0 + r)*rs + h*64 + c*8);
        }
        asm volatile("cp.async.commit_group;");
    }
    #define ISSUE_KV(jt_) do {                                               \
        uint32_t st_ = sb + 18432u + (uint32_t)((jt_)&1)*18432u;             \
        const size_t tok0_ = (size_t)(b*SEQ + (jt_)*64);                     \
        _Pragma("unroll")                                                    \
        for (int i_ = 0; i_ < 2; i_++){                                      \
            int idx_ = tid + i_*256;                                         \
            int r_ = idx_ >> 3, c_ = idx_ & 7;                               \
            uint32_t sa_ = st_ + r_*144 + c_*16;                             \
            cp16(sa_,        qkvf + (tok0_ + r_)*rs + DMODEL   + h*64 + c_*8); \
            cp16(sa_ + 9216, qkvf + (tok0_ + r_)*rs + 2*DMODEL + h*64 + c_*8); \
        }                                                                    \
        asm volatile("cp.async.commit_group;");                              \
    } while(0)

    ISSUE_KV(0);
    asm volatile("cp.async.wait_group 1;");
    __syncthreads();

    uint32_t qh[4][4];
    {
        uint32_t rbase = sb + (w*16 + (lane & 15))*144 + ((lane >> 4)*8)*2;
        #pragma unroll
        for (int ks = 0; ks < 4; ks++)
            ldsm_x4(qh[ks], rbase + ks*32);
    }

    float O[8][4];
    #pragma unroll
    for (int nt = 0; nt < 8; nt++)
        #pragma unroll
        for (int c = 0; c < 4; c++) O[nt][c] = 0.f;
    float m0 = -INFINITY, m1 = -INFINITY, l0 = 0.f, l1 = 0.f;
    const int r0g = it*128 + w*16 + (lane >> 2);

    for (int jt = 0; jt < nk; jt++){
        if (jt + 1 < nk){ ISSUE_KV(jt+1); asm volatile("cp.async.wait_group 1;"); }
        else            { asm volatile("cp.async.wait_group 0;"); }
        __syncthreads();
        const uint32_t st = sb + 18432u + (uint32_t)(jt&1)*18432u;

        float S[8][4];
        #pragma unroll
        for (int nt = 0; nt < 8; nt++)
            #pragma unroll
            for (int c = 0; c < 4; c++) S[nt][c] = 0.f;

        const uint32_t kb = st + (lane & 7)*144 + (((lane >> 3) & 1)*8)*2;
        #pragma unroll
        for (int nt = 0; nt < 8; nt++){
            #pragma unroll
            for (int ks = 0; ks < 4; ks++){
                uint32_t kh[2];
                ldsm_x2(kh, kb + nt*8*144 + ks*32);
                mma_f16(S[nt], qh[ks], kh);
            }
        }

        const bool diag = (jt >= 2*it);
        float mx0 = -INFINITY, mx1 = -INFINITY;
        #pragma unroll
        for (int nt = 0; nt < 8; nt++){
            int colb = jt*64 + nt*8 + (lane & 3)*2;
            #pragma unroll
            for (int q = 0; q < 2; q++){
                float v0 = S[nt][q]   * 0.125f;
                float v1 = S[nt][2+q] * 0.125f;
                if (diag){
                    if (colb + q > r0g)     v0 = -INFINITY;
                    if (colb + q > r0g + 8) v1 = -INFINITY;
                }
                S[nt][q] = v0; S[nt][2+q] = v1;
                mx0 = fmaxf(mx0, v0); mx1 = fmaxf(mx1, v1);
            }
        }
        mx0 = fmaxf(mx0, __shfl_xor_sync(0xffffffffu, mx0, 1));
        mx0 = fmaxf(mx0, __shfl_xor_sync(0xffffffffu, mx0, 2));
        mx1 = fmaxf(mx1, __shfl_xor_sync(0xffffffffu, mx1, 1));
        mx1 = fmaxf(mx1, __shfl_xor_sync(0xffffffffu, mx1, 2));
        float mn0 = fmaxf(m0, mx0), mn1 = fmaxf(m1, mx1);
        float f0 = __expf(m0 - mn0), f1 = __expf(m1 - mn1);
        m0 = mn0; m1 = mn1;
        float ls0 = 0.f, ls1 = 0.f;
        #pragma unroll
        for (int nt = 0; nt < 8; nt++){
            #pragma unroll
            for (int q = 0; q < 2; q++){
                float e0 = __expf(S[nt][q]   - m0);
                float e1 = __expf(S[nt][2+q] - m1);
                S[nt][q] = e0; S[nt][2+q] = e1;
                ls0 += e0; ls1 += e1;
            }
        }
        l0 = l0*f0 + ls0;
        l1 = l1*f1 + ls1;
        #pragma unroll
        for (int nt = 0; nt < 8; nt++){
            O[nt][0] *= f0; O[nt][1] *= f0;
            O[nt][2] *= f1; O[nt][3] *= f1;
        }

        #pragma unroll
        for (int ks = 0; ks < 4; ks++){
            uint32_t ph[4];
            ph[0] = pack_f16_2(S[2*ks][0],   S[2*ks][1]);
            ph[1] = pack_f16_2(S[2*ks][2],   S[2*ks][3]);
            ph[2] = pack_f16_2(S[2*ks+1][0], S[2*ks+1][1]);
            ph[3] = pack_f16_2(S[2*ks+1][2], S[2*ks+1][3]);
            uint32_t vb = st + 9216u + (ks*16 + (lane & 15))*144;
            #pragma unroll
            for (int nt = 0; nt < 8; nt++){
                uint32_t vh[2];
                ldsm_x2t(vh, vb + nt*16);
                mma_f16(O[nt], ph, vh);
            }
        }
        __syncthreads();
    }

    l0 += __shfl_xor_sync(0xffffffffu, l0, 1);
    l0 += __shfl_xor_sync(0xffffffffu, l0, 2);
    l1 += __shfl_xor_sync(0xffffffffu, l1, 1);
    l1 += __shfl_xor_sync(0xffffffffu, l1, 2);
    float inv0 = 1.0f / l0, inv1 = 1.0f / l1;
    const size_t tok0 = (size_t)(b*SEQ + it*128 + w*16 + (lane >> 2));
    const int colb = h*64 + (lane & 3)*2;
    #pragma unroll
    for (int nt = 0; nt < 8; nt++){
        #pragma unroll
        for (int rh = 0; rh < 2; rh++){
            float inv = rh ? inv1 : inv0;
            float v0 = O[nt][rh*2+0] * inv;
            float v1 = O[nt][rh*2+1] * inv;
            size_t gi = (tok0 + rh*8)*DMODEL + colb + nt*8;
            *(uint32_t*)&of[gi] = pack_f16_2(v0, v1);
        }
    }
}

// ---------------- merged weight convert: fp32 -> fp16 (all 4 tensors) ----------------
__global__ void wconv_all_kernel(const float4* __restrict__ Wqkv,
                                 const float4* __restrict__ Wo,
                                 const float4* __restrict__ W1,
                                 const float4* __restrict__ W2,
                                 uint2* __restrict__ out){
    int i = blockIdx.x * blockDim.x + threadIdx.x;   // float4 index over WF_TOT/4
    if (i >= WF_TOT/4) return;
    const float4* src;
    int off;
    if (i < WF_WO/4){ src = Wqkv; off = i; }
    else if (i < WF_W1/4){ src = Wo; off = i - WF_WO/4; }
    else if (i < WF_W2/4){ src = W1; off = i - WF_W1/4; }
    else { src = W2; off = i - WF_W2/4; }
    float4 v = src[off];
    uint2 o;
    o.x = pack_f16_2(v.x, v.y);
    o.y = pack_f16_2(v.z, v.w);
    out[i] = o;
}

// ---------------- LayerNorm: single fp16 out ----------------
__global__ void ln_kernel(const float* __restrict__ in,
                          const float* __restrict__ w,
                          const float* __restrict__ b,
                          __half* __restrict__ outf){
    int row = blockIdx.x;
    int t   = threadIdx.x;
    const float* x = in + (size_t)row * DMODEL;
    float4 v = *(const float4*)&x[t*4];
    float s  = v.x + v.y + v.z + v.w;
    float sq = v.x*v.x + v.y*v.y + v.z*v.z + v.w*v.w;
    s  = warp_sum(s);
    sq = warp_sum(sq);
    __shared__ float sh1[8], sh2[8];
    int warp = t >> 5, lane = t & 31;
    if (lane == 0){ sh1[warp] = s; sh2[warp] = sq; }
    __syncthreads();
    float tot = 0.f, tot2 = 0.f;
    #pragma unroll
    for (int i = 0; i < 8; i++){ tot += sh1[i]; tot2 += sh2[i]; }
    float mu   = tot  * (1.0f/DMODEL);
    float var  = tot2 * (1.0f/DMODEL) - mu*mu;
    float rstd = rsqrtf(var + EPS);
    float4 wv = *(const float4*)&w[t*4];
    float4 bv = *(const float4*)&b[t*4];
    float4 ov;
    ov.x = (v.x - mu)*rstd*wv.x + bv.x;
    ov.y = (v.y - mu)*rstd*wv.y + bv.y;
    ov.z = (v.z - mu)*rstd*wv.z + bv.z;
    ov.w = (v.w - mu)*rstd*wv.w + bv.w;
    size_t base = (size_t)row*DMODEL + t*4;
    uint2 H;
    H.x = pack_f16_2(ov.x, ov.y);
    H.y = pack_f16_2(ov.z, ov.w);
    *(uint2*)&outf[base] = H;
}

// ---------------- fused final LayerNorm + projection ----------------
__global__ __launch_bounds__(256)
void lnpred_kernel(const float* __restrict__ in,
                   const float* __restrict__ w,
                   const float* __restrict__ b,
                   const float* __restrict__ Wp,
                   const float* __restrict__ bp,
                   float* __restrict__ out){
    int row = blockIdx.x;
    int t   = threadIdx.x;
    const float* x = in + (size_t)row * DMODEL;
    float4 v = *(const float4*)&x[t*4];
    float s  = v.x + v.y + v.z + v.w;
    float sq = v.x*v.x + v.y*v.y + v.z*v.z + v.w*v.w;
    s  = warp_sum(s);
    sq = warp_sum(sq);
    __shared__ float sh1[8], sh2[8];
    int warp = t >> 5, lane = t & 31;
    if (lane == 0){ sh1[warp] = s; sh2[warp] = sq; }
    __syncthreads();
    float tot = 0.f, tot2 = 0.f;
    #pragma unroll
    for (int i = 0; i < 8; i++){ tot += sh1[i]; tot2 += sh2[i]; }
    float mu   = tot  * (1.0f/DMODEL);
    float var  = tot2 * (1.0f/DMODEL) - mu*mu;
    float rstd = rsqrtf(var + EPS);
    float4 wv = *(const float4*)&w[t*4];
    float4 bv = *(const float4*)&b[t*4];
    float4 ov;
    ov.x = (v.x - mu)*rstd*wv.x + bv.x;
    ov.y = (v.y - mu)*rstd*wv.y + bv.y;
    ov.z = (v.z - mu)*rstd*wv.z + bv.z;
    ov.w = (v.w - mu)*rstd*wv.w + bv.w;

    // projection: each thread handles 4 k indices
    float local[WIN];
    {
        const float* w0 = Wp + (size_t)(t*4) * WIN;
        #pragma unroll
        for (int p = 0; p < WIN; p++)
            local[p] = ov.x*w0[p] + ov.y*w0[WIN+p] + ov.z*w0[2*WIN+p] + ov.w*w0[3*WIN+p];
    }
    __shared__ float red[WIN][256];
    #pragma unroll
    for (int p = 0; p < WIN; p++) red[p][t] = local[p];
    __syncthreads();
    for (int sHalf = 128; sHalf > 0; sHalf >>= 1){
        if (t < sHalf){
            #pragma unroll
            for (int p = 0; p < WIN; p++) red[p][t] += red[p][t + sHalf];
        }
        __syncthreads();
    }
    if (t < WIN) out[(size_t)row * WIN + t] = red[t][0] + bp[t];
}

// ---------------- host orchestration ----------------
extern "C" void kernel_launch(void* const* d_in, const int* in_sizes, int n_in,
                              void* d_out, int out_size){
    const float* x     = (const float*)d_in[0];
    const float* Wqkv  = (const float*)d_in[1];
    const float* bqkv  = (const float*)d_in[2];
    const float* Wo    = (const float*)d_in[3];
    const float* bo    = (const float*)d_in[4];
    const float* ln1w  = (const float*)d_in[5];
    const float* ln1b  = (const float*)d_in[6];
    const float* W1    = (const float*)d_in[7];
    const float* b1    = (const float*)d_in[8];
    const float* W2    = (const float*)d_in[9];
    const float* b2    = (const float*)d_in[10];
    const float* ln2w  = (const float*)d_in[11];
    const float* ln2b  = (const float*)d_in[12];
    const float* lnfw  = (const float*)d_in[13];
    const float* lnfb  = (const float*)d_in[14];
    const float* Wp    = (const float*)d_in[15];
    const float* bp    = (const float*)d_in[16];
    float* out = (float*)d_out;

    float *g_h;
    __half *g_hnf, *g_qkvf, *g_of, *g_fff, *g_wf16;
    cudaGetSymbolAddress((void**)&g_h,    d_h);
    cudaGetSymbolAddress((void**)&g_hnf,  d_hnf);
    cudaGetSymbolAddress((void**)&g_qkvf, d_qkvf);
    cudaGetSymbolAddress((void**)&g_of,   d_of);
    cudaGetSymbolAddress((void**)&g_fff,  d_fff);
    cudaGetSymbolAddress((void**)&g_wf16, d_wf16);

    cudaFuncSetAttribute(gemm_f16<0>, cudaFuncAttributeMaxDynamicSharedMemorySize, FGEMM_SMEM);
    cudaFuncSetAttribute(gemm_f16<2>, cudaFuncAttributeMaxDynamicSharedMemorySize, FGEMM_SMEM);
    cudaFuncSetAttribute(gemm_g16,    cudaFuncAttributeMaxDynamicSharedMemorySize, GGEMM_SMEM);
    cudaFuncSetAttribute(flash_kernel, cudaFuncAttributeMaxDynamicSharedMemorySize, FL_SMEM);

    // one merged weight-conversion launch
    wconv_all_kernel<<<(WF_TOT/4 + 255)/256, 256>>>(
        (const float4*)Wqkv, (const float4*)Wo, (const float4*)W1, (const float4*)W2,
        (uint2*)g_wf16);

    for (int l = 0; l < LAYERS; l++){
        const __half* wqkv = g_wf16 + WF_QKV + (size_t)l * DMODEL * 3*DMODEL;
        const __half* wo   = g_wf16 + WF_WO  + (size_t)l * DMODEL * DMODEL;
        const __half* w1   = g_wf16 + WF_W1  + (size_t)l * DMODEL * DFF;
        const __half* w2   = g_wf16 + WF_W2  + (size_t)l * DFF * DMODEL;
        const float* bq = bqkv + (size_t)l * 3*DMODEL;
        const float* bO = bo   + (size_t)l * DMODEL;
        const float* B1 = b1   + (size_t)l * DFF;
        const float* B2 = b2   + (size_t)l * DMODEL;
        const float* hin = (l == 0) ? x : g_h;   // layer-0 reads input directly

        // pre-norm attention
        ln_kernel<<<TOKENS, 256>>>(hin, ln1w + l*DMODEL, ln1b + l*DMODEL, g_hnf);
        gemm_f16<0><<<dim3(3*DMODEL/128, TOKENS/128), 256, FGEMM_SMEM>>>(
            g_hnf, wqkv, bq, nullptr, nullptr, g_qkvf, TOKENS, 3*DMODEL, DMODEL);
        flash_kernel<<<dim3(BATCH*NHEAD, SEQ/128), 256, FL_SMEM>>>(g_qkvf, g_of);
        gemm_g16<<<dim3(DMODEL/128, TOKENS/64), 256, GGEMM_SMEM>>>(
            g_of, wo, bO, hin, g_h, TOKENS, DMODEL, DMODEL);

        // pre-norm FFN
        ln_kernel<<<TOKENS, 256>>>(g_h, ln2w + l*DMODEL, ln2b + l*DMODEL, g_hnf);
        gemm_f16<2><<<dim3(DFF/128, TOKENS/128), 256, FGEMM_SMEM>>>(
            g_hnf, w1, B1, nullptr, nullptr, g_fff, TOKENS, DFF, DMODEL);
        gemm_g16<<<dim3(DMODEL/128, TOKENS/64), 256, GGEMM_SMEM>>>(
            g_fff, w2, B2, g_h, g_h, TOKENS, DMODEL, DFF);
    }

    // fused final LN + projection
    lnpred_kernel<<<TOKENS, 256>>>(g_h, lnfw, lnfb, Wp, bp, out);
    (void)in_sizes; (void)n_in; (void)out_size;
}

// round 14
// speedup vs baseline: 2.2672x; 1.0063x over previous
#include <cuda_runtime.h>
#include <cuda_bf16.h>
#include <cuda_fp16.h>
#include <math.h>
#include <stdint.h>

// ---------------- problem constants ----------------
#define LAYERS 6
#define BATCH  2
#define SEQ    1024
#define DMODEL 1024
#define NHEAD  16
#define HDIM   64
#define DFF    4096
#define WIN    5
#define TOKENS (BATCH*SEQ)          // 2048
#define EPS    1e-5f

// fp16 weight scratch layout (elements)
#define QKV_ELEMS  (LAYERS*DMODEL*3*DMODEL)
#define WO_ELEMS   (LAYERS*DMODEL*DMODEL)
#define W1_ELEMS   (LAYERS*DMODEL*DFF)
#define W2_ELEMS   (LAYERS*DFF*DMODEL)
#define WF_QKV 0
#define WF_WO  (QKV_ELEMS)
#define WF_W1  (WF_WO + WO_ELEMS)
#define WF_W2  (WF_W1 + W1_ELEMS)
#define WF_TOT (WF_W2 + W2_ELEMS)

// ---------------- device scratch (no allocation allowed) ----------------
__device__ float d_h   [TOKENS*DMODEL];
__device__ __half d_hnf [TOKENS*DMODEL];
__device__ __half d_qkvf[TOKENS*3*DMODEL];
__device__ __half d_of  [TOKENS*DMODEL];
__device__ __half d_fff [TOKENS*DFF];
__device__ __half d_wf16[WF_TOT];

// ---------------- small helpers ----------------
__device__ __forceinline__ float warp_sum(float v){
    #pragma unroll
    for (int o = 16; o; o >>= 1) v += __shfl_xor_sync(0xffffffffu, v, o);
    return v;
}
__device__ __forceinline__ float gelu_exact(float x){
    return 0.5f * x * (1.0f + erff(x * 0.70710678118654752440f));
}
__device__ __forceinline__ uint32_t smem_u32(const void* p){
    uint32_t a;
    asm("{ .reg .u64 t; cvta.to.shared.u64 t, %1; cvt.u32.u64 %0, t; }" : "=r"(a) : "l"(p));
    return a;
}
__device__ __forceinline__ uint32_t pack_f16_2(float x, float y){
    __half2 h = __floats2half2_rn(x, y);
    return *reinterpret_cast<uint32_t*>(&h);
}

// ---------------- mma.sync / ldmatrix / cp.async wrappers ----------------
__device__ __forceinline__ void mma_f16(float* d, const uint32_t* a, const uint32_t* b){
    asm volatile(
      "mma.sync.aligned.m16n8k16.row.col.f32.f16.f16.f32 "
      "{%0,%1,%2,%3}, {%4,%5,%6,%7}, {%8,%9}, {%0,%1,%2,%3};\n"
      : "+f"(d[0]), "+f"(d[1]), "+f"(d[2]), "+f"(d[3])
      : "r"(a[0]), "r"(a[1]), "r"(a[2]), "r"(a[3]), "r"(b[0]), "r"(b[1]));
}
__device__ __forceinline__ void ldsm_x4(uint32_t* r, uint32_t addr){
    asm volatile("ldmatrix.sync.aligned.m8n8.x4.shared.b16 {%0,%1,%2,%3}, [%4];"
      : "=r"(r[0]), "=r"(r[1]), "=r"(r[2]), "=r"(r[3]) : "r"(addr));
}
__device__ __forceinline__ void ldsm_x2(uint32_t* r, uint32_t addr){
    asm volatile("ldmatrix.sync.aligned.m8n8.x2.shared.b16 {%0,%1}, [%2];"
      : "=r"(r[0]), "=r"(r[1]) : "r"(addr));
}
__device__ __forceinline__ void ldsm_x2t(uint32_t* r, uint32_t addr){
    asm volatile("ldmatrix.sync.aligned.m8n8.x2.trans.shared.b16 {%0,%1}, [%2];"
      : "=r"(r[0]), "=r"(r[1]) : "r"(addr));
}
__device__ __forceinline__ void cp16(uint32_t s, const void* g){
    asm volatile("cp.async.cg.shared.global [%0], [%1], 16;\n" :: "r"(s), "l"(g));
}

// ---------------- fp16 GEMM smem layouts (KC=64, 3 stages) ----------------
#define KC       64
#define A_STRIDE 144
#define B_STRIDE 272
// 128x128 tile
#define F_B_OFF  18432
#define F_STAGE  35840
#define FGEMM_SMEM (3*F_STAGE)
// 64x128 tile
#define G_B_OFF  9216
#define G_STAGE  26624
#define GGEMM_SMEM (3*G_STAGE)

__device__ __forceinline__ void issue_stage_f16(
    const __half* __restrict__ A, const __half* __restrict__ B,
    uint32_t sb0, int tid, int m0, int n0, int K, int N, int c)
{
    uint32_t sb = sb0 + (uint32_t)(c % 3) * F_STAGE;
    int k0 = c * KC;
    #pragma unroll
    for (int i = 0; i < 4; i++){
        int idx = tid + i*256;
        int r = idx >> 3, cc = idx & 7;
        cp16(sb + r*A_STRIDE + cc*16, A + (size_t)(m0 + r) * K + k0 + cc*8);
    }
    #pragma unroll
    for (int i = 0; i < 4; i++){
        int idx = tid + i*256;
        int r = idx >> 4, cc = idx & 15;
        cp16(sb + F_B_OFF + r*B_STRIDE + cc*16, B + (size_t)(k0 + r) * N + n0 + cc*8);
    }
    asm volatile("cp.async.commit_group;");
}

__device__ __forceinline__ void issue_stage_g16(
    const __half* __restrict__ A, const __half* __restrict__ B,
    uint32_t sb0, int tid, int m0, int n0, int K, int N, int c)
{
    uint32_t sb = sb0 + (uint32_t)(c % 3) * G_STAGE;
    int k0 = c * KC;
    #pragma unroll
    for (int i = 0; i < 2; i++){
        int idx = tid + i*256;
        int r = idx >> 3, cc = idx & 7;
        cp16(sb + r*A_STRIDE + cc*16, A + (size_t)(m0 + r) * K + k0 + cc*8);
    }
    #pragma unroll
    for (int i = 0; i < 4; i++){
        int idx = tid + i*256;
        int r = idx >> 4, cc = idx & 15;
        cp16(sb + G_B_OFF + r*B_STRIDE + cc*16, B + (size_t)(k0 + r) * N + n0 + cc*8);
    }
    asm volatile("cp.async.commit_group;");
}

// =====================================================================
// fp16 1-pass GEMM, 128x128 tile: C = epi(A @ B + bias)
// EPI: 0 = bias -> fp16   1 = bias+residual (f32)   2 = bias+GELU -> fp16
// =====================================================================
template<int EPI>
__global__ __launch_bounds__(256, 2)
void gemm_f16(const __half* __restrict__ A, const __half* __restrict__ B,
              const float* __restrict__ bias, const float* __restrict__ res,
              float* __restrict__ C, __half* __restrict__ Cf,
              int M, int N, int K)
{
    extern __shared__ char smem[];
    const uint32_t sb0 = smem_u32(smem);
    const int tid  = threadIdx.x;
    const int lane = tid & 31, wid = tid >> 5;
    const int m0 = blockIdx.y * 128, n0 = blockIdx.x * 128;
    const int wm = (wid >> 2) * 64, wn = (wid & 3) * 32;

    float acc[4][4][4];
    #pragma unroll
    for (int a = 0; a < 4; a++)
        #pragma unroll
        for (int b = 0; b < 4; b++)
            #pragma unroll
            for (int cc = 0; cc < 4; cc++) acc[a][b][cc] = 0.f;

    const int nch = K / KC;
    issue_stage_f16(A, B, sb0, tid, m0, n0, K, N, 0);
    issue_stage_f16(A, B, sb0, tid, m0, n0, K, N, 1);

    const uint32_t a_lrow = wm + (lane & 15);
    const uint32_t a_lcol = (lane >> 4) * 8;
    const uint32_t b_lrow = (lane & 15);

    for (int c = 0; c < nch; c++){
        asm volatile("cp.async.wait_group %0;" :: "n"(1));
        __syncthreads();
        if (c + 2 < nch) issue_stage_f16(A, B, sb0, tid, m0, n0, K, N, c + 2);
        else asm volatile("cp.async.commit_group;");

        uint32_t sb = sb0 + (uint32_t)(c % 3) * F_STAGE;
        #pragma unroll
        for (int ks = 0; ks < 4; ks++){
            uint32_t ah[4][4], bb[4][2];
            #pragma unroll
            for (int mt = 0; mt < 4; mt++)
                ldsm_x4(ah[mt], sb + (a_lrow + mt*16)*A_STRIDE + (ks*16 + a_lcol)*2);
            #pragma unroll
            for (int nt = 0; nt < 4; nt++)
                ldsm_x2t(bb[nt], sb + F_B_OFF + (ks*16 + b_lrow)*B_STRIDE + (wn + nt*8)*2);
            #pragma unroll
            for (int mt = 0; mt < 4; mt++)
                #pragma unroll
                for (int nt = 0; nt < 4; nt++)
                    mma_f16(acc[mt][nt], ah[mt], bb[nt]);
        }
    }

    const int g  = lane >> 2;
    const int tq = (lane & 3) * 2;
    #pragma unroll
    for (int mt = 0; mt < 4; mt++){
        #pragma unroll
        for (int half = 0; half < 2; half++){
            int m = m0 + wm + mt*16 + g + half*8;
            #pragma unroll
            for (int nt = 0; nt < 4; nt++){
                int n = n0 + wn + nt*8 + tq;
                float v0 = acc[mt][nt][half*2+0] + bias[n];
                float v1 = acc[mt][nt][half*2+1] + bias[n+1];
                size_t gi = (size_t)m * N + n;
                if (EPI == 1){
                    v0 += res[gi]; v1 += res[gi+1];
                    float2 o; o.x = v0; o.y = v1;
                    *(float2*)&C[gi] = o;
                } else {
                    if (EPI == 2){ v0 = gelu_exact(v0); v1 = gelu_exact(v1); }
                    *(uint32_t*)&Cf[gi] = pack_f16_2(v0, v1);
                }
            }
        }
    }
}

// =====================================================================
// fp16 1-pass GEMM, 64x128 tile: bias + residual, f32 out.
// =====================================================================
__global__ __launch_bounds__(256, 2)
void gemm_g16(const __half* __restrict__ A, const __half* __restrict__ B,
              const float* __restrict__ bias, const float* __restrict__ res,
              float* __restrict__ C, int M, int N, int K)
{
    extern __shared__ char smem[];
    const uint32_t sb0 = smem_u32(smem);
    const int tid  = threadIdx.x;
    const int lane = tid & 31, wid = tid >> 5;
    const int m0 = blockIdx.y * 64, n0 = blockIdx.x * 128;
    const int wm = (wid >> 2) * 32, wn = (wid & 3) * 32;

    float acc[2][4][4];
    #pragma unroll
    for (int a = 0; a < 2; a++)
        #pragma unroll
        for (int b = 0; b < 4; b++)
            #pragma unroll
            for (int cc = 0; cc < 4; cc++) acc[a][b][cc] = 0.f;

    const int nch = K / KC;
    issue_stage_g16(A, B, sb0, tid, m0, n0, K, N, 0);
    issue_stage_g16(A, B, sb0, tid, m0, n0, K, N, 1);

    const uint32_t a_lrow = wm + (lane & 15);
    const uint32_t a_lcol = (lane >> 4) * 8;
    const uint32_t b_lrow = (lane & 15);

    for (int c = 0; c < nch; c++){
        asm volatile("cp.async.wait_group %0;" :: "n"(1));
        __syncthreads();
        if (c + 2 < nch) issue_stage_g16(A, B, sb0, tid, m0, n0, K, N, c + 2);
        else asm volatile("cp.async.commit_group;");

        uint32_t sb = sb0 + (uint32_t)(c % 3) * G_STAGE;
        #pragma unroll
        for (int ks = 0; ks < 4; ks++){
            uint32_t ah[2][4], bb[4][2];
            #pragma unroll
            for (int mt = 0; mt < 2; mt++)
                ldsm_x4(ah[mt], sb + (a_lrow + mt*16)*A_STRIDE + (ks*16 + a_lcol)*2);
            #pragma unroll
            for (int nt = 0; nt < 4; nt++)
                ldsm_x2t(bb[nt], sb + G_B_OFF + (ks*16 + b_lrow)*B_STRIDE + (wn + nt*8)*2);
            #pragma unroll
            for (int mt = 0; mt < 2; mt++)
                #pragma unroll
                for (int nt = 0; nt < 4; nt++)
                    mma_f16(acc[mt][nt], ah[mt], bb[nt]);
        }
    }

    const int g  = lane >> 2;
    const int tq = (lane & 3) * 2;
    #pragma unroll
    for (int mt = 0; mt < 2; mt++){
        #pragma unroll
        for (int half = 0; half < 2; half++){
            int m = m0 + wm + mt*16 + g + half*8;
            #pragma unroll
            for (int nt = 0; nt < 4; nt++){
                int n = n0 + wn + nt*8 + tq;
                float v0 = acc[mt][nt][half*2+0] + bias[n];
                float v1 = acc[mt][nt][half*2+1] + bias[n+1];
                size_t gi = (size_t)m * N + n;
                v0 += res[gi]; v1 += res[gi+1];
                float2 o; o.x = v0; o.y = v1;
                *(float2*)&C[gi] = o;
            }
        }
    }
}

// =====================================================================
// Flash attention, single fp16, causal. Balanced pairing:
// Bq=64, 4 warps x 16 rows, CTA processes q-tiles (15-pair) then (pair)
// -> constant 17 KV-units per CTA.
// smem: Q 0..9216 | stage s at 9216+s*18432: K +0, V +9216
// =====================================================================
#define FL_SMEM 46080

__global__ __launch_bounds__(128)
void flash_kernel(const __half* __restrict__ qkvf, __half* __restrict__ of)
{
    extern __shared__ char fsm[];
    const uint32_t sb = smem_u32(fsm);
    const int tid = threadIdx.x, lane = tid & 31, w = tid >> 5;   // w 0..3
    const int bh = blockIdx.x;
    const int pair = blockIdx.y;                                  // 0..7
    const int b = bh >> 4, h = bh & 15;
    const size_t rs = 3*DMODEL;

    #define ISSUE_KV(jt_) do {                                               \
        uint32_t st_ = sb + 9216u + (uint32_t)((jt_)&1)*18432u;              \
        const size_t tok0_ = (size_t)(b*SEQ + (jt_)*64);                     \
        _Pragma("unroll")                                                    \
        for (int i_ = 0; i_ < 4; i_++){                                      \
            int idx_ = tid + i_*128;                                         \
            int r_ = idx_ >> 3, c_ = idx_ & 7;                               \
            uint32_t sa_ = st_ + r_*144 + c_*16;                             \
            cp16(sa_,        qkvf + (tok0_ + r_)*rs + DMODEL   + h*64 + c_*8); \
            cp16(sa_ + 9216, qkvf + (tok0_ + r_)*rs + 2*DMODEL + h*64 + c_*8); \
        }                                                                    \
        asm volatile("cp.async.commit_group;");                              \
    } while(0)

    #pragma unroll
    for (int hh = 0; hh < 2; hh++){
        const int it = hh ? pair : (15 - pair);   // heavy tile first
        const int nk = it + 1;

        // ---- Q loads (own group) ----
        {
            const size_t tok0 = (size_t)(b*SEQ + it*64);
            #pragma unroll
            for (int i = 0; i < 4; i++){
                int idx = tid + i*128;
                int r = idx >> 3, c = idx & 7;
                cp16(sb + r*144 + c*16, qkvf + (tok0 + r)*rs + h*64 + c*8);
            }
            asm volatile("cp.async.commit_group;");
        }
        ISSUE_KV(0);
        asm volatile("cp.async.wait_group 1;");   // Q ready
        __syncthreads();

        uint32_t qh[4][4];
        {
            uint32_t rbase = sb + (w*16 + (lane & 15))*144 + ((lane >> 4)*8)*2;
            #pragma unroll
            for (int ks = 0; ks < 4; ks++)
                ldsm_x4(qh[ks], rbase + ks*32);
        }

        float O[8][4];
        #pragma unroll
        for (int nt = 0; nt < 8; nt++)
            #pragma unroll
            for (int c = 0; c < 4; c++) O[nt][c] = 0.f;
        float m0 = -INFINITY, m1 = -INFINITY, l0 = 0.f, l1 = 0.f;
        const int r0g = it*64 + w*16 + (lane >> 2);

        for (int jt = 0; jt < nk; jt++){
            if (jt + 1 < nk){ ISSUE_KV(jt+1); asm volatile("cp.async.wait_group 1;"); }
            else            { asm volatile("cp.async.wait_group 0;"); }
            __syncthreads();
            const uint32_t st = sb + 9216u + (uint32_t)(jt&1)*18432u;

            float S[8][4];
            #pragma unroll
            for (int nt = 0; nt < 8; nt++)
                #pragma unroll
                for (int c = 0; c < 4; c++) S[nt][c] = 0.f;

            const uint32_t kb = st + (lane & 7)*144 + (((lane >> 3) & 1)*8)*2;
            #pragma unroll
            for (int nt = 0; nt < 8; nt++){
                #pragma unroll
                for (int ks = 0; ks < 4; ks++){
                    uint32_t kh[2];
                    ldsm_x2(kh, kb + nt*8*144 + ks*32);
                    mma_f16(S[nt], qh[ks], kh);
                }
            }

            const bool diag = (jt == it);
            float mx0 = -INFINITY, mx1 = -INFINITY;
            #pragma unroll
            for (int nt = 0; nt < 8; nt++){
                int colb = jt*64 + nt*8 + (lane & 3)*2;
                #pragma unroll
                for (int q = 0; q < 2; q++){
                    float v0 = S[nt][q]   * 0.125f;
                    float v1 = S[nt][2+q] * 0.125f;
                    if (diag){
                        if (colb + q > r0g)     v0 = -INFINITY;
                        if (colb + q > r0g + 8) v1 = -INFINITY;
                    }
                    S[nt][q] = v0; S[nt][2+q] = v1;
                    mx0 = fmaxf(mx0, v0); mx1 = fmaxf(mx1, v1);
                }
            }
            mx0 = fmaxf(mx0, __shfl_xor_sync(0xffffffffu, mx0, 1));
            mx0 = fmaxf(mx0, __shfl_xor_sync(0xffffffffu, mx0, 2));
            mx1 = fmaxf(mx1, __shfl_xor_sync(0xffffffffu, mx1, 1));
            mx1 = fmaxf(mx1, __shfl_xor_sync(0xffffffffu, mx1, 2));
            float mn0 = fmaxf(m0, mx0), mn1 = fmaxf(m1, mx1);
            float f0 = __expf(m0 - mn0), f1 = __expf(m1 - mn1);
            m0 = mn0; m1 = mn1;
            float ls0 = 0.f, ls1 = 0.f;
            #pragma unroll
            for (int nt = 0; nt < 8; nt++){
                #pragma unroll
                for (int q = 0; q < 2; q++){
                    float e0 = __expf(S[nt][q]   - m0);
                    float e1 = __expf(S[nt][2+q] - m1);
                    S[nt][q] = e0; S[nt][2+q] = e1;
                    ls0 += e0; ls1 += e1;
                }
            }
            l0 = l0*f0 + ls0;
            l1 = l1*f1 + ls1;
            #pragma unroll
            for (int nt = 0; nt < 8; nt++){
                O[nt][0] *= f0; O[nt][1] *= f0;
                O[nt][2] *= f1; O[nt][3] *= f1;
            }

            #pragma unroll
            for (int ks = 0; ks < 4; ks++){
                uint32_t ph[4];
                ph[0] = pack_f16_2(S[2*ks][0],   S[2*ks][1]);
                ph[1] = pack_f16_2(S[2*ks][2],   S[2*ks][3]);
                ph[2] = pack_f16_2(S[2*ks+1][0], S[2*ks+1][1]);
                ph[3] = pack_f16_2(S[2*ks+1][2], S[2*ks+1][3]);
                uint32_t vb = st + 9216u + (ks*16 + (lane & 15))*144;
                #pragma unroll
                for (int nt = 0; nt < 8; nt++){
                    uint32_t vh[2];
                    ldsm_x2t(vh, vb + nt*16);
                    mma_f16(O[nt], ph, vh);
                }
            }
            __syncthreads();
        }

        l0 += __shfl_xor_sync(0xffffffffu, l0, 1);
        l0 += __shfl_xor_sync(0xffffffffu, l0, 2);
        l1 += __shfl_xor_sync(0xffffffffu, l1, 1);
        l1 += __shfl_xor_sync(0xffffffffu, l1, 2);
        float inv0 = 1.0f / l0, inv1 = 1.0f / l1;
        const size_t tok0 = (size_t)(b*SEQ + it*64 + w*16 + (lane >> 2));
        const int colb = h*64 + (lane & 3)*2;
        #pragma unroll
        for (int nt = 0; nt < 8; nt++){
            #pragma unroll
            for (int rh = 0; rh < 2; rh++){
                float inv = rh ? inv1 : inv0;
                float v0 = O[nt][rh*2+0] * inv;
                float v1 = O[nt][rh*2+1] * inv;
                size_t gi = (tok0 + rh*8)*DMODEL + colb + nt*8;
                *(uint32_t*)&of[gi] = pack_f16_2(v0, v1);
            }
        }
        __syncthreads();   // protect Q/KV buffers before the second tile
    }
    #undef ISSUE_KV
}

// ---------------- merged weight convert: fp32 -> fp16 (all 4 tensors) ----------------
__global__ void wconv_all_kernel(const float4* __restrict__ Wqkv,
                                 const float4* __restrict__ Wo,
                                 const float4* __restrict__ W1,
                                 const float4* __restrict__ W2,
                                 uint2* __restrict__ out){
    int i = blockIdx.x * blockDim.x + threadIdx.x;
    if (i >= WF_TOT/4) return;
    const float4* src;
    int off;
    if (i < WF_WO/4){ src = Wqkv; off = i; }
    else if (i < WF_W1/4){ src = Wo; off = i - WF_WO/4; }
    else if (i < WF_W2/4){ src = W1; off = i - WF_W1/4; }
    else { src = W2; off = i - WF_W2/4; }
    float4 v = src[off];
    uint2 o;
    o.x = pack_f16_2(v.x, v.y);
    o.y = pack_f16_2(v.z, v.w);
    out[i] = o;
}

// ---------------- LayerNorm: single fp16 out ----------------
__global__ void ln_kernel(const float* __restrict__ in,
                          const float* __restrict__ w,
                          const float* __restrict__ b,
                          __half* __restrict__ outf){
    int row = blockIdx.x;
    int t   = threadIdx.x;
    const float* x = in + (size_t)row * DMODEL;
    float4 v = *(const float4*)&x[t*4];
    float s  = v.x + v.y + v.z + v.w;
    float sq = v.x*v.x + v.y*v.y + v.z*v.z + v.w*v.w;
    s  = warp_sum(s);
    sq = warp_sum(sq);
    __shared__ float sh1[8], sh2[8];
    int warp = t >> 5, lane = t & 31;
    if (lane == 0){ sh1[warp] = s; sh2[warp] = sq; }
    __syncthreads();
    float tot = 0.f, tot2 = 0.f;
    #pragma unroll
    for (int i = 0; i < 8; i++){ tot += sh1[i]; tot2 += sh2[i]; }
    float mu   = tot  * (1.0f/DMODEL);
    float var  = tot2 * (1.0f/DMODEL) - mu*mu;
    float rstd = rsqrtf(var + EPS);
    float4 wv = *(const float4*)&w[t*4];
    float4 bv = *(const float4*)&b[t*4];
    float4 ov;
    ov.x = (v.x - mu)*rstd*wv.x + bv.x;
    ov.y = (v.y - mu)*rstd*wv.y + bv.y;
    ov.z = (v.z - mu)*rstd*wv.z + bv.z;
    ov.w = (v.w - mu)*rstd*wv.w + bv.w;
    size_t base = (size_t)row*DMODEL + t*4;
    uint2 H;
    H.x = pack_f16_2(ov.x, ov.y);
    H.y = pack_f16_2(ov.z, ov.w);
    *(uint2*)&outf[base] = H;
}

// ---------------- fused final LayerNorm + projection ----------------
__global__ __launch_bounds__(256)
void lnpred_kernel(const float* __restrict__ in,
                   const float* __restrict__ w,
                   const float* __restrict__ b,
                   const float* __restrict__ Wp,
                   const float* __restrict__ bp,
                   float* __restrict__ out){
    int row = blockIdx.x;
    int t   = threadIdx.x;
    const float* x = in + (size_t)row * DMODEL;
    float4 v = *(const float4*)&x[t*4];
    float s  = v.x + v.y + v.z + v.w;
    float sq = v.x*v.x + v.y*v.y + v.z*v.z + v.w*v.w;
    s  = warp_sum(s);
    sq = warp_sum(sq);
    __shared__ float sh1[8], sh2[8];
    int warp = t >> 5, lane = t & 31;
    if (lane == 0){ sh1[warp] = s; sh2[warp] = sq; }
    __syncthreads();
    float tot = 0.f, tot2 = 0.f;
    #pragma unroll
    for (int i = 0; i < 8; i++){ tot += sh1[i]; tot2 += sh2[i]; }
    float mu   = tot  * (1.0f/DMODEL);
    float var  = tot2 * (1.0f/DMODEL) - mu*mu;
    float rstd = rsqrtf(var + EPS);
    float4 wv = *(const float4*)&w[t*4];
    float4 bv = *(const float4*)&b[t*4];
    float4 ov;
    ov.x = (v.x - mu)*rstd*wv.x + bv.x;
    ov.y = (v.y - mu)*rstd*wv.y + bv.y;
    ov.z = (v.z - mu)*rstd*wv.z + bv.z;
    ov.w = (v.w - mu)*rstd*wv.w + bv.w;

    float local[WIN];
    {
        const float* w0 = Wp + (size_t)(t*4) * WIN;
        #pragma unroll
        for (int p = 0; p < WIN; p++)
            local[p] = ov.x*w0[p] + ov.y*w0[WIN+p] + ov.z*w0[2*WIN+p] + ov.w*w0[3*WIN+p];
    }
    __shared__ float red[WIN][256];
    #pragma unroll
    for (int p = 0; p < WIN; p++) red[p][t] = local[p];
    __syncthreads();
    for (int sHalf = 128; sHalf > 0; sHalf >>= 1){
        if (t < sHalf){
            #pragma unroll
            for (int p = 0; p < WIN; p++) red[p][t] += red[p][t + sHalf];
        }
        __syncthreads();
    }
    if (t < WIN) out[(size_t)row * WIN + t] = red[t][0] + bp[t];
}

// ---------------- host orchestration ----------------
extern "C" void kernel_launch(void* const* d_in, const int* in_sizes, int n_in,
                              void* d_out, int out_size){
    const float* x     = (const float*)d_in[0];
    const float* Wqkv  = (const float*)d_in[1];
    const float* bqkv  = (const float*)d_in[2];
    const float* Wo    = (const float*)d_in[3];
    const float* bo    = (const float*)d_in[4];
    const float* ln1w  = (const float*)d_in[5];
    const float* ln1b  = (const float*)d_in[6];
    const float* W1    = (const float*)d_in[7];
    const float* b1    = (const float*)d_in[8];
    const float* W2    = (const float*)d_in[9];
    const float* b2    = (const float*)d_in[10];
    const float* ln2w  = (const float*)d_in[11];
    const float* ln2b  = (const float*)d_in[12];
    const float* lnfw  = (const float*)d_in[13];
    const float* lnfb  = (const float*)d_in[14];
    const float* Wp    = (const float*)d_in[15];
    const float* bp    = (const float*)d_in[16];
    float* out = (float*)d_out;

    float *g_h;
    __half *g_hnf, *g_qkvf, *g_of, *g_fff, *g_wf16;
    cudaGetSymbolAddress((void**)&g_h,    d_h);
    cudaGetSymbolAddress((void**)&g_hnf,  d_hnf);
    cudaGetSymbolAddress((void**)&g_qkvf, d_qkvf);
    cudaGetSymbolAddress((void**)&g_of,   d_of);
    cudaGetSymbolAddress((void**)&g_fff,  d_fff);
    cudaGetSymbolAddress((void**)&g_wf16, d_wf16);

    cudaFuncSetAttribute(gemm_f16<0>, cudaFuncAttributeMaxDynamicSharedMemorySize, FGEMM_SMEM);
    cudaFuncSetAttribute(gemm_f16<2>, cudaFuncAttributeMaxDynamicSharedMemorySize, FGEMM_SMEM);
    cudaFuncSetAttribute(gemm_g16,    cudaFuncAttributeMaxDynamicSharedMemorySize, GGEMM_SMEM);
    cudaFuncSetAttribute(flash_kernel, cudaFuncAttributeMaxDynamicSharedMemorySize, FL_SMEM);

    wconv_all_kernel<<<(WF_TOT/4 + 255)/256, 256>>>(
        (const float4*)Wqkv, (const float4*)Wo, (const float4*)W1, (const float4*)W2,
        (uint2*)g_wf16);

    for (int l = 0; l < LAYERS; l++){
        const __half* wqkv = g_wf16 + WF_QKV + (size_t)l * DMODEL * 3*DMODEL;
        const __half* wo   = g_wf16 + WF_WO  + (size_t)l * DMODEL * DMODEL;
        const __half* w1   = g_wf16 + WF_W1  + (size_t)l * DMODEL * DFF;
        const __half* w2   = g_wf16 + WF_W2  + (size_t)l * DFF * DMODEL;
        const float* bq = bqkv + (size_t)l * 3*DMODEL;
        const float* bO = bo   + (size_t)l * DMODEL;
        const float* B1 = b1   + (size_t)l * DFF;
        const float* B2 = b2   + (size_t)l * DMODEL;
        const float* hin = (l == 0) ? x : g_h;

        // pre-norm attention
        ln_kernel<<<TOKENS, 256>>>(hin, ln1w + l*DMODEL, ln1b + l*DMODEL, g_hnf);
        gemm_f16<0><<<dim3(3*DMODEL/128, TOKENS/128), 256, FGEMM_SMEM>>>(
            g_hnf, wqkv, bq, nullptr, nullptr, g_qkvf, TOKENS, 3*DMODEL, DMODEL);
        flash_kernel<<<dim3(BATCH*NHEAD, 8), 128, FL_SMEM>>>(g_qkvf, g_of);
        gemm_g16<<<dim3(DMODEL/128, TOKENS/64), 256, GGEMM_SMEM>>>(
            g_of, wo, bO, hin, g_h, TOKENS, DMODEL, DMODEL);

        // pre-norm FFN
        ln_kernel<<<TOKENS, 256>>>(g_h, ln2w + l*DMODEL, ln2b + l*DMODEL, g_hnf);
        gemm_f16<2><<<dim3(DFF/128, TOKENS/128), 256, FGEMM_SMEM>>>(
            g_hnf, w1, B1, nullptr, nullptr, g_fff, TOKENS, DFF, DMODEL);
        gemm_g16<<<dim3(DMODEL/128, TOKENS/64), 256, GGEMM_SMEM>>>(
            g_fff, w2, B2, g_h, g_h, TOKENS, DMODEL, DFF);
    }

    lnpred_kernel<<<TOKENS, 256>>>(g_h, lnfw, lnfb, Wp, bp, out);
    (void)in_sizes; (void)n_in; (void)out_size;
}